// round 1
// baseline (speedup 1.0000x reference)
#include <cuda_runtime.h>

// Problem constants
#define B_  4
#define S_  2048
#define D_  1024
#define M1  (B_ * S_)          // 8192 total query rows

// Scratch (allocation-free rule: __device__ globals)
__device__ float g_Q[(size_t)M1 * D_];         // 32 MB
__device__ float g_V[(size_t)M1 * D_];         // 32 MB
__device__ float g_A[(size_t)B_ * S_ * S_];    // 64 MB fallback (only if out buffer lacks A region)

// GEMM tiling
#define BM 128
#define BN 128
#define BK 8
#define TM 8
#define TN 8
#define NTHREADS 256

// ---------------------------------------------------------------------------
// Kernel 1: Q = X @ WQK^T  (z=0)  and  V = X @ WOV^T (z=1)
// X: [M1, D] row-major. W: [D, D] row-major (n,k). C: [M1, D].
// Both operands K-contiguous -> transposed smem stores for both.
// ---------------------------------------------------------------------------
__global__ __launch_bounds__(NTHREADS) void k_qv(const float* __restrict__ X,
                                                 const float* __restrict__ WQK,
                                                 const float* __restrict__ WOV) {
    __shared__ float As[BK][BM];
    __shared__ float Bs[BK][BN];

    const float* Bmat = (blockIdx.z == 0) ? WQK : WOV;
    float*       C    = (blockIdx.z == 0) ? g_Q : g_V;
    const int K = D_;

    const float* Aptr = X    + (size_t)blockIdx.y * BM * K;
    const float* Bptr = Bmat + (size_t)blockIdx.x * BN * K;

    const int tid   = threadIdx.x;
    const int ldRow = tid >> 1;           // 0..127
    const int ldCol = (tid & 1) * 4;      // 0 or 4
    const int tRow  = (tid >> 4) * TM;
    const int tCol  = (tid & 15) * TN;

    float acc[TM][TN] = {};

    for (int k0 = 0; k0 < K; k0 += BK) {
        float4 a4 = *(const float4*)(Aptr + (size_t)ldRow * K + k0 + ldCol);
        float4 b4 = *(const float4*)(Bptr + (size_t)ldRow * K + k0 + ldCol);
        As[ldCol + 0][ldRow] = a4.x; As[ldCol + 1][ldRow] = a4.y;
        As[ldCol + 2][ldRow] = a4.z; As[ldCol + 3][ldRow] = a4.w;
        Bs[ldCol + 0][ldRow] = b4.x; Bs[ldCol + 1][ldRow] = b4.y;
        Bs[ldCol + 2][ldRow] = b4.z; Bs[ldCol + 3][ldRow] = b4.w;
        __syncthreads();

        #pragma unroll
        for (int k = 0; k < BK; k++) {
            float ar[TM], br[TN];
            #pragma unroll
            for (int i = 0; i < TM; i++) ar[i] = As[k][tRow + i];
            #pragma unroll
            for (int j = 0; j < TN; j++) br[j] = Bs[k][tCol + j];
            #pragma unroll
            for (int i = 0; i < TM; i++)
                #pragma unroll
                for (int j = 0; j < TN; j++)
                    acc[i][j] += ar[i] * br[j];
        }
        __syncthreads();
    }

    float* Cp = C + ((size_t)blockIdx.y * BM + tRow) * D_ + blockIdx.x * BN + tCol;
    #pragma unroll
    for (int i = 0; i < TM; i++) {
        #pragma unroll
        for (int j = 0; j < TN; j += 4) {
            float4 v = make_float4(acc[i][j], acc[i][j+1], acc[i][j+2], acc[i][j+3]);
            *(float4*)(Cp + (size_t)i * D_ + j) = v;
        }
    }
}

// ---------------------------------------------------------------------------
// Kernel 2: Sc = 32 * (Q_b @ X_b^T), lower-triangular blocks only, written
// straight into the A-output region (stride S_).
// ---------------------------------------------------------------------------
__global__ __launch_bounds__(NTHREADS) void k_scores(const float* __restrict__ X,
                                                     float* __restrict__ Aout) {
    if (blockIdx.x > blockIdx.y) return;   // strictly above diagonal: skip

    __shared__ float As[BK][BM];
    __shared__ float Bs[BK][BN];

    const int b = blockIdx.z;
    const int K = D_;
    const float* Aptr = g_Q + (size_t)b * S_ * D_ + (size_t)blockIdx.y * BM * K;
    const float* Bptr = X   + (size_t)b * S_ * D_ + (size_t)blockIdx.x * BN * K;

    const int tid   = threadIdx.x;
    const int ldRow = tid >> 1;
    const int ldCol = (tid & 1) * 4;
    const int tRow  = (tid >> 4) * TM;
    const int tCol  = (tid & 15) * TN;

    float acc[TM][TN] = {};

    for (int k0 = 0; k0 < K; k0 += BK) {
        float4 a4 = *(const float4*)(Aptr + (size_t)ldRow * K + k0 + ldCol);
        float4 b4 = *(const float4*)(Bptr + (size_t)ldRow * K + k0 + ldCol);
        As[ldCol + 0][ldRow] = a4.x; As[ldCol + 1][ldRow] = a4.y;
        As[ldCol + 2][ldRow] = a4.z; As[ldCol + 3][ldRow] = a4.w;
        Bs[ldCol + 0][ldRow] = b4.x; Bs[ldCol + 1][ldRow] = b4.y;
        Bs[ldCol + 2][ldRow] = b4.z; Bs[ldCol + 3][ldRow] = b4.w;
        __syncthreads();

        #pragma unroll
        for (int k = 0; k < BK; k++) {
            float ar[TM], br[TN];
            #pragma unroll
            for (int i = 0; i < TM; i++) ar[i] = As[k][tRow + i];
            #pragma unroll
            for (int j = 0; j < TN; j++) br[j] = Bs[k][tCol + j];
            #pragma unroll
            for (int i = 0; i < TM; i++)
                #pragma unroll
                for (int j = 0; j < TN; j++)
                    acc[i][j] += ar[i] * br[j];
        }
        __syncthreads();
    }

    const float scale = 32.0f;   // sqrt(1024), reference MULTIPLIES by sqrt(d)
    float* Cp = Aout + (size_t)b * S_ * S_
                     + ((size_t)blockIdx.y * BM + tRow) * S_ + blockIdx.x * BN + tCol;
    #pragma unroll
    for (int i = 0; i < TM; i++) {
        #pragma unroll
        for (int j = 0; j < TN; j += 4) {
            float4 v = make_float4(acc[i][j] * scale, acc[i][j+1] * scale,
                                   acc[i][j+2] * scale, acc[i][j+3] * scale);
            *(float4*)(Cp + (size_t)i * S_ + j) = v;
        }
    }
}

// ---------------------------------------------------------------------------
// Kernel 3: causal softmax, in place over Aout. One block per (row, batch).
// Reads [0, s], writes exp-normalized there, zeros (s, S).
// ---------------------------------------------------------------------------
__global__ void k_softmax(float* __restrict__ A) {
    const int s = blockIdx.x, b = blockIdx.y;
    float* row = A + ((size_t)b * S_ + s) * S_;
    const int len = s + 1;
    const int tid = threadIdx.x;
    __shared__ float red[256];

    float m = -1e30f;
    for (int j = tid; j < len; j += 256) m = fmaxf(m, row[j]);
    red[tid] = m; __syncthreads();
    for (int o = 128; o > 0; o >>= 1) {
        if (tid < o) red[tid] = fmaxf(red[tid], red[tid + o]);
        __syncthreads();
    }
    m = red[0]; __syncthreads();

    float sum = 0.0f;
    for (int j = tid; j < len; j += 256) {
        float e = expf(row[j] - m);
        row[j] = e;
        sum += e;
    }
    red[tid] = sum; __syncthreads();
    for (int o = 128; o > 0; o >>= 1) {
        if (tid < o) red[tid] += red[tid + o];
        __syncthreads();
    }
    const float inv = 1.0f / red[0];

    for (int j = tid; j < len; j += 256) row[j] *= inv;
    for (int j = len + tid; j < S_; j += 256) row[j] = 0.0f;
}

// ---------------------------------------------------------------------------
// Kernel 4: Y = A_b @ V_b, out = X + Y. A row-major [S,S], V row-major [S,D].
// Causal: K-loop truncated at end of this block-row.
// ---------------------------------------------------------------------------
__global__ __launch_bounds__(NTHREADS) void k_av(const float* __restrict__ A,
                                                 const float* __restrict__ X,
                                                 float* __restrict__ Yout) {
    __shared__ float As[BK][BM];
    __shared__ float Bs[BK][BN];

    const int b = blockIdx.z;
    const float* Ap = A   + (size_t)b * S_ * S_ + (size_t)blockIdx.y * BM * S_;
    const float* Vp = g_V + (size_t)b * S_ * D_ + blockIdx.x * BN;

    const int tid   = threadIdx.x;
    const int aRow  = tid >> 1;
    const int aCol  = (tid & 1) * 4;
    const int bRow  = tid >> 5;           // 0..7  (k within tile)
    const int bCol  = (tid & 31) * 4;     // 0..124
    const int tRow  = (tid >> 4) * TM;
    const int tCol  = (tid & 15) * TN;

    float acc[TM][TN] = {};
    const int kmax = (blockIdx.y + 1) * BM;   // A[m,k]==0 beyond the diagonal

    for (int k0 = 0; k0 < kmax; k0 += BK) {
        float4 a4 = *(const float4*)(Ap + (size_t)aRow * S_ + k0 + aCol);
        As[aCol + 0][aRow] = a4.x; As[aCol + 1][aRow] = a4.y;
        As[aCol + 2][aRow] = a4.z; As[aCol + 3][aRow] = a4.w;
        float4 b4 = *(const float4*)(Vp + (size_t)(k0 + bRow) * D_ + bCol);
        *(float4*)&Bs[bRow][bCol] = b4;
        __syncthreads();

        #pragma unroll
        for (int k = 0; k < BK; k++) {
            float ar[TM], br[TN];
            #pragma unroll
            for (int i = 0; i < TM; i++) ar[i] = As[k][tRow + i];
            #pragma unroll
            for (int j = 0; j < TN; j++) br[j] = Bs[k][tCol + j];
            #pragma unroll
            for (int i = 0; i < TM; i++)
                #pragma unroll
                for (int j = 0; j < TN; j++)
                    acc[i][j] += ar[i] * br[j];
        }
        __syncthreads();
    }

    const size_t base = (size_t)b * S_ * D_ + ((size_t)blockIdx.y * BM + tRow) * D_
                      + blockIdx.x * BN + tCol;
    const float* Xp = X + base;
    float*       Op = Yout + base;
    #pragma unroll
    for (int i = 0; i < TM; i++) {
        #pragma unroll
        for (int j = 0; j < TN; j += 4) {
            float4 x4 = *(const float4*)(Xp + (size_t)i * D_ + j);
            float4 v  = make_float4(acc[i][j]   + x4.x, acc[i][j+1] + x4.y,
                                    acc[i][j+2] + x4.z, acc[i][j+3] + x4.w);
            *(float4*)(Op + (size_t)i * D_ + j) = v;
        }
    }
}

// ---------------------------------------------------------------------------
extern "C" void kernel_launch(void* const* d_in, const int* in_sizes, int n_in,
                              void* d_out, int out_size) {
    const float* X   = (const float*)d_in[0];
    // d_in[1] is the causal mask (bool) — structure is known (tril), applied analytically.
    const float* WQK = (const float*)d_in[2];
    const float* WOV = (const float*)d_in[3];

    float* out = (float*)d_out;

    // Output layout: [X+Y : B*S*D floats][A : B*S*S floats]
    const size_t nY = (size_t)M1 * D_;
    const size_t nA = (size_t)B_ * S_ * S_;
    float* Aout;
    if ((size_t)out_size >= nY + nA) {
        Aout = out + nY;
    } else {
        void* p = nullptr;
        cudaGetSymbolAddress(&p, g_A);   // fallback: A not part of output
        Aout = (float*)p;
    }

    // 1) Q and V
    k_qv<<<dim3(D_ / BN, M1 / BM, 2), NTHREADS>>>(X, WQK, WOV);
    // 2) scaled causal scores -> A region
    k_scores<<<dim3(S_ / BN, S_ / BM, B_), NTHREADS>>>(X, Aout);
    // 3) softmax in place (also zeros the strictly-upper triangle)
    k_softmax<<<dim3(S_, B_), 256>>>(Aout);
    // 4) Y = A @ V, out = X + Y
    k_av<<<dim3(D_ / BN, S_ / BM, B_), NTHREADS>>>(Aout, X, out);
}

// round 3
// speedup vs baseline: 3.1330x; 3.1330x over previous
#include <cuda_runtime.h>
#include <cuda_bf16.h>
#include <cuda_fp16.h>
#include <cstdint>

#define B_  4
#define S_  2048
#define D_  1024
#define M1  (B_ * S_)

typedef __nv_bfloat16 bf16;

// ---------------------------------------------------------------------------
// Scratch (allocation-free rule: __device__ globals)
// ---------------------------------------------------------------------------
__device__ __align__(256) bf16  g_Xhi[(size_t)M1 * D_];
__device__ __align__(256) bf16  g_Xlo[(size_t)M1 * D_];
__device__ __align__(256) bf16  g_Whi[2][(size_t)D_ * D_];
__device__ __align__(256) bf16  g_Wlo[2][(size_t)D_ * D_];
__device__ __align__(256) bf16  g_Qhi[(size_t)M1 * D_];
__device__ __align__(256) bf16  g_Qlo[(size_t)M1 * D_];
__device__ __align__(256) __half g_Vh[(size_t)M1 * D_];          // V row-major [m][d]
__device__ __align__(256) __half g_Ah[(size_t)B_ * S_ * S_];     // A fp16 [s][t]
__device__ float g_Afallback[(size_t)B_ * S_ * S_];

// ---------------------------------------------------------------------------
// Baseline-PTX primitives (sm_80-era: assemble fine for compute_103)
// ---------------------------------------------------------------------------
__device__ __forceinline__ uint32_t smem_u32(const void* p) {
    uint32_t a;
    asm("{ .reg .u64 t; cvta.to.shared.u64 t, %1; cvt.u32.u64 %0, t; }" : "=r"(a) : "l"(p));
    return a;
}

#define CPA(dst, src)  asm volatile("cp.async.cg.shared.global [%0], [%1], 16;\n" :: "r"(dst), "l"(src))
#define CP_COMMIT()    asm volatile("cp.async.commit_group;\n" ::: "memory")
#define CP_WAIT1()     asm volatile("cp.async.wait_group 1;\n" ::: "memory")
#define CP_WAIT0()     asm volatile("cp.async.wait_group 0;\n" ::: "memory")

__device__ __forceinline__ void ldsm4(uint32_t r[4], uint32_t a) {
    asm volatile("ldmatrix.sync.aligned.m8n8.x4.shared.b16 {%0,%1,%2,%3}, [%4];\n"
                 : "=r"(r[0]), "=r"(r[1]), "=r"(r[2]), "=r"(r[3]) : "r"(a));
}
__device__ __forceinline__ void ldsm4t(uint32_t r[4], uint32_t a) {
    asm volatile("ldmatrix.sync.aligned.m8n8.x4.trans.shared.b16 {%0,%1,%2,%3}, [%4];\n"
                 : "=r"(r[0]), "=r"(r[1]), "=r"(r[2]), "=r"(r[3]) : "r"(a));
}

__device__ __forceinline__ void mma_bf16(float* c, const uint32_t a[4], uint32_t b0, uint32_t b1) {
    asm volatile("mma.sync.aligned.m16n8k16.row.col.f32.bf16.bf16.f32 "
                 "{%0,%1,%2,%3}, {%4,%5,%6,%7}, {%8,%9}, {%0,%1,%2,%3};\n"
                 : "+f"(c[0]), "+f"(c[1]), "+f"(c[2]), "+f"(c[3])
                 : "r"(a[0]), "r"(a[1]), "r"(a[2]), "r"(a[3]), "r"(b0), "r"(b1));
}
__device__ __forceinline__ void mma_f16(float* c, const uint32_t a[4], uint32_t b0, uint32_t b1) {
    asm volatile("mma.sync.aligned.m16n8k16.row.col.f32.f16.f16.f32 "
                 "{%0,%1,%2,%3}, {%4,%5,%6,%7}, {%8,%9}, {%0,%1,%2,%3};\n"
                 : "+f"(c[0]), "+f"(c[1]), "+f"(c[2]), "+f"(c[3])
                 : "r"(a[0]), "r"(a[1]), "r"(a[2]), "r"(a[3]), "r"(b0), "r"(b1));
}

__device__ __forceinline__ void split_bf16(float v, bf16& h, bf16& l) {
    h = __float2bfloat16_rn(v);
    l = __float2bfloat16_rn(v - __bfloat162float(h));
}

// ---------------------------------------------------------------------------
// Tile loaders (cp.async, 128 threads)
// [128 rows][32 2B-elems] tile; smem rows stride 80B (conflict-free ldmatrix)
// ---------------------------------------------------------------------------
__device__ __forceinline__ void cpa_A(uint32_t sdst, const void* g, int ldbytes, int tid) {
#pragma unroll
    for (int i = 0; i < 4; i++) {
        int u = tid + i * 128;
        int r = u >> 2, c = u & 3;
        CPA(sdst + r * 80 + c * 16, (const char*)g + (size_t)r * ldbytes + c * 16);
    }
}
// [32 k-rows][128 2B-elems] tile; smem rows 256B with XOR swizzle
__device__ __forceinline__ void cpa_BT(uint32_t sdst, const void* g, int ldbytes, int tid) {
#pragma unroll
    for (int i = 0; i < 4; i++) {
        int u = tid + i * 128;
        int k = u >> 4, c = u & 15;
        CPA(sdst + k * 256 + ((c ^ ((k & 7) << 1)) << 4),
            (const char*)g + (size_t)k * ldbytes + c * 16);
    }
}

// ---------------------------------------------------------------------------
// 3-pass compensated k-step (bf16): C += Ahi*Bhi + Alo*Bhi + Ahi*Blo
// sA -> Ahi region (Alo at +10240); sB -> Bhi region (Blo at +10240)
// ---------------------------------------------------------------------------
__device__ __forceinline__ void kstep_hilo(uint32_t sA, uint32_t sB, int ks,
                                           int lane, int wm, int wn, float c[4][8][4]) {
    const int row = lane & 15;
    const int ch  = (lane >> 4) + ks * 2;
    const uint32_t ao = sA + (wm * 64 + row) * 80 + ch * 16;
    const uint32_t bo = sB + (wn * 64 + row) * 80 + ch * 16;
    uint32_t ah[4][4], bh[4][4];
#pragma unroll
    for (int mi = 0; mi < 4; mi++) ldsm4(ah[mi], ao + mi * 1280);
#pragma unroll
    for (int nj = 0; nj < 4; nj++) ldsm4(bh[nj], bo + nj * 1280);
#pragma unroll
    for (int mi = 0; mi < 4; mi++)
#pragma unroll
        for (int nj = 0; nj < 4; nj++) {
            mma_bf16(c[mi][2 * nj],     ah[mi], bh[nj][0], bh[nj][2]);
            mma_bf16(c[mi][2 * nj + 1], ah[mi], bh[nj][1], bh[nj][3]);
        }
    {
        uint32_t al[4][4];
#pragma unroll
        for (int mi = 0; mi < 4; mi++) ldsm4(al[mi], ao + 10240 + mi * 1280);
#pragma unroll
        for (int mi = 0; mi < 4; mi++)
#pragma unroll
            for (int nj = 0; nj < 4; nj++) {
                mma_bf16(c[mi][2 * nj],     al[mi], bh[nj][0], bh[nj][2]);
                mma_bf16(c[mi][2 * nj + 1], al[mi], bh[nj][1], bh[nj][3]);
            }
    }
    {
        uint32_t bl[4][4];
#pragma unroll
        for (int nj = 0; nj < 4; nj++) ldsm4(bl[nj], bo + 10240 + nj * 1280);
#pragma unroll
        for (int mi = 0; mi < 4; mi++)
#pragma unroll
            for (int nj = 0; nj < 4; nj++) {
                mma_bf16(c[mi][2 * nj],     ah[mi], bl[nj][0], bl[nj][2]);
                mma_bf16(c[mi][2 * nj + 1], ah[mi], bl[nj][1], bl[nj][3]);
            }
    }
}

// stage layout (hilo): Ahi 0, Alo 10240, Bhi 20480, Blo 30720; stage stride 40960
__device__ __forceinline__ void gemm_hilo(const bf16* Ah, const bf16* Al, int lda,
                                          const bf16* Bh, const bf16* Bl, int ldb,
                                          int nit, uint32_t sb, int tid, float c[4][8][4]) {
    const int lane = tid & 31, wid = tid >> 5;
    const int wm = wid >> 1, wn = wid & 1;
    const int la = lda * 2, lb = ldb * 2;
    cpa_A(sb,         Ah, la, tid);
    cpa_A(sb + 10240, Al, la, tid);
    cpa_A(sb + 20480, Bh, lb, tid);
    cpa_A(sb + 30720, Bl, lb, tid);
    CP_COMMIT();
    for (int it = 0; it < nit; it++) {
        if (it + 1 < nit) {
            const uint32_t nb = sb + ((it + 1) & 1) * 40960;
            const int ko = (it + 1) * 32;
            cpa_A(nb,         Ah + ko, la, tid);
            cpa_A(nb + 10240, Al + ko, la, tid);
            cpa_A(nb + 20480, Bh + ko, lb, tid);
            cpa_A(nb + 30720, Bl + ko, lb, tid);
            CP_COMMIT();
            CP_WAIT1();
        } else {
            CP_WAIT0();
        }
        __syncthreads();
        const uint32_t sA = sb + (it & 1) * 40960;
        kstep_hilo(sA, sA + 20480, 0, lane, wm, wn, c);
        kstep_hilo(sA, sA + 20480, 1, lane, wm, wn, c);
        __syncthreads();
    }
}

// ---------------------------------------------------------------------------
// fp16 single-pass k-step for A@V (B = V in [K][N] layout, trans ldmatrix)
// ---------------------------------------------------------------------------
__device__ __forceinline__ void kstep_av(uint32_t sA, uint32_t sB, int ks,
                                         int lane, int wm, int wn, float c[4][8][4]) {
    const int row = lane & 15;
    const uint32_t ao = sA + (wm * 64 + row) * 80 + ((lane >> 4) + ks * 2) * 16;
    uint32_t af[4][4];
#pragma unroll
    for (int mi = 0; mi < 4; mi++) ldsm4(af[mi], ao + mi * 1280);
    const int k = ks * 16 + row;
    uint32_t bf_[4][4];
#pragma unroll
    for (int nj = 0; nj < 4; nj++) {
        const int cl = wn * 8 + nj * 2 + (lane >> 4);
        ldsm4t(bf_[nj], sB + k * 256 + ((cl ^ ((k & 7) << 1)) << 4));
    }
#pragma unroll
    for (int mi = 0; mi < 4; mi++)
#pragma unroll
        for (int nj = 0; nj < 4; nj++) {
            // trans pairing: n-tile (2nj) = (r0, r1), n-tile (2nj+1) = (r2, r3)
            mma_f16(c[mi][2 * nj],     af[mi], bf_[nj][0], bf_[nj][1]);
            mma_f16(c[mi][2 * nj + 1], af[mi], bf_[nj][2], bf_[nj][3]);
        }
}

// stage layout (av): A 0 (10240), B 10240 (8192); stage stride 18432
__device__ __forceinline__ void gemm_av(const __half* Af, int lda, const __half* Bf, int ldb,
                                        int nit, uint32_t sb, int tid, float c[4][8][4]) {
    const int lane = tid & 31, wid = tid >> 5;
    const int wm = wid >> 1, wn = wid & 1;
    const int la = lda * 2, lb = ldb * 2;
    cpa_A (sb,         Af, la, tid);
    cpa_BT(sb + 10240, Bf, lb, tid);
    CP_COMMIT();
    for (int it = 0; it < nit; it++) {
        if (it + 1 < nit) {
            const uint32_t nb = sb + ((it + 1) & 1) * 18432;
            const int ko = (it + 1) * 32;
            cpa_A (nb,         Af + ko, la, tid);
            cpa_BT(nb + 10240, Bf + (size_t)ko * ldb, lb, tid);
            CP_COMMIT();
            CP_WAIT1();
        } else {
            CP_WAIT0();
        }
        __syncthreads();
        const uint32_t sA = sb + (it & 1) * 18432;
        kstep_av(sA, sA + 10240, 0, lane, wm, wn, c);
        kstep_av(sA, sA + 10240, 1, lane, wm, wn, c);
        __syncthreads();
    }
}

// ---------------------------------------------------------------------------
// Elementwise split fp32 -> hi/lo bf16
// ---------------------------------------------------------------------------
__global__ void k_cvt(const float* __restrict__ x, bf16* __restrict__ hi,
                      bf16* __restrict__ lo, int n) {
    int i = blockIdx.x * 256 + threadIdx.x;
    const int stride = gridDim.x * 256;
    for (; i < n; i += stride) {
        bf16 h, l;
        split_bf16(x[i], h, l);
        hi[i] = h; lo[i] = l;
    }
}

// ---------------------------------------------------------------------------
// GEMM1: z=0: Q = X@WQK^T -> Qhi/Qlo ; z=1: V = X@WOV^T -> fp16 [m][d]
// ---------------------------------------------------------------------------
__global__ __launch_bounds__(128) void k_qv() {
    extern __shared__ __align__(256) char smem[];
    const uint32_t sb = smem_u32(smem);
    const int tid = threadIdx.x;
    const int z = blockIdx.z;
    const int m0 = blockIdx.y * 128, n0 = blockIdx.x * 128;
    float c[4][8][4] = {};
    gemm_hilo(g_Xhi + (size_t)m0 * D_, g_Xlo + (size_t)m0 * D_, D_,
              g_Whi[z] + (size_t)n0 * D_, g_Wlo[z] + (size_t)n0 * D_, D_,
              D_ / 32, sb, tid, c);
    const int lane = tid & 31, wid = tid >> 5;
    const int wm = wid >> 1, wn = wid & 1;
#pragma unroll
    for (int mi = 0; mi < 4; mi++) {
        const int r0 = m0 + wm * 64 + mi * 16 + (lane >> 2);
#pragma unroll
        for (int ni = 0; ni < 8; ni++) {
            const int gc = n0 + wn * 64 + ni * 8 + (lane & 3) * 2;
            const float* cc = c[mi][ni];
            if (z == 0) {
#pragma unroll
                for (int h = 0; h < 2; h++) {
                    const size_t idx = (size_t)(r0 + 8 * h) * D_ + gc;
                    bf16 h0, l0, h1, l1;
                    split_bf16(cc[2 * h],     h0, l0);
                    split_bf16(cc[2 * h + 1], h1, l1);
                    __nv_bfloat162 hh; hh.x = h0; hh.y = h1;
                    __nv_bfloat162 ll; ll.x = l0; ll.y = l1;
                    *(__nv_bfloat162*)(g_Qhi + idx) = hh;
                    *(__nv_bfloat162*)(g_Qlo + idx) = ll;
                }
            } else {
#pragma unroll
                for (int h = 0; h < 2; h++) {
                    const size_t idx = (size_t)(r0 + 8 * h) * D_ + gc;
                    *(__half2*)(g_Vh + idx) = __floats2half2_rn(cc[2 * h], cc[2 * h + 1]);
                }
            }
        }
    }
}

// ---------------------------------------------------------------------------
// GEMM2: Sc = 32 * Q@X^T (causal blocks only) -> Aout fp32
// ---------------------------------------------------------------------------
__global__ __launch_bounds__(128) void k_scores(float* __restrict__ Aout) {
    if (blockIdx.x > blockIdx.y) return;
    extern __shared__ __align__(256) char smem[];
    const uint32_t sb = smem_u32(smem);
    const int tid = threadIdx.x;
    const int b = blockIdx.z;
    const int m0 = blockIdx.y * 128, n0 = blockIdx.x * 128;
    const size_t xb = (size_t)b * S_ * D_;
    float c[4][8][4] = {};
    gemm_hilo(g_Qhi + xb + (size_t)m0 * D_, g_Qlo + xb + (size_t)m0 * D_, D_,
              g_Xhi + xb + (size_t)n0 * D_, g_Xlo + xb + (size_t)n0 * D_, D_,
              D_ / 32, sb, tid, c);
    const int lane = tid & 31, wid = tid >> 5;
    const int wm = wid >> 1, wn = wid & 1;
    float* Ab = Aout + (size_t)b * S_ * S_;
#pragma unroll
    for (int mi = 0; mi < 4; mi++) {
        const int r0 = m0 + wm * 64 + mi * 16 + (lane >> 2);
#pragma unroll
        for (int ni = 0; ni < 8; ni++) {
            const int gc = n0 + wn * 64 + ni * 8 + (lane & 3) * 2;
            const float* cc = c[mi][ni];
#pragma unroll
            for (int h = 0; h < 2; h++) {
                float2 v = make_float2(cc[2 * h] * 32.0f, cc[2 * h + 1] * 32.0f);
                *(float2*)(Ab + (size_t)(r0 + 8 * h) * S_ + gc) = v;
            }
        }
    }
}

// ---------------------------------------------------------------------------
// Softmax (causal, in place) + fp16 A emission. One 256-thread block per row.
// ---------------------------------------------------------------------------
__global__ void k_softmax(float* __restrict__ A) {
    const int s = blockIdx.x, b = blockIdx.y;
    const size_t rb = ((size_t)b * S_ + s) * S_;
    float* row = A + rb;
    __half* Ah = g_Ah + rb;
    const int len = s + 1;
    const int tid = threadIdx.x;
    __shared__ float red[256];

    float v[8];
    float m = -1e30f;
#pragma unroll
    for (int it = 0; it < 8; it++) {
        int j = tid + it * 256;
        v[it] = (j < len) ? row[j] : -1e30f;
        m = fmaxf(m, v[it]);
    }
    red[tid] = m; __syncthreads();
    for (int o = 128; o > 0; o >>= 1) {
        if (tid < o) red[tid] = fmaxf(red[tid], red[tid + o]);
        __syncthreads();
    }
    m = red[0]; __syncthreads();

    float sum = 0.0f;
#pragma unroll
    for (int it = 0; it < 8; it++) {
        int j = tid + it * 256;
        v[it] = (j < len) ? __expf(v[it] - m) : 0.0f;
        sum += v[it];
    }
    red[tid] = sum; __syncthreads();
    for (int o = 128; o > 0; o >>= 1) {
        if (tid < o) red[tid] += red[tid + o];
        __syncthreads();
    }
    const float inv = 1.0f / red[0];

#pragma unroll
    for (int it = 0; it < 8; it++) {
        int j = tid + it * 256;
        float a = v[it] * inv;
        row[j] = a;
        Ah[j]  = __float2half_rn(a);
    }
}

// ---------------------------------------------------------------------------
// GEMM3: Y = A@V (K truncated causally, fp16 single-pass), out = X + Y
// ---------------------------------------------------------------------------
__global__ __launch_bounds__(128) void k_av(const float* __restrict__ X,
                                            float* __restrict__ Yout) {
    extern __shared__ __align__(256) char smem[];
    const uint32_t sb = smem_u32(smem);
    const int tid = threadIdx.x;
    const int b = blockIdx.z;
    const int m0 = blockIdx.y * 128, n0 = blockIdx.x * 128;
    float c[4][8][4] = {};
    gemm_av(g_Ah + (size_t)b * S_ * S_ + (size_t)m0 * S_, S_,
            g_Vh + (size_t)b * S_ * D_ + n0, D_,
            (blockIdx.y + 1) * 4, sb, tid, c);
    const int lane = tid & 31, wid = tid >> 5;
    const int wm = wid >> 1, wn = wid & 1;
#pragma unroll
    for (int mi = 0; mi < 4; mi++) {
        const int r0 = m0 + wm * 64 + mi * 16 + (lane >> 2);
#pragma unroll
        for (int ni = 0; ni < 8; ni++) {
            const int gc = n0 + wn * 64 + ni * 8 + (lane & 3) * 2;
            const float* cc = c[mi][ni];
#pragma unroll
            for (int h = 0; h < 2; h++) {
                const size_t idx = ((size_t)b * S_ + (r0 + 8 * h)) * D_ + gc;
                float2 x2 = *(const float2*)(X + idx);
                float2 o = make_float2(cc[2 * h] + x2.x, cc[2 * h + 1] + x2.y);
                *(float2*)(Yout + idx) = o;
            }
        }
    }
}

// ---------------------------------------------------------------------------
#define SMEM_HILO 81920
#define SMEM_AV   36864

extern "C" void kernel_launch(void* const* d_in, const int* in_sizes, int n_in,
                              void* d_out, int out_size) {
    const float* X   = (const float*)d_in[0];
    const float* WQK = (const float*)d_in[2];
    const float* WOV = (const float*)d_in[3];
    float* out = (float*)d_out;

    const size_t nY = (size_t)M1 * D_;
    const size_t nA = (size_t)B_ * S_ * S_;
    float* Aout;
    if ((size_t)out_size >= nY + nA) {
        Aout = out + nY;
    } else {
        void* p = nullptr;
        cudaGetSymbolAddress(&p, g_Afallback);
        Aout = (float*)p;
    }

    static bool attrs_set = false;
    if (!attrs_set) {
        cudaFuncSetAttribute(k_qv,     cudaFuncAttributeMaxDynamicSharedMemorySize, SMEM_HILO);
        cudaFuncSetAttribute(k_scores, cudaFuncAttributeMaxDynamicSharedMemorySize, SMEM_HILO);
        cudaFuncSetAttribute(k_av,     cudaFuncAttributeMaxDynamicSharedMemorySize, SMEM_AV);
        attrs_set = true;
    }

    bf16 *xhi, *xlo, *whi, *wlo;
    { void* p; cudaGetSymbolAddress(&p, g_Xhi); xhi = (bf16*)p; }
    { void* p; cudaGetSymbolAddress(&p, g_Xlo); xlo = (bf16*)p; }
    { void* p; cudaGetSymbolAddress(&p, g_Whi); whi = (bf16*)p; }
    { void* p; cudaGetSymbolAddress(&p, g_Wlo); wlo = (bf16*)p; }

    // 1) fp32 -> hi/lo bf16 splits
    k_cvt<<<512, 256>>>(X,   xhi, xlo, M1 * D_);
    k_cvt<<<256, 256>>>(WQK, whi,                      wlo,                      D_ * D_);
    k_cvt<<<256, 256>>>(WOV, whi + (size_t)D_ * D_,    wlo + (size_t)D_ * D_,    D_ * D_);
    // 2) Q (hi/lo bf16) and V (fp16)
    k_qv<<<dim3(D_ / 128, M1 / 128, 2), 128, SMEM_HILO>>>();
    // 3) causal scaled scores -> A region (fp32)
    k_scores<<<dim3(S_ / 128, S_ / 128, B_), 128, SMEM_HILO>>>(Aout);
    // 4) softmax in place + A fp16
    k_softmax<<<dim3(S_, B_), 256>>>(Aout);
    // 5) Y = A@V + X
    k_av<<<dim3(D_ / 128, S_ / 128, B_), 128, SMEM_AV>>>(X, out);
}

// round 4
// speedup vs baseline: 3.2708x; 1.0440x over previous
#include <cuda_runtime.h>
#include <cuda_bf16.h>
#include <cuda_fp16.h>
#include <cstdint>

#define B_  4
#define S_  2048
#define D_  1024
#define M1  (B_ * S_)

typedef __nv_bfloat16 bf16;

// ---------------------------------------------------------------------------
// Scratch (__device__ globals; no allocation allowed)
// ---------------------------------------------------------------------------
__device__ __align__(256) bf16   g_Xhi[(size_t)M1 * D_];
__device__ __align__(256) bf16   g_Xlo[(size_t)M1 * D_];
__device__ __align__(256) __half g_Xh [(size_t)M1 * D_];
__device__ __align__(256) bf16   g_Whi[(size_t)D_ * D_];
__device__ __align__(256) bf16   g_Wlo[(size_t)D_ * D_];
__device__ __align__(256) __half g_Wh [(size_t)D_ * D_];
__device__ __align__(256) bf16   g_Qhi[(size_t)M1 * D_];
__device__ __align__(256) bf16   g_Qlo[(size_t)M1 * D_];
__device__ __align__(256) __half g_Vh [(size_t)M1 * D_];        // V [m][d]
__device__ __align__(256) __half g_Ah [(size_t)B_ * S_ * S_];   // A fp16 [s][t]
__device__ float g_Afallback[(size_t)B_ * S_ * S_];

// ---------------------------------------------------------------------------
// Baseline-PTX primitives (sm_80-era, assemble at compute_103)
// ---------------------------------------------------------------------------
__device__ __forceinline__ uint32_t smem_u32(const void* p) {
    uint32_t a;
    asm("{ .reg .u64 t; cvta.to.shared.u64 t, %1; cvt.u32.u64 %0, t; }" : "=r"(a) : "l"(p));
    return a;
}
#define CPA(dst, src)  asm volatile("cp.async.cg.shared.global [%0], [%1], 16;\n" :: "r"(dst), "l"(src))
#define CP_COMMIT()    asm volatile("cp.async.commit_group;\n" ::: "memory")
#define CP_WAIT1()     asm volatile("cp.async.wait_group 1;\n" ::: "memory")
#define CP_WAIT0()     asm volatile("cp.async.wait_group 0;\n" ::: "memory")

__device__ __forceinline__ void ldsm4(uint32_t r[4], uint32_t a) {
    asm volatile("ldmatrix.sync.aligned.m8n8.x4.shared.b16 {%0,%1,%2,%3}, [%4];\n"
                 : "=r"(r[0]), "=r"(r[1]), "=r"(r[2]), "=r"(r[3]) : "r"(a));
}
__device__ __forceinline__ void ldsm4t(uint32_t r[4], uint32_t a) {
    asm volatile("ldmatrix.sync.aligned.m8n8.x4.trans.shared.b16 {%0,%1,%2,%3}, [%4];\n"
                 : "=r"(r[0]), "=r"(r[1]), "=r"(r[2]), "=r"(r[3]) : "r"(a));
}
__device__ __forceinline__ void mma_bf16(float* c, const uint32_t a[4], uint32_t b0, uint32_t b1) {
    asm volatile("mma.sync.aligned.m16n8k16.row.col.f32.bf16.bf16.f32 "
                 "{%0,%1,%2,%3}, {%4,%5,%6,%7}, {%8,%9}, {%0,%1,%2,%3};\n"
                 : "+f"(c[0]), "+f"(c[1]), "+f"(c[2]), "+f"(c[3])
                 : "r"(a[0]), "r"(a[1]), "r"(a[2]), "r"(a[3]), "r"(b0), "r"(b1));
}
__device__ __forceinline__ void mma_f16(float* c, const uint32_t a[4], uint32_t b0, uint32_t b1) {
    asm volatile("mma.sync.aligned.m16n8k16.row.col.f32.f16.f16.f32 "
                 "{%0,%1,%2,%3}, {%4,%5,%6,%7}, {%8,%9}, {%0,%1,%2,%3};\n"
                 : "+f"(c[0]), "+f"(c[1]), "+f"(c[2]), "+f"(c[3])
                 : "r"(a[0]), "r"(a[1]), "r"(a[2]), "r"(a[3]), "r"(b0), "r"(b1));
}
__device__ __forceinline__ void split_bf16(float v, bf16& h, bf16& l) {
    h = __float2bfloat16_rn(v);
    l = __float2bfloat16_rn(v - __bfloat162float(h));
}

// ---------------------------------------------------------------------------
// Tile loaders: 256 threads.
// K-major tile: [ROWS rows][32 elems], smem rows 80B (conflict-free ldsm).
// ---------------------------------------------------------------------------
template<int ITERS>   // ITERS = ROWS/64
__device__ __forceinline__ void cpa_k(uint32_t sdst, const void* g, int ldbytes, int tid) {
#pragma unroll
    for (int i = 0; i < ITERS; i++) {
        int u = tid + i * 256;
        int r = u >> 2, c = u & 3;
        CPA(sdst + r * 80 + c * 16, (const char*)g + (size_t)r * ldbytes + c * 16);
    }
}
// Transposed tile: [32 k][128 n], 256B rows, XOR swizzle
__device__ __forceinline__ void cpa_t(uint32_t sdst, const void* g, int ldbytes, int tid) {
#pragma unroll
    for (int i = 0; i < 2; i++) {
        int u = tid + i * 256;
        int k = u >> 4, c = u & 15;
        CPA(sdst + k * 256 + ((c ^ ((k & 7) << 1)) << 4),
            (const char*)g + (size_t)k * ldbytes + c * 16);
    }
}

__device__ __forceinline__ void ld4frag(uint32_t base, uint32_t r[4][4]) {
#pragma unroll
    for (int i = 0; i < 4; i++) ldsm4(r[i], base + i * 1280);
}
__device__ __forceinline__ void mmas_bf16(float c[4][8][4], uint32_t a[4][4], uint32_t b[4][4]) {
#pragma unroll
    for (int mi = 0; mi < 4; mi++)
#pragma unroll
        for (int nj = 0; nj < 4; nj++) {
            mma_bf16(c[mi][2 * nj],     a[mi], b[nj][0], b[nj][2]);
            mma_bf16(c[mi][2 * nj + 1], a[mi], b[nj][1], b[nj][3]);
        }
}
__device__ __forceinline__ void mmas_f16(float c[4][8][4], uint32_t a[4][4], uint32_t b[4][4]) {
#pragma unroll
    for (int mi = 0; mi < 4; mi++)
#pragma unroll
        for (int nj = 0; nj < 4; nj++) {
            mma_f16(c[mi][2 * nj],     a[mi], b[nj][0], b[nj][2]);
            mma_f16(c[mi][2 * nj + 1], a[mi], b[nj][1], b[nj][3]);
        }
}

// ---------------------------------------------------------------------------
// hi/lo 3-pass GEMM: CTA 256x128, warps 4x2 (64x64 tiles)
// stage: Ahi 0 (20480), Alo 20480, Bhi 40960 (10240), Blo 51200; stride 61440
// ---------------------------------------------------------------------------
#define HL_ALO 20480
#define HL_BHI 40960
#define HL_STG 61440
#define SMEM_HILO (2 * HL_STG)

__device__ __forceinline__ void kstep_hilo(uint32_t stg, int ks, int lane,
                                           int wm, int wn, float c[4][8][4]) {
    const int row = lane & 15;
    const int ch  = (lane >> 4) + ks * 2;
    const uint32_t ao = stg + (wm * 64 + row) * 80 + ch * 16;
    const uint32_t bo = stg + HL_BHI + (wn * 64 + row) * 80 + ch * 16;
    uint32_t ah[4][4], bh[4][4], t[4][4];
    ld4frag(ao, ah);
    ld4frag(bo, bh);
    mmas_bf16(c, ah, bh);
    ld4frag(bo + 10240, t);     // Blo
    mmas_bf16(c, ah, t);
    ld4frag(ao + HL_ALO, t);    // Alo
    mmas_bf16(c, t, bh);
}

__device__ __forceinline__ void gemm_hilo(const bf16* Ah, const bf16* Al, int lda,
                                          const bf16* Bh, const bf16* Bl, int ldb,
                                          int nit, uint32_t sb, int tid, float c[4][8][4]) {
    const int lane = tid & 31, wid = tid >> 5;
    const int wm = wid >> 1, wn = wid & 1;
    const int la = lda * 2, lb = ldb * 2;
    cpa_k<4>(sb,           Ah, la, tid);
    cpa_k<4>(sb + HL_ALO,  Al, la, tid);
    cpa_k<2>(sb + HL_BHI,  Bh, lb, tid);
    cpa_k<2>(sb + HL_BHI + 10240, Bl, lb, tid);
    CP_COMMIT();
    for (int it = 0; it < nit; it++) {
        if (it + 1 < nit) {
            const uint32_t nb = sb + ((it + 1) & 1) * HL_STG;
            const int ko = (it + 1) * 32;
            cpa_k<4>(nb,           Ah + ko, la, tid);
            cpa_k<4>(nb + HL_ALO,  Al + ko, la, tid);
            cpa_k<2>(nb + HL_BHI,  Bh + ko, lb, tid);
            cpa_k<2>(nb + HL_BHI + 10240, Bl + ko, lb, tid);
            CP_COMMIT();
            CP_WAIT1();
        } else {
            CP_WAIT0();
        }
        __syncthreads();
        const uint32_t stg = sb + (it & 1) * HL_STG;
        kstep_hilo(stg, 0, lane, wm, wn, c);
        kstep_hilo(stg, 1, lane, wm, wn, c);
        __syncthreads();
    }
}

// ---------------------------------------------------------------------------
// fp16 single-pass GEMM, B K-major: CTA 256x128
// stage: A 0 (20480), B 20480 (10240); stride 30720
// ---------------------------------------------------------------------------
#define V_B   20480
#define V_STG 30720
#define SMEM_V (2 * V_STG)

__device__ __forceinline__ void gemm_f16nt(const __half* Af, int lda, const __half* Bf, int ldb,
                                           int nit, uint32_t sb, int tid, float c[4][8][4]) {
    const int lane = tid & 31, wid = tid >> 5;
    const int wm = wid >> 1, wn = wid & 1;
    const int la = lda * 2, lb = ldb * 2;
    cpa_k<4>(sb,       Af, la, tid);
    cpa_k<2>(sb + V_B, Bf, lb, tid);
    CP_COMMIT();
    for (int it = 0; it < nit; it++) {
        if (it + 1 < nit) {
            const uint32_t nb = sb + ((it + 1) & 1) * V_STG;
            const int ko = (it + 1) * 32;
            cpa_k<4>(nb,       Af + ko, la, tid);
            cpa_k<2>(nb + V_B, Bf + ko, lb, tid);
            CP_COMMIT();
            CP_WAIT1();
        } else {
            CP_WAIT0();
        }
        __syncthreads();
        const uint32_t stg = sb + (it & 1) * V_STG;
#pragma unroll
        for (int ks = 0; ks < 2; ks++) {
            const int row = lane & 15;
            const int ch  = (lane >> 4) + ks * 2;
            uint32_t ah[4][4], bh[4][4];
            ld4frag(stg + (wm * 64 + row) * 80 + ch * 16, ah);
            ld4frag(stg + V_B + (wn * 64 + row) * 80 + ch * 16, bh);
            mmas_f16(c, ah, bh);
        }
        __syncthreads();
    }
}

// ---------------------------------------------------------------------------
// fp16 single-pass GEMM, B transposed ([k][n], V layout): CTA 256x128
// stage: A 0 (20480), B 20480 (8192); stride 28672
// ---------------------------------------------------------------------------
#define AV_B   20480
#define AV_STG 28672
#define SMEM_AV (2 * AV_STG)

__device__ __forceinline__ void gemm_f16t(const __half* Af, int lda, const __half* Bf, int ldb,
                                          int nit, uint32_t sb, int tid, float c[4][8][4]) {
    const int lane = tid & 31, wid = tid >> 5;
    const int wm = wid >> 1, wn = wid & 1;
    const int la = lda * 2, lb = ldb * 2;
    cpa_k<4>(sb,        Af, la, tid);
    cpa_t  (sb + AV_B,  Bf, lb, tid);
    CP_COMMIT();
    for (int it = 0; it < nit; it++) {
        if (it + 1 < nit) {
            const uint32_t nb = sb + ((it + 1) & 1) * AV_STG;
            const int ko = (it + 1) * 32;
            cpa_k<4>(nb,       Af + ko, la, tid);
            cpa_t  (nb + AV_B, Bf + (size_t)ko * ldb, lb, tid);
            CP_COMMIT();
            CP_WAIT1();
        } else {
            CP_WAIT0();
        }
        __syncthreads();
        const uint32_t stg = sb + (it & 1) * AV_STG;
#pragma unroll
        for (int ks = 0; ks < 2; ks++) {
            const int row = lane & 15;
            uint32_t ah[4][4], bt[4][4];
            ld4frag(stg + (wm * 64 + row) * 80 + ((lane >> 4) + ks * 2) * 16, ah);
            const int k = ks * 16 + row;
#pragma unroll
            for (int nj = 0; nj < 4; nj++) {
                const int cl = wn * 8 + nj * 2 + (lane >> 4);
                ldsm4t(bt[nj], stg + AV_B + k * 256 + ((cl ^ ((k & 7) << 1)) << 4));
            }
#pragma unroll
            for (int mi = 0; mi < 4; mi++)
#pragma unroll
                for (int nj = 0; nj < 4; nj++) {
                    mma_f16(c[mi][2 * nj],     ah[mi], bt[nj][0], bt[nj][1]);
                    mma_f16(c[mi][2 * nj + 1], ah[mi], bt[nj][2], bt[nj][3]);
                }
        }
        __syncthreads();
    }
}

// ---------------------------------------------------------------------------
// Conversions
// ---------------------------------------------------------------------------
__global__ void k_cvtX(const float* __restrict__ x, int n) {
    int i = blockIdx.x * 256 + threadIdx.x;
    const int stride = gridDim.x * 256;
    for (; i < n; i += stride) {
        float v = x[i];
        bf16 h, l; split_bf16(v, h, l);
        g_Xhi[i] = h; g_Xlo[i] = l; g_Xh[i] = __float2half_rn(v);
    }
}
__global__ void k_cvtW(const float* __restrict__ wqk, const float* __restrict__ wov, int n) {
    int i = blockIdx.x * 256 + threadIdx.x;
    const int stride = gridDim.x * 256;
    for (; i < n; i += stride) {
        bf16 h, l; split_bf16(wqk[i], h, l);
        g_Whi[i] = h; g_Wlo[i] = l;
        g_Wh[i] = __float2half_rn(wov[i]);
    }
}

// ---------------------------------------------------------------------------
// GEMM kernels
// ---------------------------------------------------------------------------
__global__ __launch_bounds__(256, 1) void k_q() {
    extern __shared__ __align__(1024) char smem[];
    const uint32_t sb = smem_u32(smem);
    const int tid = threadIdx.x;
    const int m0 = blockIdx.y * 256, n0 = blockIdx.x * 128;
    float c[4][8][4] = {};
    gemm_hilo(g_Xhi + (size_t)m0 * D_, g_Xlo + (size_t)m0 * D_, D_,
              g_Whi + (size_t)n0 * D_, g_Wlo + (size_t)n0 * D_, D_,
              D_ / 32, sb, tid, c);
    const int lane = tid & 31, wid = tid >> 5;
    const int wm = wid >> 1, wn = wid & 1;
#pragma unroll
    for (int mi = 0; mi < 4; mi++) {
        const int r0 = m0 + wm * 64 + mi * 16 + (lane >> 2);
#pragma unroll
        for (int ni = 0; ni < 8; ni++) {
            const int gc = n0 + wn * 64 + ni * 8 + (lane & 3) * 2;
            const float* cc = c[mi][ni];
#pragma unroll
            for (int h = 0; h < 2; h++) {
                const size_t idx = (size_t)(r0 + 8 * h) * D_ + gc;
                bf16 h0, l0, h1, l1;
                split_bf16(cc[2 * h],     h0, l0);
                split_bf16(cc[2 * h + 1], h1, l1);
                __nv_bfloat162 hh; hh.x = h0; hh.y = h1;
                __nv_bfloat162 ll; ll.x = l0; ll.y = l1;
                *(__nv_bfloat162*)(g_Qhi + idx) = hh;
                *(__nv_bfloat162*)(g_Qlo + idx) = ll;
            }
        }
    }
}

__global__ __launch_bounds__(256, 1) void k_v() {
    extern __shared__ __align__(1024) char smem[];
    const uint32_t sb = smem_u32(smem);
    const int tid = threadIdx.x;
    const int m0 = blockIdx.y * 256, n0 = blockIdx.x * 128;
    float c[4][8][4] = {};
    gemm_f16nt(g_Xh + (size_t)m0 * D_, D_, g_Wh + (size_t)n0 * D_, D_,
               D_ / 32, sb, tid, c);
    const int lane = tid & 31, wid = tid >> 5;
    const int wm = wid >> 1, wn = wid & 1;
#pragma unroll
    for (int mi = 0; mi < 4; mi++) {
        const int r0 = m0 + wm * 64 + mi * 16 + (lane >> 2);
#pragma unroll
        for (int ni = 0; ni < 8; ni++) {
            const int gc = n0 + wn * 64 + ni * 8 + (lane & 3) * 2;
            const float* cc = c[mi][ni];
#pragma unroll
            for (int h = 0; h < 2; h++) {
                const size_t idx = (size_t)(r0 + 8 * h) * D_ + gc;
                *(__half2*)(g_Vh + idx) = __floats2half2_rn(cc[2 * h], cc[2 * h + 1]);
            }
        }
    }
}

__global__ __launch_bounds__(256, 1) void k_scores(float* __restrict__ Aout) {
    if ((int)blockIdx.x > 2 * (int)blockIdx.y + 1) return;   // fully above diagonal
    extern __shared__ __align__(1024) char smem[];
    const uint32_t sb = smem_u32(smem);
    const int tid = threadIdx.x;
    const int b = blockIdx.z;
    const int m0 = blockIdx.y * 256, n0 = blockIdx.x * 128;
    const size_t xb = (size_t)b * S_ * D_;
    float c[4][8][4] = {};
    gemm_hilo(g_Qhi + xb + (size_t)m0 * D_, g_Qlo + xb + (size_t)m0 * D_, D_,
              g_Xhi + xb + (size_t)n0 * D_, g_Xlo + xb + (size_t)n0 * D_, D_,
              D_ / 32, sb, tid, c);
    const int lane = tid & 31, wid = tid >> 5;
    const int wm = wid >> 1, wn = wid & 1;
    float* Ab = Aout + (size_t)b * S_ * S_;
#pragma unroll
    for (int mi = 0; mi < 4; mi++) {
        const int r0 = m0 + wm * 64 + mi * 16 + (lane >> 2);
#pragma unroll
        for (int ni = 0; ni < 8; ni++) {
            const int gc = n0 + wn * 64 + ni * 8 + (lane & 3) * 2;
            const float* cc = c[mi][ni];
#pragma unroll
            for (int h = 0; h < 2; h++) {
                float2 v = make_float2(cc[2 * h] * 32.0f, cc[2 * h + 1] * 32.0f);
                *(float2*)(Ab + (size_t)(r0 + 8 * h) * S_ + gc) = v;
            }
        }
    }
}

// ---------------------------------------------------------------------------
// Softmax (causal, in place) + fp16 A emission
// ---------------------------------------------------------------------------
__global__ void k_softmax(float* __restrict__ A) {
    const int s = blockIdx.x, b = blockIdx.y;
    const size_t rb = ((size_t)b * S_ + s) * S_;
    float* row = A + rb;
    __half* Ah = g_Ah + rb;
    const int len = s + 1;
    const int tid = threadIdx.x;
    __shared__ float red[256];

    float v[8];
    float m = -1e30f;
#pragma unroll
    for (int it = 0; it < 8; it++) {
        int j = tid + it * 256;
        v[it] = (j < len) ? row[j] : -1e30f;
        m = fmaxf(m, v[it]);
    }
    red[tid] = m; __syncthreads();
    for (int o = 128; o > 0; o >>= 1) {
        if (tid < o) red[tid] = fmaxf(red[tid], red[tid + o]);
        __syncthreads();
    }
    m = red[0]; __syncthreads();

    float sum = 0.0f;
#pragma unroll
    for (int it = 0; it < 8; it++) {
        int j = tid + it * 256;
        v[it] = (j < len) ? __expf(v[it] - m) : 0.0f;
        sum += v[it];
    }
    red[tid] = sum; __syncthreads();
    for (int o = 128; o > 0; o >>= 1) {
        if (tid < o) red[tid] += red[tid + o];
        __syncthreads();
    }
    const float inv = 1.0f / red[0];

#pragma unroll
    for (int it = 0; it < 8; it++) {
        int j = tid + it * 256;
        float a = v[it] * inv;
        row[j] = a;
        Ah[j]  = __float2half_rn(a);
    }
}

// ---------------------------------------------------------------------------
// GEMM3: Y = A@V (fp16, causal K-truncation), out = X + Y
// ---------------------------------------------------------------------------
__global__ __launch_bounds__(256, 1) void k_av(const float* __restrict__ X,
                                               float* __restrict__ Yout) {
    extern __shared__ __align__(1024) char smem[];
    const uint32_t sb = smem_u32(smem);
    const int tid = threadIdx.x;
    const int b = blockIdx.z;
    const int m0 = blockIdx.y * 256, n0 = blockIdx.x * 128;
    float c[4][8][4] = {};
    gemm_f16t(g_Ah + (size_t)b * S_ * S_ + (size_t)m0 * S_, S_,
              g_Vh + (size_t)b * S_ * D_ + n0, D_,
              (blockIdx.y + 1) * 8, sb, tid, c);
    const int lane = tid & 31, wid = tid >> 5;
    const int wm = wid >> 1, wn = wid & 1;
#pragma unroll
    for (int mi = 0; mi < 4; mi++) {
        const int r0 = m0 + wm * 64 + mi * 16 + (lane >> 2);
#pragma unroll
        for (int ni = 0; ni < 8; ni++) {
            const int gc = n0 + wn * 64 + ni * 8 + (lane & 3) * 2;
            const float* cc = c[mi][ni];
#pragma unroll
            for (int h = 0; h < 2; h++) {
                const size_t idx = ((size_t)b * S_ + (r0 + 8 * h)) * D_ + gc;
                float2 x2 = *(const float2*)(X + idx);
                float2 o = make_float2(cc[2 * h] + x2.x, cc[2 * h + 1] + x2.y);
                *(float2*)(Yout + idx) = o;
            }
        }
    }
}

// ---------------------------------------------------------------------------
extern "C" void kernel_launch(void* const* d_in, const int* in_sizes, int n_in,
                              void* d_out, int out_size) {
    const float* X   = (const float*)d_in[0];
    const float* WQK = (const float*)d_in[2];
    const float* WOV = (const float*)d_in[3];
    float* out = (float*)d_out;

    const size_t nY = (size_t)M1 * D_;
    const size_t nA = (size_t)B_ * S_ * S_;
    float* Aout;
    if ((size_t)out_size >= nY + nA) {
        Aout = out + nY;
    } else {
        void* p = nullptr;
        cudaGetSymbolAddress(&p, g_Afallback);
        Aout = (float*)p;
    }

    static bool attrs_set = false;
    if (!attrs_set) {
        cudaFuncSetAttribute(k_q,      cudaFuncAttributeMaxDynamicSharedMemorySize, SMEM_HILO);
        cudaFuncSetAttribute(k_scores, cudaFuncAttributeMaxDynamicSharedMemorySize, SMEM_HILO);
        cudaFuncSetAttribute(k_v,      cudaFuncAttributeMaxDynamicSharedMemorySize, SMEM_V);
        cudaFuncSetAttribute(k_av,     cudaFuncAttributeMaxDynamicSharedMemorySize, SMEM_AV);
        attrs_set = true;
    }

    // 1) conversions
    k_cvtX<<<512, 256>>>(X, M1 * D_);
    k_cvtW<<<256, 256>>>(WQK, WOV, D_ * D_);
    // 2) Q (hi/lo bf16, 3-pass) and V (fp16, 1-pass)
    k_q<<<dim3(D_ / 128, M1 / 256), 256, SMEM_HILO>>>();
    k_v<<<dim3(D_ / 128, M1 / 256), 256, SMEM_V>>>();
    // 3) causal scaled scores -> A region (fp32)
    k_scores<<<dim3(S_ / 128, S_ / 256, B_), 256, SMEM_HILO>>>(Aout);
    // 4) softmax in place + A fp16
    k_softmax<<<dim3(S_, B_), 256>>>(Aout);
    // 5) Y = A@V + X
    k_av<<<dim3(D_ / 128, S_ / 256, B_), 256, SMEM_AV>>>(X, out);
}

// round 5
// speedup vs baseline: 3.2897x; 1.0058x over previous
#include <cuda_runtime.h>
#include <cuda_bf16.h>
#include <cuda_fp16.h>
#include <cstdint>

#define B_  4
#define S_  2048
#define D_  1024
#define M1  (B_ * S_)

typedef __nv_bfloat16 bf16;

// ---------------------------------------------------------------------------
// Scratch (__device__ globals; no allocation allowed)
// ---------------------------------------------------------------------------
__device__ __align__(256) bf16   g_Xhi[(size_t)M1 * D_];
__device__ __align__(256) bf16   g_Xlo[(size_t)M1 * D_];
__device__ __align__(256) __half g_Xh [(size_t)M1 * D_];
__device__ __align__(256) bf16   g_Whi[(size_t)D_ * D_];
__device__ __align__(256) bf16   g_Wlo[(size_t)D_ * D_];
__device__ __align__(256) __half g_Wh [(size_t)D_ * D_];
__device__ __align__(256) bf16   g_Qhi[(size_t)M1 * D_];
__device__ __align__(256) bf16   g_Qlo[(size_t)M1 * D_];
__device__ __align__(256) __half g_Vh [(size_t)M1 * D_];        // V [m][d]
__device__ __align__(256) __half g_Ah [(size_t)B_ * S_ * S_];   // A fp16 [s][t]
__device__ float g_Afallback[(size_t)B_ * S_ * S_];

// ---------------------------------------------------------------------------
// Baseline-PTX primitives
// ---------------------------------------------------------------------------
__device__ __forceinline__ uint32_t smem_u32(const void* p) {
    uint32_t a;
    asm("{ .reg .u64 t; cvta.to.shared.u64 t, %1; cvt.u32.u64 %0, t; }" : "=r"(a) : "l"(p));
    return a;
}
#define CPA(dst, src)  asm volatile("cp.async.cg.shared.global [%0], [%1], 16;\n" :: "r"(dst), "l"(src))
#define CP_COMMIT()    asm volatile("cp.async.commit_group;\n" ::: "memory")
#define CP_WAIT1()     asm volatile("cp.async.wait_group 1;\n" ::: "memory")
#define CP_WAIT0()     asm volatile("cp.async.wait_group 0;\n" ::: "memory")

__device__ __forceinline__ void ldsm4(uint32_t r[4], uint32_t a) {
    asm volatile("ldmatrix.sync.aligned.m8n8.x4.shared.b16 {%0,%1,%2,%3}, [%4];\n"
                 : "=r"(r[0]), "=r"(r[1]), "=r"(r[2]), "=r"(r[3]) : "r"(a));
}
__device__ __forceinline__ void ldsm4t(uint32_t r[4], uint32_t a) {
    asm volatile("ldmatrix.sync.aligned.m8n8.x4.trans.shared.b16 {%0,%1,%2,%3}, [%4];\n"
                 : "=r"(r[0]), "=r"(r[1]), "=r"(r[2]), "=r"(r[3]) : "r"(a));
}
__device__ __forceinline__ void mma_bf16(float* c, const uint32_t a[4], uint32_t b0, uint32_t b1) {
    asm volatile("mma.sync.aligned.m16n8k16.row.col.f32.bf16.bf16.f32 "
                 "{%0,%1,%2,%3}, {%4,%5,%6,%7}, {%8,%9}, {%0,%1,%2,%3};\n"
                 : "+f"(c[0]), "+f"(c[1]), "+f"(c[2]), "+f"(c[3])
                 : "r"(a[0]), "r"(a[1]), "r"(a[2]), "r"(a[3]), "r"(b0), "r"(b1));
}
__device__ __forceinline__ void mma_f16(float* c, const uint32_t a[4], uint32_t b0, uint32_t b1) {
    asm volatile("mma.sync.aligned.m16n8k16.row.col.f32.f16.f16.f32 "
                 "{%0,%1,%2,%3}, {%4,%5,%6,%7}, {%8,%9}, {%0,%1,%2,%3};\n"
                 : "+f"(c[0]), "+f"(c[1]), "+f"(c[2]), "+f"(c[3])
                 : "r"(a[0]), "r"(a[1]), "r"(a[2]), "r"(a[3]), "r"(b0), "r"(b1));
}
__device__ __forceinline__ void split_bf16(float v, bf16& h, bf16& l) {
    h = __float2bfloat16_rn(v);
    l = __float2bfloat16_rn(v - __bfloat162float(h));
}

// ---------------------------------------------------------------------------
// Tile loaders: 512 threads. K-major [rows][32], smem row stride 80B.
// ---------------------------------------------------------------------------
template<int ITERS>   // ITERS = rows/128
__device__ __forceinline__ void cpa_k(uint32_t sdst, const void* g, int ldbytes, int tid) {
#pragma unroll
    for (int i = 0; i < ITERS; i++) {
        int u = tid + i * 512;
        int r = u >> 2, c = u & 3;
        CPA(sdst + r * 80 + c * 16, (const char*)g + (size_t)r * ldbytes + c * 16);
    }
}
// Transposed tile [32 k][128 n], 256B rows, XOR swizzle (512 threads, 1 iter)
__device__ __forceinline__ void cpa_t(uint32_t sdst, const void* g, int ldbytes, int tid) {
    int k = tid >> 4, c = tid & 15;
    CPA(sdst + k * 256 + ((c ^ ((k & 7) << 1)) << 4),
        (const char*)g + (size_t)k * ldbytes + c * 16);
}

__device__ __forceinline__ void ld4frag(uint32_t base, uint32_t r[4][4]) {
#pragma unroll
    for (int i = 0; i < 4; i++) ldsm4(r[i], base + i * 1280);
}
__device__ __forceinline__ void ld2frag(uint32_t base, uint32_t r[2][4]) {
    ldsm4(r[0], base);
    ldsm4(r[1], base + 1280);
}
__device__ __forceinline__ void mmas_bf16(float c[4][4][4], uint32_t a[4][4], uint32_t b[2][4]) {
#pragma unroll
    for (int mi = 0; mi < 4; mi++)
#pragma unroll
        for (int nj = 0; nj < 2; nj++) {
            mma_bf16(c[mi][2 * nj],     a[mi], b[nj][0], b[nj][2]);
            mma_bf16(c[mi][2 * nj + 1], a[mi], b[nj][1], b[nj][3]);
        }
}
__device__ __forceinline__ void mmas_f16(float c[4][4][4], uint32_t a[4][4], uint32_t b[2][4]) {
#pragma unroll
    for (int mi = 0; mi < 4; mi++)
#pragma unroll
        for (int nj = 0; nj < 2; nj++) {
            mma_f16(c[mi][2 * nj],     a[mi], b[nj][0], b[nj][2]);
            mma_f16(c[mi][2 * nj + 1], a[mi], b[nj][1], b[nj][3]);
        }
}

// ---------------------------------------------------------------------------
// hi/lo 3-pass GEMM: CTA 256x128, 16 warps (4m x 4n), warp tile 64x32
// stage: Ahi 0(20480) Alo 20480 Bhi 40960(10240) Blo 51200(10240); stride 61440
// ---------------------------------------------------------------------------
#define HL_ALO 20480
#define HL_BHI 40960
#define HL_BLO 51200
#define HL_STG 61440
#define SMEM_HILO (3 * HL_STG)

__device__ __forceinline__ void kstep_hilo(uint32_t stg, int ks, int lane,
                                           int wm, int wn, float c[4][4][4]) {
    const int row = lane & 15;
    const int ch  = (lane >> 4) + ks * 2;
    const uint32_t ao = stg + (wm * 64 + row) * 80 + ch * 16;
    const uint32_t bo = stg + HL_BHI + (wn * 32 + row) * 80 + ch * 16;
    uint32_t ah[4][4], bh[2][4];
    ld4frag(ao, ah);
    ld2frag(bo, bh);
    mmas_bf16(c, ah, bh);
    {
        uint32_t bl[2][4];
        ld2frag(bo + (HL_BLO - HL_BHI), bl);
        mmas_bf16(c, ah, bl);
    }
    {
        uint32_t al[4][4];
        ld4frag(ao + HL_ALO, al);
        mmas_bf16(c, al, bh);
    }
}

#define HL_LOAD(saddr, ko)                                        \
    do {                                                          \
        cpa_k<2>((saddr),           Ah + (ko), la, tid);          \
        cpa_k<2>((saddr) + HL_ALO,  Al + (ko), la, tid);          \
        cpa_k<1>((saddr) + HL_BHI,  Bh + (ko), lb, tid);          \
        cpa_k<1>((saddr) + HL_BLO,  Bl + (ko), lb, tid);          \
        CP_COMMIT();                                              \
    } while (0)

__device__ __forceinline__ void gemm_hilo(const bf16* Ah, const bf16* Al, int lda,
                                          const bf16* Bh, const bf16* Bl, int ldb,
                                          int nit, uint32_t sb, int tid, float c[4][4][4]) {
    const int lane = tid & 31, wid = tid >> 5;
    const int wm = wid & 3, wn = wid >> 2;
    const int la = lda * 2, lb = ldb * 2;
    HL_LOAD(sb, 0);
    HL_LOAD(sb + HL_STG, 32);
    int si = 0;
    for (int it = 0; it < nit; it++) {
        if (it + 1 < nit) { CP_WAIT1(); } else { CP_WAIT0(); }
        __syncthreads();
        if (it + 2 < nit) {
            int s2 = si + 2; if (s2 >= 3) s2 -= 3;
            HL_LOAD(sb + s2 * HL_STG, (it + 2) * 32);
        }
        const uint32_t stg = sb + si * HL_STG;
        kstep_hilo(stg, 0, lane, wm, wn, c);
        kstep_hilo(stg, 1, lane, wm, wn, c);
        if (++si == 3) si = 0;
    }
}

// ---------------------------------------------------------------------------
// fp16 single-pass GEMM (B K-major): CTA 256x128
// stage: A 0(20480) B 20480(10240); stride 30720
// ---------------------------------------------------------------------------
#define V_B   20480
#define V_STG 30720
#define SMEM_V (3 * V_STG)

#define V_LOAD(saddr, ko)                                         \
    do {                                                          \
        cpa_k<2>((saddr),        Af + (ko), la, tid);             \
        cpa_k<1>((saddr) + V_B,  Bf + (ko), lb, tid);             \
        CP_COMMIT();                                              \
    } while (0)

__device__ __forceinline__ void gemm_f16nt(const __half* Af, int lda, const __half* Bf, int ldb,
                                           int nit, uint32_t sb, int tid, float c[4][4][4]) {
    const int lane = tid & 31, wid = tid >> 5;
    const int wm = wid & 3, wn = wid >> 2;
    const int la = lda * 2, lb = ldb * 2;
    V_LOAD(sb, 0);
    V_LOAD(sb + V_STG, 32);
    int si = 0;
    for (int it = 0; it < nit; it++) {
        if (it + 1 < nit) { CP_WAIT1(); } else { CP_WAIT0(); }
        __syncthreads();
        if (it + 2 < nit) {
            int s2 = si + 2; if (s2 >= 3) s2 -= 3;
            V_LOAD(sb + s2 * V_STG, (it + 2) * 32);
        }
        const uint32_t stg = sb + si * V_STG;
#pragma unroll
        for (int ks = 0; ks < 2; ks++) {
            const int row = lane & 15;
            const int ch  = (lane >> 4) + ks * 2;
            uint32_t ah[4][4], bh[2][4];
            ld4frag(stg + (wm * 64 + row) * 80 + ch * 16, ah);
            ld2frag(stg + V_B + (wn * 32 + row) * 80 + ch * 16, bh);
            mmas_f16(c, ah, bh);
        }
        if (++si == 3) si = 0;
    }
}

// ---------------------------------------------------------------------------
// fp16 single-pass GEMM (B transposed [k][n]): CTA 256x128
// stage: A 0(20480) B 20480(8192); stride 28672
// ---------------------------------------------------------------------------
#define AV_B   20480
#define AV_STG 28672
#define SMEM_AV (3 * AV_STG)

#define AV_LOAD(saddr, ko)                                        \
    do {                                                          \
        cpa_k<2>((saddr),         Af + (ko), la, tid);            \
        cpa_t   ((saddr) + AV_B,  Bf + (size_t)(ko) * ldb, lb, tid); \
        CP_COMMIT();                                              \
    } while (0)

__device__ __forceinline__ void gemm_f16t(const __half* Af, int lda, const __half* Bf, int ldb,
                                          int nit, uint32_t sb, int tid, float c[4][4][4]) {
    const int lane = tid & 31, wid = tid >> 5;
    const int wm = wid & 3, wn = wid >> 2;
    const int la = lda * 2, lb = ldb * 2;
    AV_LOAD(sb, 0);
    AV_LOAD(sb + AV_STG, 32);
    int si = 0;
    for (int it = 0; it < nit; it++) {
        if (it + 1 < nit) { CP_WAIT1(); } else { CP_WAIT0(); }
        __syncthreads();
        if (it + 2 < nit) {
            int s2 = si + 2; if (s2 >= 3) s2 -= 3;
            AV_LOAD(sb + s2 * AV_STG, (it + 2) * 32);
        }
        const uint32_t stg = sb + si * AV_STG;
#pragma unroll
        for (int ks = 0; ks < 2; ks++) {
            const int row = lane & 15;
            uint32_t ah[4][4], bt[2][4];
            ld4frag(stg + (wm * 64 + row) * 80 + ((lane >> 4) + ks * 2) * 16, ah);
            const int k = ks * 16 + row;
#pragma unroll
            for (int nj = 0; nj < 2; nj++) {
                const int cl = wn * 4 + nj * 2 + (lane >> 4);
                ldsm4t(bt[nj], stg + AV_B + k * 256 + ((cl ^ ((k & 7) << 1)) << 4));
            }
#pragma unroll
            for (int mi = 0; mi < 4; mi++)
#pragma unroll
                for (int nj = 0; nj < 2; nj++) {
                    mma_f16(c[mi][2 * nj],     ah[mi], bt[nj][0], bt[nj][1]);
                    mma_f16(c[mi][2 * nj + 1], ah[mi], bt[nj][2], bt[nj][3]);
                }
        }
        if (++si == 3) si = 0;
    }
}

// ---------------------------------------------------------------------------
// Conversions
// ---------------------------------------------------------------------------
__global__ void k_cvtX(const float* __restrict__ x, int n) {
    int i = blockIdx.x * 256 + threadIdx.x;
    const int stride = gridDim.x * 256;
    for (; i < n; i += stride) {
        float v = x[i];
        bf16 h, l; split_bf16(v, h, l);
        g_Xhi[i] = h; g_Xlo[i] = l; g_Xh[i] = __float2half_rn(v);
    }
}
__global__ void k_cvtW(const float* __restrict__ wqk, const float* __restrict__ wov, int n) {
    int i = blockIdx.x * 256 + threadIdx.x;
    const int stride = gridDim.x * 256;
    for (; i < n; i += stride) {
        bf16 h, l; split_bf16(wqk[i], h, l);
        g_Whi[i] = h; g_Wlo[i] = l;
        g_Wh[i] = __float2half_rn(wov[i]);
    }
}

// ---------------------------------------------------------------------------
// GEMM kernels (512 threads, CTA tile 256x128)
// ---------------------------------------------------------------------------
__global__ __launch_bounds__(512, 1) void k_q() {
    extern __shared__ __align__(1024) char smem[];
    const uint32_t sb = smem_u32(smem);
    const int tid = threadIdx.x;
    const int m0 = blockIdx.y * 256, n0 = blockIdx.x * 128;
    float c[4][4][4] = {};
    gemm_hilo(g_Xhi + (size_t)m0 * D_, g_Xlo + (size_t)m0 * D_, D_,
              g_Whi + (size_t)n0 * D_, g_Wlo + (size_t)n0 * D_, D_,
              D_ / 32, sb, tid, c);
    const int lane = tid & 31, wid = tid >> 5;
    const int wm = wid & 3, wn = wid >> 2;
#pragma unroll
    for (int mi = 0; mi < 4; mi++) {
        const int r0 = m0 + wm * 64 + mi * 16 + (lane >> 2);
#pragma unroll
        for (int ni = 0; ni < 4; ni++) {
            const int gc = n0 + wn * 32 + ni * 8 + (lane & 3) * 2;
            const float* cc = c[mi][ni];
#pragma unroll
            for (int h = 0; h < 2; h++) {
                const size_t idx = (size_t)(r0 + 8 * h) * D_ + gc;
                bf16 h0, l0, h1, l1;
                split_bf16(cc[2 * h],     h0, l0);
                split_bf16(cc[2 * h + 1], h1, l1);
                __nv_bfloat162 hh; hh.x = h0; hh.y = h1;
                __nv_bfloat162 ll; ll.x = l0; ll.y = l1;
                *(__nv_bfloat162*)(g_Qhi + idx) = hh;
                *(__nv_bfloat162*)(g_Qlo + idx) = ll;
            }
        }
    }
}

__global__ __launch_bounds__(512, 1) void k_v() {
    extern __shared__ __align__(1024) char smem[];
    const uint32_t sb = smem_u32(smem);
    const int tid = threadIdx.x;
    const int m0 = blockIdx.y * 256, n0 = blockIdx.x * 128;
    float c[4][4][4] = {};
    gemm_f16nt(g_Xh + (size_t)m0 * D_, D_, g_Wh + (size_t)n0 * D_, D_,
               D_ / 32, sb, tid, c);
    const int lane = tid & 31, wid = tid >> 5;
    const int wm = wid & 3, wn = wid >> 2;
#pragma unroll
    for (int mi = 0; mi < 4; mi++) {
        const int r0 = m0 + wm * 64 + mi * 16 + (lane >> 2);
#pragma unroll
        for (int ni = 0; ni < 4; ni++) {
            const int gc = n0 + wn * 32 + ni * 8 + (lane & 3) * 2;
            const float* cc = c[mi][ni];
#pragma unroll
            for (int h = 0; h < 2; h++) {
                const size_t idx = (size_t)(r0 + 8 * h) * D_ + gc;
                *(__half2*)(g_Vh + idx) = __floats2half2_rn(cc[2 * h], cc[2 * h + 1]);
            }
        }
    }
}

__global__ __launch_bounds__(512, 1) void k_scores(float* __restrict__ Aout) {
    if ((int)blockIdx.x > 2 * (int)blockIdx.y + 1) return;   // fully above diagonal
    extern __shared__ __align__(1024) char smem[];
    const uint32_t sb = smem_u32(smem);
    const int tid = threadIdx.x;
    const int b = blockIdx.z;
    const int m0 = blockIdx.y * 256, n0 = blockIdx.x * 128;
    const size_t xb = (size_t)b * S_ * D_;
    float c[4][4][4] = {};
    gemm_hilo(g_Qhi + xb + (size_t)m0 * D_, g_Qlo + xb + (size_t)m0 * D_, D_,
              g_Xhi + xb + (size_t)n0 * D_, g_Xlo + xb + (size_t)n0 * D_, D_,
              D_ / 32, sb, tid, c);
    const int lane = tid & 31, wid = tid >> 5;
    const int wm = wid & 3, wn = wid >> 2;
    float* Ab = Aout + (size_t)b * S_ * S_;
#pragma unroll
    for (int mi = 0; mi < 4; mi++) {
        const int r0 = m0 + wm * 64 + mi * 16 + (lane >> 2);
#pragma unroll
        for (int ni = 0; ni < 4; ni++) {
            const int gc = n0 + wn * 32 + ni * 8 + (lane & 3) * 2;
            const float* cc = c[mi][ni];
#pragma unroll
            for (int h = 0; h < 2; h++) {
                float2 v = make_float2(cc[2 * h] * 32.0f, cc[2 * h + 1] * 32.0f);
                *(float2*)(Ab + (size_t)(r0 + 8 * h) * S_ + gc) = v;
            }
        }
    }
}

// ---------------------------------------------------------------------------
// Softmax (causal, in place) + fp16 A emission
// ---------------------------------------------------------------------------
__global__ void k_softmax(float* __restrict__ A) {
    const int s = blockIdx.x, b = blockIdx.y;
    const size_t rb = ((size_t)b * S_ + s) * S_;
    float* row = A + rb;
    __half* Ah = g_Ah + rb;
    const int len = s + 1;
    const int tid = threadIdx.x;
    __shared__ float red[256];

    float v[8];
    float m = -1e30f;
#pragma unroll
    for (int it = 0; it < 8; it++) {
        int j = tid + it * 256;
        v[it] = (j < len) ? row[j] : -1e30f;
        m = fmaxf(m, v[it]);
    }
    red[tid] = m; __syncthreads();
    for (int o = 128; o > 0; o >>= 1) {
        if (tid < o) red[tid] = fmaxf(red[tid], red[tid + o]);
        __syncthreads();
    }
    m = red[0]; __syncthreads();

    float sum = 0.0f;
#pragma unroll
    for (int it = 0; it < 8; it++) {
        int j = tid + it * 256;
        v[it] = (j < len) ? __expf(v[it] - m) : 0.0f;
        sum += v[it];
    }
    red[tid] = sum; __syncthreads();
    for (int o = 128; o > 0; o >>= 1) {
        if (tid < o) red[tid] += red[tid + o];
        __syncthreads();
    }
    const float inv = 1.0f / red[0];

#pragma unroll
    for (int it = 0; it < 8; it++) {
        int j = tid + it * 256;
        float a = v[it] * inv;
        row[j] = a;
        Ah[j]  = __float2half_rn(a);
    }
}

// ---------------------------------------------------------------------------
// GEMM3: Y = A@V (fp16, causal K-truncation), out = X + Y
// ---------------------------------------------------------------------------
__global__ __launch_bounds__(512, 1) void k_av(const float* __restrict__ X,
                                               float* __restrict__ Yout) {
    extern __shared__ __align__(1024) char smem[];
    const uint32_t sb = smem_u32(smem);
    const int tid = threadIdx.x;
    const int b = blockIdx.z;
    const int m0 = blockIdx.y * 256, n0 = blockIdx.x * 128;
    float c[4][4][4] = {};
    gemm_f16t(g_Ah + (size_t)b * S_ * S_ + (size_t)m0 * S_, S_,
              g_Vh + (size_t)b * S_ * D_ + n0, D_,
              (blockIdx.y + 1) * 8, sb, tid, c);
    const int lane = tid & 31, wid = tid >> 5;
    const int wm = wid & 3, wn = wid >> 2;
#pragma unroll
    for (int mi = 0; mi < 4; mi++) {
        const int r0 = m0 + wm * 64 + mi * 16 + (lane >> 2);
#pragma unroll
        for (int ni = 0; ni < 4; ni++) {
            const int gc = n0 + wn * 32 + ni * 8 + (lane & 3) * 2;
            const float* cc = c[mi][ni];
#pragma unroll
            for (int h = 0; h < 2; h++) {
                const size_t idx = ((size_t)b * S_ + (r0 + 8 * h)) * D_ + gc;
                float2 x2 = *(const float2*)(X + idx);
                float2 o = make_float2(cc[2 * h] + x2.x, cc[2 * h + 1] + x2.y);
                *(float2*)(Yout + idx) = o;
            }
        }
    }
}

// ---------------------------------------------------------------------------
extern "C" void kernel_launch(void* const* d_in, const int* in_sizes, int n_in,
                              void* d_out, int out_size) {
    const float* X   = (const float*)d_in[0];
    const float* WQK = (const float*)d_in[2];
    const float* WOV = (const float*)d_in[3];
    float* out = (float*)d_out;

    const size_t nY = (size_t)M1 * D_;
    const size_t nA = (size_t)B_ * S_ * S_;
    float* Aout;
    if ((size_t)out_size >= nY + nA) {
        Aout = out + nY;
    } else {
        void* p = nullptr;
        cudaGetSymbolAddress(&p, g_Afallback);
        Aout = (float*)p;
    }

    static bool attrs_set = false;
    if (!attrs_set) {
        cudaFuncSetAttribute(k_q,      cudaFuncAttributeMaxDynamicSharedMemorySize, SMEM_HILO);
        cudaFuncSetAttribute(k_scores, cudaFuncAttributeMaxDynamicSharedMemorySize, SMEM_HILO);
        cudaFuncSetAttribute(k_v,      cudaFuncAttributeMaxDynamicSharedMemorySize, SMEM_V);
        cudaFuncSetAttribute(k_av,     cudaFuncAttributeMaxDynamicSharedMemorySize, SMEM_AV);
        attrs_set = true;
    }

    // 1) conversions
    k_cvtX<<<512, 256>>>(X, M1 * D_);
    k_cvtW<<<256, 256>>>(WQK, WOV, D_ * D_);
    // 2) Q (hi/lo bf16, 3-pass) and V (fp16, 1-pass)
    k_q<<<dim3(D_ / 128, M1 / 256), 512, SMEM_HILO>>>();
    k_v<<<dim3(D_ / 128, M1 / 256), 512, SMEM_V>>>();
    // 3) causal scaled scores -> A region (fp32)
    k_scores<<<dim3(S_ / 128, S_ / 256, B_), 512, SMEM_HILO>>>(Aout);
    // 4) softmax in place + A fp16
    k_softmax<<<dim3(S_, B_), 256>>>(Aout);
    // 5) Y = A@V + X
    k_av<<<dim3(D_ / 128, S_ / 256, B_), 512, SMEM_AV>>>(X, out);
}

// round 7
// speedup vs baseline: 3.3559x; 1.0201x over previous
#include <cuda_runtime.h>
#include <cuda_bf16.h>
#include <cuda_fp16.h>
#include <cstdint>

#define B_  4
#define S_  2048
#define D_  1024
#define M1  (B_ * S_)

typedef __nv_bfloat16 bf16;

// ---------------------------------------------------------------------------
// Scratch (__device__ globals; no allocation allowed)
// ---------------------------------------------------------------------------
__device__ __align__(256) bf16   g_Xhi[(size_t)M1 * D_];
__device__ __align__(256) bf16   g_Xlo[(size_t)M1 * D_];
__device__ __align__(256) __half g_Xh [(size_t)M1 * D_];
__device__ __align__(256) bf16   g_Whi[(size_t)D_ * D_];
__device__ __align__(256) bf16   g_Wlo[(size_t)D_ * D_];
__device__ __align__(256) __half g_Wh [(size_t)D_ * D_];
__device__ __align__(256) bf16   g_Qhi[(size_t)M1 * D_];
__device__ __align__(256) bf16   g_Qlo[(size_t)M1 * D_];
__device__ __align__(256) __half g_Vh [(size_t)M1 * D_];        // V [m][d]
__device__ __align__(256) __half g_Ah [(size_t)B_ * S_ * S_];   // A fp16 [s][t]
__device__ float g_Afallback[(size_t)B_ * S_ * S_];

// ---------------------------------------------------------------------------
// Baseline-PTX primitives
// ---------------------------------------------------------------------------
__device__ __forceinline__ uint32_t smem_u32(const void* p) {
    uint32_t a;
    asm("{ .reg .u64 t; cvta.to.shared.u64 t, %1; cvt.u32.u64 %0, t; }" : "=r"(a) : "l"(p));
    return a;
}
#define CPA(dst, src)  asm volatile("cp.async.cg.shared.global [%0], [%1], 16;\n" :: "r"(dst), "l"(src))
#define CP_COMMIT()    asm volatile("cp.async.commit_group;\n" ::: "memory")
#define CP_WAIT1()     asm volatile("cp.async.wait_group 1;\n" ::: "memory")
#define CP_WAIT0()     asm volatile("cp.async.wait_group 0;\n" ::: "memory")

__device__ __forceinline__ void ldsm4(uint32_t r[4], uint32_t a) {
    asm volatile("ldmatrix.sync.aligned.m8n8.x4.shared.b16 {%0,%1,%2,%3}, [%4];\n"
                 : "=r"(r[0]), "=r"(r[1]), "=r"(r[2]), "=r"(r[3]) : "r"(a));
}
__device__ __forceinline__ void ldsm4t(uint32_t r[4], uint32_t a) {
    asm volatile("ldmatrix.sync.aligned.m8n8.x4.trans.shared.b16 {%0,%1,%2,%3}, [%4];\n"
                 : "=r"(r[0]), "=r"(r[1]), "=r"(r[2]), "=r"(r[3]) : "r"(a));
}
__device__ __forceinline__ void mma_bf16(float* c, const uint32_t a[4], uint32_t b0, uint32_t b1) {
    asm volatile("mma.sync.aligned.m16n8k16.row.col.f32.bf16.bf16.f32 "
                 "{%0,%1,%2,%3}, {%4,%5,%6,%7}, {%8,%9}, {%0,%1,%2,%3};\n"
                 : "+f"(c[0]), "+f"(c[1]), "+f"(c[2]), "+f"(c[3])
                 : "r"(a[0]), "r"(a[1]), "r"(a[2]), "r"(a[3]), "r"(b0), "r"(b1));
}
__device__ __forceinline__ void mma_f16(float* c, const uint32_t a[4], uint32_t b0, uint32_t b1) {
    asm volatile("mma.sync.aligned.m16n8k16.row.col.f32.f16.f16.f32 "
                 "{%0,%1,%2,%3}, {%4,%5,%6,%7}, {%8,%9}, {%0,%1,%2,%3};\n"
                 : "+f"(c[0]), "+f"(c[1]), "+f"(c[2]), "+f"(c[3])
                 : "r"(a[0]), "r"(a[1]), "r"(a[2]), "r"(a[3]), "r"(b0), "r"(b1));
}
__device__ __forceinline__ void split_bf16(float v, bf16& h, bf16& l) {
    h = __float2bfloat16_rn(v);
    l = __float2bfloat16_rn(v - __bfloat162float(h));
}

// ---------------------------------------------------------------------------
// Tile loaders: 512 threads. K-major [rows][32], smem row stride 80B.
// ---------------------------------------------------------------------------
template<int ITERS>   // ITERS = rows/128
__device__ __forceinline__ void cpa_k(uint32_t sdst, const void* g, int ldbytes, int tid) {
#pragma unroll
    for (int i = 0; i < ITERS; i++) {
        int u = tid + i * 512;
        int r = u >> 2, c = u & 3;
        CPA(sdst + r * 80 + c * 16, (const char*)g + (size_t)r * ldbytes + c * 16);
    }
}
// Transposed tile [32 k][128 n], 256B rows, XOR swizzle (512 threads)
__device__ __forceinline__ void cpa_t(uint32_t sdst, const void* g, int ldbytes, int tid) {
    int k = tid >> 4, c = tid & 15;
    CPA(sdst + k * 256 + ((c ^ ((k & 7) << 1)) << 4),
        (const char*)g + (size_t)k * ldbytes + c * 16);
}

__device__ __forceinline__ void ld4frag(uint32_t base, uint32_t r[4][4]) {
#pragma unroll
    for (int i = 0; i < 4; i++) ldsm4(r[i], base + i * 1280);
}
__device__ __forceinline__ void ld2frag(uint32_t base, uint32_t r[2][4]) {
    ldsm4(r[0], base);
    ldsm4(r[1], base + 1280);
}
// A fragment (64 rows), K-major smem
__device__ __forceinline__ void ldA64(uint32_t r[4][4], uint32_t stg, int wm, int lane, int ks) {
    const int row = lane & 15;
    const int ch  = (lane >> 4) + ks * 2;
    ld4frag(stg + (wm * 64 + row) * 80 + ch * 16, r);
}
// B fragment (32 rows), K-major smem
__device__ __forceinline__ void ldB32(uint32_t r[2][4], uint32_t stgb, int wn, int lane, int ks) {
    const int row = lane & 15;
    const int ch  = (lane >> 4) + ks * 2;
    ld2frag(stgb + (wn * 32 + row) * 80 + ch * 16, r);
}
// B fragment from transposed [k][n] smem (ldsm trans)
__device__ __forceinline__ void ldBT32(uint32_t r[2][4], uint32_t bbase, int wn, int lane, int ks) {
    const int k = ks * 16 + (lane & 15);
#pragma unroll
    for (int nj = 0; nj < 2; nj++) {
        const int cl = wn * 4 + nj * 2 + (lane >> 4);
        ldsm4t(r[nj], bbase + k * 256 + ((cl ^ ((k & 7) << 1)) << 4));
    }
}

__device__ __forceinline__ void mmas_bf16(float c[4][4][4], uint32_t a[4][4], uint32_t b[2][4]) {
#pragma unroll
    for (int mi = 0; mi < 4; mi++)
#pragma unroll
        for (int nj = 0; nj < 2; nj++) {
            mma_bf16(c[mi][2 * nj],     a[mi], b[nj][0], b[nj][2]);
            mma_bf16(c[mi][2 * nj + 1], a[mi], b[nj][1], b[nj][3]);
        }
}
__device__ __forceinline__ void mmas_f16(float c[4][4][4], uint32_t a[4][4], uint32_t b[2][4]) {
#pragma unroll
    for (int mi = 0; mi < 4; mi++)
#pragma unroll
        for (int nj = 0; nj < 2; nj++) {
            mma_f16(c[mi][2 * nj],     a[mi], b[nj][0], b[nj][2]);
            mma_f16(c[mi][2 * nj + 1], a[mi], b[nj][1], b[nj][3]);
        }
}
__device__ __forceinline__ void mmas_f16t(float c[4][4][4], uint32_t a[4][4], uint32_t b[2][4]) {
#pragma unroll
    for (int mi = 0; mi < 4; mi++)
#pragma unroll
        for (int nj = 0; nj < 2; nj++) {
            mma_f16(c[mi][2 * nj],     a[mi], b[nj][0], b[nj][1]);
            mma_f16(c[mi][2 * nj + 1], a[mi], b[nj][2], b[nj][3]);
        }
}

// Pipeline bottom: complete the next stage and publish it to all warps.
// At bottom of iter `it`, pending groups = {it+1} plus {it+2} iff issued.
#define PIPE_BOTTOM(issued_next)                 \
    do {                                         \
        if (issued_next) { CP_WAIT1(); }         \
        else             { CP_WAIT0(); }         \
        __syncthreads();                         \
    } while (0)

// ---------------------------------------------------------------------------
// hi/lo 3-pass GEMM: CTA 256x128, 16 warps (4m x 4n), warp tile 64x32
// ---------------------------------------------------------------------------
#define HL_ALO 20480
#define HL_BHI 40960
#define HL_BLO 51200
#define HL_STG 61440
#define SMEM_HILO (3 * HL_STG)

#define HL_LOAD(saddr, ko)                                        \
    do {                                                          \
        cpa_k<2>((saddr),           Ah + (ko), la, tid);          \
        cpa_k<2>((saddr) + HL_ALO,  Al + (ko), la, tid);          \
        cpa_k<1>((saddr) + HL_BHI,  Bh + (ko), lb, tid);          \
        cpa_k<1>((saddr) + HL_BLO,  Bl + (ko), lb, tid);          \
        CP_COMMIT();                                              \
    } while (0)

// One k16 step: ALL ldsm up front, then uninterrupted 24-mma stream.
__device__ __forceinline__ void kstep_hilo(uint32_t stg, int ks, int lane,
                                           int wm, int wn, float c[4][4][4]) {
    uint32_t ah[4][4], al[4][4], bh[2][4], bl[2][4];
    ldA64(ah, stg, wm, lane, ks);
    ldB32(bh, stg + HL_BHI, wn, lane, ks);
    ldB32(bl, stg + HL_BLO, wn, lane, ks);
    ldA64(al, stg + HL_ALO, wm, lane, ks);
    mmas_bf16(c, ah, bh);
    mmas_bf16(c, ah, bl);
    mmas_bf16(c, al, bh);
}

__device__ __forceinline__ void gemm_hilo(const bf16* Ah, const bf16* Al, int lda,
                                          const bf16* Bh, const bf16* Bl, int ldb,
                                          int nit, uint32_t sb, int tid, float c[4][4][4]) {
    const int lane = tid & 31, wid = tid >> 5;
    const int wm = wid & 3, wn = wid >> 2;
    const int la = lda * 2, lb = ldb * 2;
    HL_LOAD(sb, 0);
    if (nit > 1) { HL_LOAD(sb + HL_STG, 32); CP_WAIT1(); }
    else         { CP_WAIT0(); }
    __syncthreads();
    int si = 0;
    for (int it = 0; it < nit; it++) {
        const bool more = (it + 2 < nit);
        if (more) {
            int s2 = si + 2; if (s2 >= 3) s2 -= 3;
            HL_LOAD(sb + s2 * HL_STG, (it + 2) * 32);
        }
        const uint32_t stg = sb + si * HL_STG;
        kstep_hilo(stg, 0, lane, wm, wn, c);
        kstep_hilo(stg, 1, lane, wm, wn, c);
        if (it + 1 < nit) PIPE_BOTTOM(more);
        if (++si == 3) si = 0;
    }
}

// ---------------------------------------------------------------------------
// fp16 single-pass GEMM (B K-major): CTA 256x128
// ---------------------------------------------------------------------------
#define V_B   20480
#define V_STG 30720
#define SMEM_V (3 * V_STG)

#define V_LOAD(saddr, ko)                                         \
    do {                                                          \
        cpa_k<2>((saddr),        Af + (ko), la, tid);             \
        cpa_k<1>((saddr) + V_B,  Bf + (ko), lb, tid);             \
        CP_COMMIT();                                              \
    } while (0)

__device__ __forceinline__ void gemm_f16nt(const __half* Af, int lda, const __half* Bf, int ldb,
                                           int nit, uint32_t sb, int tid, float c[4][4][4]) {
    const int lane = tid & 31, wid = tid >> 5;
    const int wm = wid & 3, wn = wid >> 2;
    const int la = lda * 2, lb = ldb * 2;
    V_LOAD(sb, 0);
    if (nit > 1) { V_LOAD(sb + V_STG, 32); CP_WAIT1(); }
    else         { CP_WAIT0(); }
    __syncthreads();
    int si = 0;
    for (int it = 0; it < nit; it++) {
        const bool more = (it + 2 < nit);
        if (more) {
            int s2 = si + 2; if (s2 >= 3) s2 -= 3;
            V_LOAD(sb + s2 * V_STG, (it + 2) * 32);
        }
        const uint32_t stg = sb + si * V_STG;
        uint32_t a0[4][4], a1[4][4], b0[2][4], b1[2][4];
        ldA64(a0, stg, wm, lane, 0);
        ldB32(b0, stg + V_B, wn, lane, 0);
        ldA64(a1, stg, wm, lane, 1);
        ldB32(b1, stg + V_B, wn, lane, 1);
        mmas_f16(c, a0, b0);
        mmas_f16(c, a1, b1);
        if (it + 1 < nit) PIPE_BOTTOM(more);
        if (++si == 3) si = 0;
    }
}

// ---------------------------------------------------------------------------
// fp16 single-pass GEMM (B transposed [k][n]): CTA 256x128
// ---------------------------------------------------------------------------
#define AV_B   20480
#define AV_STG 28672
#define SMEM_AV (3 * AV_STG)

#define AV_LOAD(saddr, ko)                                        \
    do {                                                          \
        cpa_k<2>((saddr),         Af + (ko), la, tid);            \
        cpa_t   ((saddr) + AV_B,  Bf + (size_t)(ko) * ldb, lb, tid); \
        CP_COMMIT();                                              \
    } while (0)

__device__ __forceinline__ void gemm_f16t(const __half* Af, int lda, const __half* Bf, int ldb,
                                          int nit, uint32_t sb, int tid, float c[4][4][4]) {
    const int lane = tid & 31, wid = tid >> 5;
    const int wm = wid & 3, wn = wid >> 2;
    const int la = lda * 2, lb = ldb * 2;
    AV_LOAD(sb, 0);
    if (nit > 1) { AV_LOAD(sb + AV_STG, 32); CP_WAIT1(); }
    else         { CP_WAIT0(); }
    __syncthreads();
    int si = 0;
    for (int it = 0; it < nit; it++) {
        const bool more = (it + 2 < nit);
        if (more) {
            int s2 = si + 2; if (s2 >= 3) s2 -= 3;
            AV_LOAD(sb + s2 * AV_STG, (it + 2) * 32);
        }
        const uint32_t stg = sb + si * AV_STG;
        uint32_t a0[4][4], a1[4][4], b0[2][4], b1[2][4];
        ldA64 (a0, stg, wm, lane, 0);
        ldBT32(b0, stg + AV_B, wn, lane, 0);
        ldA64 (a1, stg, wm, lane, 1);
        ldBT32(b1, stg + AV_B, wn, lane, 1);
        mmas_f16t(c, a0, b0);
        mmas_f16t(c, a1, b1);
        if (it + 1 < nit) PIPE_BOTTOM(more);
        if (++si == 3) si = 0;
    }
}

// ---------------------------------------------------------------------------
// Conversions
// ---------------------------------------------------------------------------
__global__ void k_cvtX(const float* __restrict__ x, int n) {
    int i = blockIdx.x * 256 + threadIdx.x;
    const int stride = gridDim.x * 256;
    for (; i < n; i += stride) {
        float v = x[i];
        bf16 h, l; split_bf16(v, h, l);
        g_Xhi[i] = h; g_Xlo[i] = l; g_Xh[i] = __float2half_rn(v);
    }
}
__global__ void k_cvtW(const float* __restrict__ wqk, const float* __restrict__ wov, int n) {
    int i = blockIdx.x * 256 + threadIdx.x;
    const int stride = gridDim.x * 256;
    for (; i < n; i += stride) {
        bf16 h, l; split_bf16(wqk[i], h, l);
        g_Whi[i] = h; g_Wlo[i] = l;
        g_Wh[i] = __float2half_rn(wov[i]);
    }
}

// ---------------------------------------------------------------------------
// GEMM kernels (512 threads, CTA tile 256x128)
// ---------------------------------------------------------------------------
__global__ __launch_bounds__(512, 1) void k_q() {
    extern __shared__ __align__(1024) char smem[];
    const uint32_t sb = smem_u32(smem);
    const int tid = threadIdx.x;
    const int m0 = blockIdx.y * 256, n0 = blockIdx.x * 128;
    float c[4][4][4] = {};
    gemm_hilo(g_Xhi + (size_t)m0 * D_, g_Xlo + (size_t)m0 * D_, D_,
              g_Whi + (size_t)n0 * D_, g_Wlo + (size_t)n0 * D_, D_,
              D_ / 32, sb, tid, c);
    const int lane = tid & 31, wid = tid >> 5;
    const int wm = wid & 3, wn = wid >> 2;
#pragma unroll
    for (int mi = 0; mi < 4; mi++) {
        const int r0 = m0 + wm * 64 + mi * 16 + (lane >> 2);
#pragma unroll
        for (int ni = 0; ni < 4; ni++) {
            const int gc = n0 + wn * 32 + ni * 8 + (lane & 3) * 2;
            const float* cc = c[mi][ni];
#pragma unroll
            for (int h = 0; h < 2; h++) {
                const size_t idx = (size_t)(r0 + 8 * h) * D_ + gc;
                bf16 h0, l0, h1, l1;
                split_bf16(cc[2 * h],     h0, l0);
                split_bf16(cc[2 * h + 1], h1, l1);
                __nv_bfloat162 hh; hh.x = h0; hh.y = h1;
                __nv_bfloat162 ll; ll.x = l0; ll.y = l1;
                *(__nv_bfloat162*)(g_Qhi + idx) = hh;
                *(__nv_bfloat162*)(g_Qlo + idx) = ll;
            }
        }
    }
}

__global__ __launch_bounds__(512, 1) void k_v() {
    extern __shared__ __align__(1024) char smem[];
    const uint32_t sb = smem_u32(smem);
    const int tid = threadIdx.x;
    const int m0 = blockIdx.y * 256, n0 = blockIdx.x * 128;
    float c[4][4][4] = {};
    gemm_f16nt(g_Xh + (size_t)m0 * D_, D_, g_Wh + (size_t)n0 * D_, D_,
               D_ / 32, sb, tid, c);
    const int lane = tid & 31, wid = tid >> 5;
    const int wm = wid & 3, wn = wid >> 2;
#pragma unroll
    for (int mi = 0; mi < 4; mi++) {
        const int r0 = m0 + wm * 64 + mi * 16 + (lane >> 2);
#pragma unroll
        for (int ni = 0; ni < 4; ni++) {
            const int gc = n0 + wn * 32 + ni * 8 + (lane & 3) * 2;
            const float* cc = c[mi][ni];
#pragma unroll
            for (int h = 0; h < 2; h++) {
                const size_t idx = (size_t)(r0 + 8 * h) * D_ + gc;
                *(__half2*)(g_Vh + idx) = __floats2half2_rn(cc[2 * h], cc[2 * h + 1]);
            }
        }
    }
}

__global__ __launch_bounds__(512, 1) void k_scores(float* __restrict__ Aout) {
    if ((int)blockIdx.x > 2 * (int)blockIdx.y + 1) return;   // fully above diagonal
    extern __shared__ __align__(1024) char smem[];
    const uint32_t sb = smem_u32(smem);
    const int tid = threadIdx.x;
    const int b = blockIdx.z;
    const int m0 = blockIdx.y * 256, n0 = blockIdx.x * 128;
    const size_t xb = (size_t)b * S_ * D_;
    float c[4][4][4] = {};
    gemm_hilo(g_Qhi + xb + (size_t)m0 * D_, g_Qlo + xb + (size_t)m0 * D_, D_,
              g_Xhi + xb + (size_t)n0 * D_, g_Xlo + xb + (size_t)n0 * D_, D_,
              D_ / 32, sb, tid, c);
    const int lane = tid & 31, wid = tid >> 5;
    const int wm = wid & 3, wn = wid >> 2;
    float* Ab = Aout + (size_t)b * S_ * S_;
#pragma unroll
    for (int mi = 0; mi < 4; mi++) {
        const int r0 = m0 + wm * 64 + mi * 16 + (lane >> 2);
#pragma unroll
        for (int ni = 0; ni < 4; ni++) {
            const int gc = n0 + wn * 32 + ni * 8 + (lane & 3) * 2;
            const float* cc = c[mi][ni];
#pragma unroll
            for (int h = 0; h < 2; h++) {
                float2 v = make_float2(cc[2 * h] * 32.0f, cc[2 * h + 1] * 32.0f);
                *(float2*)(Ab + (size_t)(r0 + 8 * h) * S_ + gc) = v;
            }
        }
    }
}

// ---------------------------------------------------------------------------
// Softmax (causal, in place) + fp16 A emission
// ---------------------------------------------------------------------------
__global__ void k_softmax(float* __restrict__ A) {
    const int s = blockIdx.x, b = blockIdx.y;
    const size_t rb = ((size_t)b * S_ + s) * S_;
    float* row = A + rb;
    __half* Ah = g_Ah + rb;
    const int len = s + 1;
    const int tid = threadIdx.x;
    __shared__ float red[256];

    float v[8];
    float m = -1e30f;
#pragma unroll
    for (int it = 0; it < 8; it++) {
        int j = tid + it * 256;
        v[it] = (j < len) ? row[j] : -1e30f;
        m = fmaxf(m, v[it]);
    }
    red[tid] = m; __syncthreads();
    for (int o = 128; o > 0; o >>= 1) {
        if (tid < o) red[tid] = fmaxf(red[tid], red[tid + o]);
        __syncthreads();
    }
    m = red[0]; __syncthreads();

    float sum = 0.0f;
#pragma unroll
    for (int it = 0; it < 8; it++) {
        int j = tid + it * 256;
        v[it] = (j < len) ? __expf(v[it] - m) : 0.0f;
        sum += v[it];
    }
    red[tid] = sum; __syncthreads();
    for (int o = 128; o > 0; o >>= 1) {
        if (tid < o) red[tid] += red[tid + o];
        __syncthreads();
    }
    const float inv = 1.0f / red[0];

#pragma unroll
    for (int it = 0; it < 8; it++) {
        int j = tid + it * 256;
        float a = v[it] * inv;
        row[j] = a;
        Ah[j]  = __float2half_rn(a);
    }
}

// ---------------------------------------------------------------------------
// GEMM3: Y = A@V (fp16, causal K-truncation), out = X + Y
// ---------------------------------------------------------------------------
__global__ __launch_bounds__(512, 1) void k_av(const float* __restrict__ X,
                                               float* __restrict__ Yout) {
    extern __shared__ __align__(1024) char smem[];
    const uint32_t sb = smem_u32(smem);
    const int tid = threadIdx.x;
    const int b = blockIdx.z;
    const int m0 = blockIdx.y * 256, n0 = blockIdx.x * 128;
    float c[4][4][4] = {};
    gemm_f16t(g_Ah + (size_t)b * S_ * S_ + (size_t)m0 * S_, S_,
              g_Vh + (size_t)b * S_ * D_ + n0, D_,
              (blockIdx.y + 1) * 8, sb, tid, c);
    const int lane = tid & 31, wid = tid >> 5;
    const int wm = wid & 3, wn = wid >> 2;
#pragma unroll
    for (int mi = 0; mi < 4; mi++) {
        const int r0 = m0 + wm * 64 + mi * 16 + (lane >> 2);
#pragma unroll
        for (int ni = 0; ni < 4; ni++) {
            const int gc = n0 + wn * 32 + ni * 8 + (lane & 3) * 2;
            const float* cc = c[mi][ni];
#pragma unroll
            for (int h = 0; h < 2; h++) {
                const size_t idx = ((size_t)b * S_ + (r0 + 8 * h)) * D_ + gc;
                float2 x2 = *(const float2*)(X + idx);
                float2 o = make_float2(cc[2 * h] + x2.x, cc[2 * h + 1] + x2.y);
                *(float2*)(Yout + idx) = o;
            }
        }
    }
}

// ---------------------------------------------------------------------------
extern "C" void kernel_launch(void* const* d_in, const int* in_sizes, int n_in,
                              void* d_out, int out_size) {
    const float* X   = (const float*)d_in[0];
    const float* WQK = (const float*)d_in[2];
    const float* WOV = (const float*)d_in[3];
    float* out = (float*)d_out;

    const size_t nY = (size_t)M1 * D_;
    const size_t nA = (size_t)B_ * S_ * S_;
    float* Aout;
    if ((size_t)out_size >= nY + nA) {
        Aout = out + nY;
    } else {
        void* p = nullptr;
        cudaGetSymbolAddress(&p, g_Afallback);
        Aout = (float*)p;
    }

    static bool attrs_set = false;
    if (!attrs_set) {
        cudaFuncSetAttribute(k_q,      cudaFuncAttributeMaxDynamicSharedMemorySize, SMEM_HILO);
        cudaFuncSetAttribute(k_scores, cudaFuncAttributeMaxDynamicSharedMemorySize, SMEM_HILO);
        cudaFuncSetAttribute(k_v,      cudaFuncAttributeMaxDynamicSharedMemorySize, SMEM_V);
        cudaFuncSetAttribute(k_av,     cudaFuncAttributeMaxDynamicSharedMemorySize, SMEM_AV);
        attrs_set = true;
    }

    // 1) conversions
    k_cvtX<<<512, 256>>>(X, M1 * D_);
    k_cvtW<<<256, 256>>>(WQK, WOV, D_ * D_);
    // 2) Q (hi/lo bf16, 3-pass) and V (fp16, 1-pass)
    k_q<<<dim3(D_ / 128, M1 / 256), 512, SMEM_HILO>>>();
    k_v<<<dim3(D_ / 128, M1 / 256), 512, SMEM_V>>>();
    // 3) causal scaled scores -> A region (fp32)
    k_scores<<<dim3(S_ / 128, S_ / 256, B_), 512, SMEM_HILO>>>(Aout);
    // 4) softmax in place + A fp16
    k_softmax<<<dim3(S_, B_), 256>>>(Aout);
    // 5) Y = A@V + X
    k_av<<<dim3(D_ / 128, S_ / 256, B_), 512, SMEM_AV>>>(X, out);
}

// round 8
// speedup vs baseline: 3.4702x; 1.0341x over previous
#include <cuda_runtime.h>
#include <cuda_bf16.h>
#include <cuda_fp16.h>
#include <cstdint>

#define B_  4
#define S_  2048
#define D_  1024
#define M1  (B_ * S_)

typedef __nv_bfloat16 bf16;

// ---------------------------------------------------------------------------
// Scratch (__device__ globals; no allocation allowed)
// ---------------------------------------------------------------------------
__device__ __align__(256) bf16   g_Xhi[(size_t)M1 * D_];
__device__ __align__(256) bf16   g_Xlo[(size_t)M1 * D_];
__device__ __align__(256) __half g_Xh [(size_t)M1 * D_];
__device__ __align__(256) bf16   g_Whi[(size_t)D_ * D_];
__device__ __align__(256) bf16   g_Wlo[(size_t)D_ * D_];
__device__ __align__(256) __half g_Wh [(size_t)D_ * D_];
__device__ __align__(256) bf16   g_Qhi[(size_t)M1 * D_];
__device__ __align__(256) bf16   g_Qlo[(size_t)M1 * D_];
__device__ __align__(256) __half g_Vh [(size_t)M1 * D_];        // V [m][d]
__device__ __align__(256) __half g_Ah [(size_t)B_ * S_ * S_];   // A fp16 [s][t]
__device__ float g_Afallback[(size_t)B_ * S_ * S_];

// ---------------------------------------------------------------------------
// Baseline-PTX primitives
// ---------------------------------------------------------------------------
__device__ __forceinline__ uint32_t smem_u32(const void* p) {
    uint32_t a;
    asm("{ .reg .u64 t; cvta.to.shared.u64 t, %1; cvt.u32.u64 %0, t; }" : "=r"(a) : "l"(p));
    return a;
}
#define CPA(dst, src)  asm volatile("cp.async.cg.shared.global [%0], [%1], 16;\n" :: "r"(dst), "l"(src))
#define CP_COMMIT()    asm volatile("cp.async.commit_group;\n" ::: "memory")
#define CP_WAIT1()     asm volatile("cp.async.wait_group 1;\n" ::: "memory")
#define CP_WAIT0()     asm volatile("cp.async.wait_group 0;\n" ::: "memory")

__device__ __forceinline__ void ldsm4(uint32_t r[4], uint32_t a) {
    asm volatile("ldmatrix.sync.aligned.m8n8.x4.shared.b16 {%0,%1,%2,%3}, [%4];\n"
                 : "=r"(r[0]), "=r"(r[1]), "=r"(r[2]), "=r"(r[3]) : "r"(a));
}
__device__ __forceinline__ void ldsm4t(uint32_t r[4], uint32_t a) {
    asm volatile("ldmatrix.sync.aligned.m8n8.x4.trans.shared.b16 {%0,%1,%2,%3}, [%4];\n"
                 : "=r"(r[0]), "=r"(r[1]), "=r"(r[2]), "=r"(r[3]) : "r"(a));
}
__device__ __forceinline__ void mma_bf16(float* c, const uint32_t a[4], uint32_t b0, uint32_t b1) {
    asm volatile("mma.sync.aligned.m16n8k16.row.col.f32.bf16.bf16.f32 "
                 "{%0,%1,%2,%3}, {%4,%5,%6,%7}, {%8,%9}, {%0,%1,%2,%3};\n"
                 : "+f"(c[0]), "+f"(c[1]), "+f"(c[2]), "+f"(c[3])
                 : "r"(a[0]), "r"(a[1]), "r"(a[2]), "r"(a[3]), "r"(b0), "r"(b1));
}
__device__ __forceinline__ void mma_f16(float* c, const uint32_t a[4], uint32_t b0, uint32_t b1) {
    asm volatile("mma.sync.aligned.m16n8k16.row.col.f32.f16.f16.f32 "
                 "{%0,%1,%2,%3}, {%4,%5,%6,%7}, {%8,%9}, {%0,%1,%2,%3};\n"
                 : "+f"(c[0]), "+f"(c[1]), "+f"(c[2]), "+f"(c[3])
                 : "r"(a[0]), "r"(a[1]), "r"(a[2]), "r"(a[3]), "r"(b0), "r"(b1));
}
__device__ __forceinline__ void split_bf16(float v, bf16& h, bf16& l) {
    h = __float2bfloat16_rn(v);
    l = __float2bfloat16_rn(v - __bfloat162float(h));
}

// ---------------------------------------------------------------------------
// Tile loaders: 128 threads. K-major [rows][32 elems], smem rows stride 80B.
// ---------------------------------------------------------------------------
template<int ITERS>   // ITERS = rows/32
__device__ __forceinline__ void cpa_k(uint32_t sdst, const void* g, int ldbytes, int tid) {
#pragma unroll
    for (int i = 0; i < ITERS; i++) {
        int u = tid + i * 128;
        int r = u >> 2, c = u & 3;
        CPA(sdst + r * 80 + c * 16, (const char*)g + (size_t)r * ldbytes + c * 16);
    }
}
// Transposed tile [32 k][128 n], 256B rows, XOR swizzle (128 threads, 4 iters)
__device__ __forceinline__ void cpa_t(uint32_t sdst, const void* g, int ldbytes, int tid) {
#pragma unroll
    for (int i = 0; i < 4; i++) {
        int u = tid + i * 128;
        int k = u >> 4, c = u & 15;
        CPA(sdst + k * 256 + ((c ^ ((k & 7) << 1)) << 4),
            (const char*)g + (size_t)k * ldbytes + c * 16);
    }
}

__device__ __forceinline__ void ld4frag(uint32_t base, uint32_t r[4][4]) {
#pragma unroll
    for (int i = 0; i < 4; i++) ldsm4(r[i], base + i * 1280);
}
// 64-row fragment (A or B), K-major smem
__device__ __forceinline__ void ldF64(uint32_t r[4][4], uint32_t base, int w, int lane, int ks) {
    const int row = lane & 15;
    const int ch  = (lane >> 4) + ks * 2;
    ld4frag(base + (w * 64 + row) * 80 + ch * 16, r);
}
// B fragment from transposed [k][n] smem (ldsm trans), 64 cols
__device__ __forceinline__ void ldBT64(uint32_t r[4][4], uint32_t bbase, int wn, int lane, int ks) {
    const int k = ks * 16 + (lane & 15);
#pragma unroll
    for (int nj = 0; nj < 4; nj++) {
        const int cl = wn * 8 + nj * 2 + (lane >> 4);
        ldsm4t(r[nj], bbase + k * 256 + ((cl ^ ((k & 7) << 1)) << 4));
    }
}

__device__ __forceinline__ void mmas_bf16(float c[4][8][4], uint32_t a[4][4], uint32_t b[4][4]) {
#pragma unroll
    for (int mi = 0; mi < 4; mi++)
#pragma unroll
        for (int nj = 0; nj < 4; nj++) {
            mma_bf16(c[mi][2 * nj],     a[mi], b[nj][0], b[nj][2]);
            mma_bf16(c[mi][2 * nj + 1], a[mi], b[nj][1], b[nj][3]);
        }
}
__device__ __forceinline__ void mmas_f16(float c[4][8][4], uint32_t a[4][4], uint32_t b[4][4]) {
#pragma unroll
    for (int mi = 0; mi < 4; mi++)
#pragma unroll
        for (int nj = 0; nj < 4; nj++) {
            mma_f16(c[mi][2 * nj],     a[mi], b[nj][0], b[nj][2]);
            mma_f16(c[mi][2 * nj + 1], a[mi], b[nj][1], b[nj][3]);
        }
}
__device__ __forceinline__ void mmas_f16t(float c[4][8][4], uint32_t a[4][4], uint32_t b[4][4]) {
#pragma unroll
    for (int mi = 0; mi < 4; mi++)
#pragma unroll
        for (int nj = 0; nj < 4; nj++) {
            mma_f16(c[mi][2 * nj],     a[mi], b[nj][0], b[nj][1]);
            mma_f16(c[mi][2 * nj + 1], a[mi], b[nj][2], b[nj][3]);
        }
}

// 2-stage pipeline bottom (iter it): publish stage(it+1), refill freed buffer.
#define PIPE2_BOTTOM(LOADM, it, nit)                              \
    do {                                                          \
        if ((it) + 1 < (nit)) {                                   \
            __syncthreads();      /* stage(it) reads done */      \
            const bool more = ((it) + 2 < (nit));                 \
            if (more) { LOADM(sb + ((it) & 1) * STG_, ((it) + 2) * 32); } \
            if (more) { CP_WAIT1(); } else { CP_WAIT0(); }        \
            __syncthreads();      /* stage(it+1) published */     \
        }                                                         \
    } while (0)

// ---------------------------------------------------------------------------
// hi/lo 3-pass GEMM: CTA 128x128, 4 warps (2m x 2n), warp tile 64x64
// stage: Ahi 0, Alo 10240, Bhi 20480, Blo 30720; stride 40960
// ---------------------------------------------------------------------------
#define HL_ALO 10240
#define HL_BHI 20480
#define HL_BLO 30720
#define HL_STG 40960
#define SMEM_HILO (2 * HL_STG)

#define HL_LOAD(saddr, ko)                                        \
    do {                                                          \
        cpa_k<4>((saddr),           Ah + (ko), la, tid);          \
        cpa_k<4>((saddr) + HL_ALO,  Al + (ko), la, tid);          \
        cpa_k<4>((saddr) + HL_BHI,  Bh + (ko), lb, tid);          \
        cpa_k<4>((saddr) + HL_BLO,  Bl + (ko), lb, tid);          \
        CP_COMMIT();                                              \
    } while (0)

// k16 step: ah/bh hoisted, t reused for bl/al (keeps regs ~R3 level)
__device__ __forceinline__ void kstep_hilo(uint32_t stg, int ks, int lane,
                                           int wm, int wn, float c[4][8][4]) {
    uint32_t ah[4][4], bh[4][4], t[4][4];
    ldF64(ah, stg, wm, lane, ks);
    ldF64(bh, stg + HL_BHI, wn, lane, ks);
    mmas_bf16(c, ah, bh);
    ldF64(t, stg + HL_BLO, wn, lane, ks);
    mmas_bf16(c, ah, t);
    ldF64(t, stg + HL_ALO, wm, lane, ks);
    mmas_bf16(c, t, bh);
}

__device__ __forceinline__ void gemm_hilo(const bf16* Ah, const bf16* Al, int lda,
                                          const bf16* Bh, const bf16* Bl, int ldb,
                                          int nit, uint32_t sb, int tid, float c[4][8][4]) {
    const int lane = tid & 31, wid = tid >> 5;
    const int wm = wid >> 1, wn = wid & 1;
    const int la = lda * 2, lb = ldb * 2;
    HL_LOAD(sb, 0);
    if (nit > 1) { HL_LOAD(sb + HL_STG, 32); CP_WAIT1(); }
    else         { CP_WAIT0(); }
    __syncthreads();
#define STG_ HL_STG
    for (int it = 0; it < nit; it++) {
        const uint32_t stg = sb + (it & 1) * HL_STG;
        kstep_hilo(stg, 0, lane, wm, wn, c);
        kstep_hilo(stg, 1, lane, wm, wn, c);
        PIPE2_BOTTOM(HL_LOAD, it, nit);
    }
#undef STG_
}

// ---------------------------------------------------------------------------
// fp16 single-pass GEMM (B K-major): CTA 128x128
// ---------------------------------------------------------------------------
#define V_B   10240
#define V_STG 20480
#define SMEM_V (2 * V_STG)

#define V_LOAD(saddr, ko)                                         \
    do {                                                          \
        cpa_k<4>((saddr),        Af + (ko), la, tid);             \
        cpa_k<4>((saddr) + V_B,  Bf + (ko), lb, tid);             \
        CP_COMMIT();                                              \
    } while (0)

__device__ __forceinline__ void gemm_f16nt(const __half* Af, int lda, const __half* Bf, int ldb,
                                           int nit, uint32_t sb, int tid, float c[4][8][4]) {
    const int lane = tid & 31, wid = tid >> 5;
    const int wm = wid >> 1, wn = wid & 1;
    const int la = lda * 2, lb = ldb * 2;
    V_LOAD(sb, 0);
    if (nit > 1) { V_LOAD(sb + V_STG, 32); CP_WAIT1(); }
    else         { CP_WAIT0(); }
    __syncthreads();
#define STG_ V_STG
    for (int it = 0; it < nit; it++) {
        const uint32_t stg = sb + (it & 1) * V_STG;
#pragma unroll
        for (int ks = 0; ks < 2; ks++) {
            uint32_t ah[4][4], bh[4][4];
            ldF64(ah, stg, wm, lane, ks);
            ldF64(bh, stg + V_B, wn, lane, ks);
            mmas_f16(c, ah, bh);
        }
        PIPE2_BOTTOM(V_LOAD, it, nit);
    }
#undef STG_
}

// ---------------------------------------------------------------------------
// fp16 single-pass GEMM (B transposed [k][n]): CTA 128x128
// ---------------------------------------------------------------------------
#define AV_B   10240
#define AV_STG 18432
#define SMEM_AV (2 * AV_STG)

#define AV_LOAD(saddr, ko)                                        \
    do {                                                          \
        cpa_k<4>((saddr),         Af + (ko), la, tid);            \
        cpa_t   ((saddr) + AV_B,  Bf + (size_t)(ko) * ldb, lb, tid); \
        CP_COMMIT();                                              \
    } while (0)

__device__ __forceinline__ void gemm_f16t(const __half* Af, int lda, const __half* Bf, int ldb,
                                          int nit, uint32_t sb, int tid, float c[4][8][4]) {
    const int lane = tid & 31, wid = tid >> 5;
    const int wm = wid >> 1, wn = wid & 1;
    const int la = lda * 2, lb = ldb * 2;
    AV_LOAD(sb, 0);
    if (nit > 1) { AV_LOAD(sb + AV_STG, 32); CP_WAIT1(); }
    else         { CP_WAIT0(); }
    __syncthreads();
#define STG_ AV_STG
    for (int it = 0; it < nit; it++) {
        const uint32_t stg = sb + (it & 1) * AV_STG;
#pragma unroll
        for (int ks = 0; ks < 2; ks++) {
            uint32_t ah[4][4], bt[4][4];
            ldF64 (ah, stg, wm, lane, ks);
            ldBT64(bt, stg + AV_B, wn, lane, ks);
            mmas_f16t(c, ah, bt);
        }
        PIPE2_BOTTOM(AV_LOAD, it, nit);
    }
#undef STG_
}

// ---------------------------------------------------------------------------
// Conversions
// ---------------------------------------------------------------------------
__global__ void k_cvtX(const float* __restrict__ x, int n) {
    int i = blockIdx.x * 256 + threadIdx.x;
    const int stride = gridDim.x * 256;
    for (; i < n; i += stride) {
        float v = x[i];
        bf16 h, l; split_bf16(v, h, l);
        g_Xhi[i] = h; g_Xlo[i] = l; g_Xh[i] = __float2half_rn(v);
    }
}
__global__ void k_cvtW(const float* __restrict__ wqk, const float* __restrict__ wov, int n) {
    int i = blockIdx.x * 256 + threadIdx.x;
    const int stride = gridDim.x * 256;
    for (; i < n; i += stride) {
        bf16 h, l; split_bf16(wqk[i], h, l);
        g_Whi[i] = h; g_Wlo[i] = l;
        g_Wh[i] = __float2half_rn(wov[i]);
    }
}

// ---------------------------------------------------------------------------
// GEMM kernels (128 threads, CTA 128x128, 2 CTAs/SM)
// ---------------------------------------------------------------------------
__global__ __launch_bounds__(128, 2) void k_q() {
    extern __shared__ __align__(1024) char smem[];
    const uint32_t sb = smem_u32(smem);
    const int tid = threadIdx.x;
    const int m0 = blockIdx.y * 128, n0 = blockIdx.x * 128;
    float c[4][8][4] = {};
    gemm_hilo(g_Xhi + (size_t)m0 * D_, g_Xlo + (size_t)m0 * D_, D_,
              g_Whi + (size_t)n0 * D_, g_Wlo + (size_t)n0 * D_, D_,
              D_ / 32, sb, tid, c);
    const int lane = tid & 31, wid = tid >> 5;
    const int wm = wid >> 1, wn = wid & 1;
#pragma unroll
    for (int mi = 0; mi < 4; mi++) {
        const int r0 = m0 + wm * 64 + mi * 16 + (lane >> 2);
#pragma unroll
        for (int ni = 0; ni < 8; ni++) {
            const int gc = n0 + wn * 64 + ni * 8 + (lane & 3) * 2;
            const float* cc = c[mi][ni];
#pragma unroll
            for (int h = 0; h < 2; h++) {
                const size_t idx = (size_t)(r0 + 8 * h) * D_ + gc;
                bf16 h0, l0, h1, l1;
                split_bf16(cc[2 * h],     h0, l0);
                split_bf16(cc[2 * h + 1], h1, l1);
                __nv_bfloat162 hh; hh.x = h0; hh.y = h1;
                __nv_bfloat162 ll; ll.x = l0; ll.y = l1;
                *(__nv_bfloat162*)(g_Qhi + idx) = hh;
                *(__nv_bfloat162*)(g_Qlo + idx) = ll;
            }
        }
    }
}

__global__ __launch_bounds__(128, 2) void k_v() {
    extern __shared__ __align__(1024) char smem[];
    const uint32_t sb = smem_u32(smem);
    const int tid = threadIdx.x;
    const int m0 = blockIdx.y * 128, n0 = blockIdx.x * 128;
    float c[4][8][4] = {};
    gemm_f16nt(g_Xh + (size_t)m0 * D_, D_, g_Wh + (size_t)n0 * D_, D_,
               D_ / 32, sb, tid, c);
    const int lane = tid & 31, wid = tid >> 5;
    const int wm = wid >> 1, wn = wid & 1;
#pragma unroll
    for (int mi = 0; mi < 4; mi++) {
        const int r0 = m0 + wm * 64 + mi * 16 + (lane >> 2);
#pragma unroll
        for (int ni = 0; ni < 8; ni++) {
            const int gc = n0 + wn * 64 + ni * 8 + (lane & 3) * 2;
            const float* cc = c[mi][ni];
#pragma unroll
            for (int h = 0; h < 2; h++) {
                const size_t idx = (size_t)(r0 + 8 * h) * D_ + gc;
                *(__half2*)(g_Vh + idx) = __floats2half2_rn(cc[2 * h], cc[2 * h + 1]);
            }
        }
    }
}

__global__ __launch_bounds__(128, 2) void k_scores(float* __restrict__ Aout) {
    if (blockIdx.x > blockIdx.y) return;   // strictly above diagonal
    extern __shared__ __align__(1024) char smem[];
    const uint32_t sb = smem_u32(smem);
    const int tid = threadIdx.x;
    const int b = blockIdx.z;
    const int m0 = blockIdx.y * 128, n0 = blockIdx.x * 128;
    const size_t xb = (size_t)b * S_ * D_;
    float c[4][8][4] = {};
    gemm_hilo(g_Qhi + xb + (size_t)m0 * D_, g_Qlo + xb + (size_t)m0 * D_, D_,
              g_Xhi + xb + (size_t)n0 * D_, g_Xlo + xb + (size_t)n0 * D_, D_,
              D_ / 32, sb, tid, c);
    const int lane = tid & 31, wid = tid >> 5;
    const int wm = wid >> 1, wn = wid & 1;
    float* Ab = Aout + (size_t)b * S_ * S_;
#pragma unroll
    for (int mi = 0; mi < 4; mi++) {
        const int r0 = m0 + wm * 64 + mi * 16 + (lane >> 2);
#pragma unroll
        for (int ni = 0; ni < 8; ni++) {
            const int gc = n0 + wn * 64 + ni * 8 + (lane & 3) * 2;
            const float* cc = c[mi][ni];
#pragma unroll
            for (int h = 0; h < 2; h++) {
                float2 v = make_float2(cc[2 * h] * 32.0f, cc[2 * h + 1] * 32.0f);
                *(float2*)(Ab + (size_t)(r0 + 8 * h) * S_ + gc) = v;
            }
        }
    }
}

// ---------------------------------------------------------------------------
// Softmax (causal, in place) + fp16 A emission
// ---------------------------------------------------------------------------
__global__ void k_softmax(float* __restrict__ A) {
    const int s = blockIdx.x, b = blockIdx.y;
    const size_t rb = ((size_t)b * S_ + s) * S_;
    float* row = A + rb;
    __half* Ah = g_Ah + rb;
    const int len = s + 1;
    const int tid = threadIdx.x;
    __shared__ float red[256];

    float v[8];
    float m = -1e30f;
#pragma unroll
    for (int it = 0; it < 8; it++) {
        int j = tid + it * 256;
        v[it] = (j < len) ? row[j] : -1e30f;
        m = fmaxf(m, v[it]);
    }
    red[tid] = m; __syncthreads();
    for (int o = 128; o > 0; o >>= 1) {
        if (tid < o) red[tid] = fmaxf(red[tid], red[tid + o]);
        __syncthreads();
    }
    m = red[0]; __syncthreads();

    float sum = 0.0f;
#pragma unroll
    for (int it = 0; it < 8; it++) {
        int j = tid + it * 256;
        v[it] = (j < len) ? __expf(v[it] - m) : 0.0f;
        sum += v[it];
    }
    red[tid] = sum; __syncthreads();
    for (int o = 128; o > 0; o >>= 1) {
        if (tid < o) red[tid] += red[tid + o];
        __syncthreads();
    }
    const float inv = 1.0f / red[0];

#pragma unroll
    for (int it = 0; it < 8; it++) {
        int j = tid + it * 256;
        float a = v[it] * inv;
        row[j] = a;
        Ah[j]  = __float2half_rn(a);
    }
}

// ---------------------------------------------------------------------------
// GEMM3: Y = A@V (fp16, causal K-truncation), out = X + Y
// ---------------------------------------------------------------------------
__global__ __launch_bounds__(128, 2) void k_av(const float* __restrict__ X,
                                               float* __restrict__ Yout) {
    extern __shared__ __align__(1024) char smem[];
    const uint32_t sb = smem_u32(smem);
    const int tid = threadIdx.x;
    const int b = blockIdx.z;
    const int m0 = blockIdx.y * 128, n0 = blockIdx.x * 128;
    float c[4][8][4] = {};
    gemm_f16t(g_Ah + (size_t)b * S_ * S_ + (size_t)m0 * S_, S_,
              g_Vh + (size_t)b * S_ * D_ + n0, D_,
              (blockIdx.y + 1) * 4, sb, tid, c);
    const int lane = tid & 31, wid = tid >> 5;
    const int wm = wid >> 1, wn = wid & 1;
#pragma unroll
    for (int mi = 0; mi < 4; mi++) {
        const int r0 = m0 + wm * 64 + mi * 16 + (lane >> 2);
#pragma unroll
        for (int ni = 0; ni < 8; ni++) {
            const int gc = n0 + wn * 64 + ni * 8 + (lane & 3) * 2;
            const float* cc = c[mi][ni];
#pragma unroll
            for (int h = 0; h < 2; h++) {
                const size_t idx = ((size_t)b * S_ + (r0 + 8 * h)) * D_ + gc;
                float2 x2 = *(const float2*)(X + idx);
                float2 o = make_float2(cc[2 * h] + x2.x, cc[2 * h + 1] + x2.y);
                *(float2*)(Yout + idx) = o;
            }
        }
    }
}

// ---------------------------------------------------------------------------
extern "C" void kernel_launch(void* const* d_in, const int* in_sizes, int n_in,
                              void* d_out, int out_size) {
    const float* X   = (const float*)d_in[0];
    const float* WQK = (const float*)d_in[2];
    const float* WOV = (const float*)d_in[3];
    float* out = (float*)d_out;

    const size_t nY = (size_t)M1 * D_;
    const size_t nA = (size_t)B_ * S_ * S_;
    float* Aout;
    if ((size_t)out_size >= nY + nA) {
        Aout = out + nY;
    } else {
        void* p = nullptr;
        cudaGetSymbolAddress(&p, g_Afallback);
        Aout = (float*)p;
    }

    static bool attrs_set = false;
    if (!attrs_set) {
        cudaFuncSetAttribute(k_q,      cudaFuncAttributeMaxDynamicSharedMemorySize, SMEM_HILO);
        cudaFuncSetAttribute(k_scores, cudaFuncAttributeMaxDynamicSharedMemorySize, SMEM_HILO);
        cudaFuncSetAttribute(k_v,      cudaFuncAttributeMaxDynamicSharedMemorySize, SMEM_V);
        cudaFuncSetAttribute(k_av,     cudaFuncAttributeMaxDynamicSharedMemorySize, SMEM_AV);
        attrs_set = true;
    }

    // 1) conversions
    k_cvtX<<<512, 256>>>(X, M1 * D_);
    k_cvtW<<<256, 256>>>(WQK, WOV, D_ * D_);
    // 2) Q (hi/lo bf16, 3-pass) and V (fp16, 1-pass)
    k_q<<<dim3(D_ / 128, M1 / 128), 128, SMEM_HILO>>>();
    k_v<<<dim3(D_ / 128, M1 / 128), 128, SMEM_V>>>();
    // 3) causal scaled scores -> A region (fp32)
    k_scores<<<dim3(S_ / 128, S_ / 128, B_), 128, SMEM_HILO>>>(Aout);
    // 4) softmax in place + A fp16
    k_softmax<<<dim3(S_, B_), 256>>>(Aout);
    // 5) Y = A@V + X
    k_av<<<dim3(D_ / 128, S_ / 128, B_), 128, SMEM_AV>>>(X, out);
}

// round 9
// speedup vs baseline: 3.5848x; 1.0330x over previous
#include <cuda_runtime.h>
#include <cuda_bf16.h>
#include <cuda_fp16.h>
#include <cstdint>

#define B_  4
#define S_  2048
#define D_  1024
#define M1  (B_ * S_)

typedef __nv_bfloat16 bf16;

// ---------------------------------------------------------------------------
// Scratch (__device__ globals; no allocation allowed)
// ---------------------------------------------------------------------------
__device__ __align__(256) bf16   g_Xhi[(size_t)M1 * D_];
__device__ __align__(256) bf16   g_Xlo[(size_t)M1 * D_];
__device__ __align__(256) __half g_Xh [(size_t)M1 * D_];
__device__ __align__(256) bf16   g_Whi[(size_t)D_ * D_];
__device__ __align__(256) bf16   g_Wlo[(size_t)D_ * D_];
__device__ __align__(256) __half g_Wh [(size_t)D_ * D_];
__device__ __align__(256) bf16   g_Qhi[(size_t)M1 * D_];
__device__ __align__(256) bf16   g_Qlo[(size_t)M1 * D_];
__device__ __align__(256) __half g_Vh [(size_t)M1 * D_];        // V [m][d]
__device__ __align__(256) __half g_Ah [(size_t)B_ * S_ * S_];   // A fp16 [s][t]
__device__ float g_Afallback[(size_t)B_ * S_ * S_];

// ---------------------------------------------------------------------------
// Baseline-PTX primitives
// ---------------------------------------------------------------------------
__device__ __forceinline__ uint32_t smem_u32(const void* p) {
    uint32_t a;
    asm("{ .reg .u64 t; cvta.to.shared.u64 t, %1; cvt.u32.u64 %0, t; }" : "=r"(a) : "l"(p));
    return a;
}
#define CPA(dst, src)  asm volatile("cp.async.cg.shared.global [%0], [%1], 16;\n" :: "r"(dst), "l"(src))
#define CP_COMMIT()    asm volatile("cp.async.commit_group;\n" ::: "memory")
#define CP_WAIT1()     asm volatile("cp.async.wait_group 1;\n" ::: "memory")
#define CP_WAIT0()     asm volatile("cp.async.wait_group 0;\n" ::: "memory")

__device__ __forceinline__ void ldsm4(uint32_t r[4], uint32_t a) {
    asm volatile("ldmatrix.sync.aligned.m8n8.x4.shared.b16 {%0,%1,%2,%3}, [%4];\n"
                 : "=r"(r[0]), "=r"(r[1]), "=r"(r[2]), "=r"(r[3]) : "r"(a));
}
__device__ __forceinline__ void ldsm4t(uint32_t r[4], uint32_t a) {
    asm volatile("ldmatrix.sync.aligned.m8n8.x4.trans.shared.b16 {%0,%1,%2,%3}, [%4];\n"
                 : "=r"(r[0]), "=r"(r[1]), "=r"(r[2]), "=r"(r[3]) : "r"(a));
}
__device__ __forceinline__ void mma_bf16(float* c, const uint32_t a[4], uint32_t b0, uint32_t b1) {
    asm volatile("mma.sync.aligned.m16n8k16.row.col.f32.bf16.bf16.f32 "
                 "{%0,%1,%2,%3}, {%4,%5,%6,%7}, {%8,%9}, {%0,%1,%2,%3};\n"
                 : "+f"(c[0]), "+f"(c[1]), "+f"(c[2]), "+f"(c[3])
                 : "r"(a[0]), "r"(a[1]), "r"(a[2]), "r"(a[3]), "r"(b0), "r"(b1));
}
__device__ __forceinline__ void mma_f16(float* c, const uint32_t a[4], uint32_t b0, uint32_t b1) {
    asm volatile("mma.sync.aligned.m16n8k16.row.col.f32.f16.f16.f32 "
                 "{%0,%1,%2,%3}, {%4,%5,%6,%7}, {%8,%9}, {%0,%1,%2,%3};\n"
                 : "+f"(c[0]), "+f"(c[1]), "+f"(c[2]), "+f"(c[3])
                 : "r"(a[0]), "r"(a[1]), "r"(a[2]), "r"(a[3]), "r"(b0), "r"(b1));
}
__device__ __forceinline__ void split_bf16(float v, bf16& h, bf16& l) {
    h = __float2bfloat16_rn(v);
    l = __float2bfloat16_rn(v - __bfloat162float(h));
}

// ---------------------------------------------------------------------------
// Tile loaders: 128 threads. K-major [128 rows][32 elems], smem rows 80B.
// ---------------------------------------------------------------------------
__device__ __forceinline__ void cpa_k(uint32_t sdst, const void* g, int ldbytes, int tid) {
#pragma unroll
    for (int i = 0; i < 4; i++) {
        int u = tid + i * 128;
        int r = u >> 2, c = u & 3;
        CPA(sdst + r * 80 + c * 16, (const char*)g + (size_t)r * ldbytes + c * 16);
    }
}
// Transposed tile [32 k][128 n], 256B rows, XOR swizzle (128 threads, 4 iters)
__device__ __forceinline__ void cpa_t(uint32_t sdst, const void* g, int ldbytes, int tid) {
#pragma unroll
    for (int i = 0; i < 4; i++) {
        int u = tid + i * 128;
        int k = u >> 4, c = u & 15;
        CPA(sdst + k * 256 + ((c ^ ((k & 7) << 1)) << 4),
            (const char*)g + (size_t)k * ldbytes + c * 16);
    }
}

__device__ __forceinline__ void ld4frag(uint32_t base, uint32_t r[4][4]) {
#pragma unroll
    for (int i = 0; i < 4; i++) ldsm4(r[i], base + i * 1280);
}
// 64-row fragment, K-major smem sub-tile
__device__ __forceinline__ void ldF64(uint32_t r[4][4], uint32_t base, int w, int lane, int ks) {
    const int row = lane & 15;
    const int ch  = (lane >> 4) + ks * 2;
    ld4frag(base + (w * 64 + row) * 80 + ch * 16, r);
}
// B fragment from transposed [k][n] smem sub-tile (ldsm trans), 64 cols
__device__ __forceinline__ void ldBT64(uint32_t r[4][4], uint32_t bbase, int wn, int lane, int ks) {
    const int k = ks * 16 + (lane & 15);
#pragma unroll
    for (int nj = 0; nj < 4; nj++) {
        const int cl = wn * 8 + nj * 2 + (lane >> 4);
        ldsm4t(r[nj], bbase + k * 256 + ((cl ^ ((k & 7) << 1)) << 4));
    }
}

__device__ __forceinline__ void mmas_bf16(float c[4][8][4], uint32_t a[4][4], uint32_t b[4][4]) {
#pragma unroll
    for (int mi = 0; mi < 4; mi++)
#pragma unroll
        for (int nj = 0; nj < 4; nj++) {
            mma_bf16(c[mi][2 * nj],     a[mi], b[nj][0], b[nj][2]);
            mma_bf16(c[mi][2 * nj + 1], a[mi], b[nj][1], b[nj][3]);
        }
}
__device__ __forceinline__ void mmas_f16(float c[4][8][4], uint32_t a[4][4], uint32_t b[4][4]) {
#pragma unroll
    for (int mi = 0; mi < 4; mi++)
#pragma unroll
        for (int nj = 0; nj < 4; nj++) {
            mma_f16(c[mi][2 * nj],     a[mi], b[nj][0], b[nj][2]);
            mma_f16(c[mi][2 * nj + 1], a[mi], b[nj][1], b[nj][3]);
        }
}
__device__ __forceinline__ void mmas_f16t(float c[4][8][4], uint32_t a[4][4], uint32_t b[4][4]) {
#pragma unroll
    for (int mi = 0; mi < 4; mi++)
#pragma unroll
        for (int nj = 0; nj < 4; nj++) {
            mma_f16(c[mi][2 * nj],     a[mi], b[nj][0], b[nj][1]);
            mma_f16(c[mi][2 * nj + 1], a[mi], b[nj][2], b[nj][3]);
        }
}

// 2-stage pipeline bottom (iter it): publish stage(it+1), refill freed buffer.
// LOADI(saddr, itn) loads iteration itn's K-chunk into saddr.
#define PIPE2_BOTTOM(LOADI, it, nit, STGB)                        \
    do {                                                          \
        if ((it) + 1 < (nit)) {                                   \
            __syncthreads();      /* stage(it) reads done */      \
            const bool more = ((it) + 2 < (nit));                 \
            if (more) { LOADI(sb + ((it) & 1) * (STGB), (it) + 2); } \
            if (more) { CP_WAIT1(); } else { CP_WAIT0(); }        \
            __syncthreads();      /* stage(it+1) published */     \
        }                                                         \
    } while (0)

// ---------------------------------------------------------------------------
// hi/lo 3-pass GEMM: CTA 128x128, 4 warps (2m x 2n), warp 64x64, BK=32
// stage: Ahi 0, Alo 10240, Bhi 20480, Blo 30720; stride 40960
// ---------------------------------------------------------------------------
#define HL_ALO 10240
#define HL_BHI 20480
#define HL_BLO 30720
#define HL_STG 40960
#define SMEM_HILO (2 * HL_STG)

#define HL_LOADI(saddr, itn)                                      \
    do {                                                          \
        const int ko_ = (itn) * 32;                               \
        cpa_k((saddr),           Ah + ko_, la, tid);              \
        cpa_k((saddr) + HL_ALO,  Al + ko_, la, tid);              \
        cpa_k((saddr) + HL_BHI,  Bh + ko_, lb, tid);              \
        cpa_k((saddr) + HL_BLO,  Bl + ko_, lb, tid);              \
        CP_COMMIT();                                              \
    } while (0)

__device__ __forceinline__ void kstep_hilo(uint32_t stg, int ks, int lane,
                                           int wm, int wn, float c[4][8][4]) {
    uint32_t ah[4][4], bh[4][4], t[4][4];
    ldF64(ah, stg, wm, lane, ks);
    ldF64(bh, stg + HL_BHI, wn, lane, ks);
    mmas_bf16(c, ah, bh);
    ldF64(t, stg + HL_BLO, wn, lane, ks);
    mmas_bf16(c, ah, t);
    ldF64(t, stg + HL_ALO, wm, lane, ks);
    mmas_bf16(c, t, bh);
}

__device__ __forceinline__ void gemm_hilo(const bf16* Ah, const bf16* Al, int lda,
                                          const bf16* Bh, const bf16* Bl, int ldb,
                                          int nit, uint32_t sb, int tid, float c[4][8][4]) {
    const int lane = tid & 31, wid = tid >> 5;
    const int wm = wid >> 1, wn = wid & 1;
    const int la = lda * 2, lb = ldb * 2;
    HL_LOADI(sb, 0);
    if (nit > 1) { HL_LOADI(sb + HL_STG, 1); CP_WAIT1(); }
    else         { CP_WAIT0(); }
    __syncthreads();
    for (int it = 0; it < nit; it++) {
        const uint32_t stg = sb + (it & 1) * HL_STG;
        kstep_hilo(stg, 0, lane, wm, wn, c);
        kstep_hilo(stg, 1, lane, wm, wn, c);
        PIPE2_BOTTOM(HL_LOADI, it, nit, HL_STG);
    }
}

// ---------------------------------------------------------------------------
// fp16 single-pass GEMM (B K-major): CTA 128x128, BK=64 (two 32-col sub-tiles)
// stage: A0 0, A1 10240, B0 20480, B1 30720; stride 40960
// ---------------------------------------------------------------------------
#define V_STG  40960
#define SMEM_V (2 * V_STG)

#define V_LOADI(saddr, itn)                                       \
    do {                                                          \
        const int ko_ = (itn) * 64;                               \
        cpa_k((saddr),          Af + ko_,      la, tid);          \
        cpa_k((saddr) + 10240,  Af + ko_ + 32, la, tid);          \
        cpa_k((saddr) + 20480,  Bf + ko_,      lb, tid);          \
        cpa_k((saddr) + 30720,  Bf + ko_ + 32, lb, tid);          \
        CP_COMMIT();                                              \
    } while (0)

__device__ __forceinline__ void gemm_f16nt(const __half* Af, int lda, const __half* Bf, int ldb,
                                           int nit, uint32_t sb, int tid, float c[4][8][4]) {
    const int lane = tid & 31, wid = tid >> 5;
    const int wm = wid >> 1, wn = wid & 1;
    const int la = lda * 2, lb = ldb * 2;
    V_LOADI(sb, 0);
    if (nit > 1) { V_LOADI(sb + V_STG, 1); CP_WAIT1(); }
    else         { CP_WAIT0(); }
    __syncthreads();
    for (int it = 0; it < nit; it++) {
        const uint32_t stg = sb + (it & 1) * V_STG;
#pragma unroll
        for (int k4 = 0; k4 < 4; k4++) {
            const int sub = k4 >> 1, ks = k4 & 1;
            uint32_t ah[4][4], bh[4][4];
            ldF64(ah, stg + sub * 10240, wm, lane, ks);
            ldF64(bh, stg + 20480 + sub * 10240, wn, lane, ks);
            mmas_f16(c, ah, bh);
        }
        PIPE2_BOTTOM(V_LOADI, it, nit, V_STG);
    }
}

// ---------------------------------------------------------------------------
// fp16 single-pass GEMM (B transposed [k][n]): CTA 128x128, BK=64
// stage: A0 0, A1 10240, BT0 20480 (8192), BT1 28672 (8192); stride 36864
// ---------------------------------------------------------------------------
#define AV_STG  36864
#define SMEM_AV (2 * AV_STG)

#define AV_LOADI(saddr, itn)                                      \
    do {                                                          \
        const int ko_ = (itn) * 64;                               \
        cpa_k((saddr),          Af + ko_,      la, tid);          \
        cpa_k((saddr) + 10240,  Af + ko_ + 32, la, tid);          \
        cpa_t((saddr) + 20480,  Bf + (size_t)ko_ * ldb,        lb, tid); \
        cpa_t((saddr) + 28672,  Bf + (size_t)(ko_ + 32) * ldb, lb, tid); \
        CP_COMMIT();                                              \
    } while (0)

__device__ __forceinline__ void gemm_f16t(const __half* Af, int lda, const __half* Bf, int ldb,
                                          int nit, uint32_t sb, int tid, float c[4][8][4]) {
    const int lane = tid & 31, wid = tid >> 5;
    const int wm = wid >> 1, wn = wid & 1;
    const int la = lda * 2, lb = ldb * 2;
    AV_LOADI(sb, 0);
    if (nit > 1) { AV_LOADI(sb + AV_STG, 1); CP_WAIT1(); }
    else         { CP_WAIT0(); }
    __syncthreads();
    for (int it = 0; it < nit; it++) {
        const uint32_t stg = sb + (it & 1) * AV_STG;
#pragma unroll
        for (int k4 = 0; k4 < 4; k4++) {
            const int sub = k4 >> 1, ks = k4 & 1;
            uint32_t ah[4][4], bt[4][4];
            ldF64 (ah, stg + sub * 10240, wm, lane, ks);
            ldBT64(bt, stg + 20480 + sub * 8192, wn, lane, ks);
            mmas_f16t(c, ah, bt);
        }
        PIPE2_BOTTOM(AV_LOADI, it, nit, AV_STG);
    }
}

// ---------------------------------------------------------------------------
// Conversions
// ---------------------------------------------------------------------------
__global__ void k_cvtX(const float* __restrict__ x, int n) {
    int i = blockIdx.x * 256 + threadIdx.x;
    const int stride = gridDim.x * 256;
    for (; i < n; i += stride) {
        float v = x[i];
        bf16 h, l; split_bf16(v, h, l);
        g_Xhi[i] = h; g_Xlo[i] = l; g_Xh[i] = __float2half_rn(v);
    }
}
__global__ void k_cvtW(const float* __restrict__ wqk, const float* __restrict__ wov, int n) {
    int i = blockIdx.x * 256 + threadIdx.x;
    const int stride = gridDim.x * 256;
    for (; i < n; i += stride) {
        bf16 h, l; split_bf16(wqk[i], h, l);
        g_Whi[i] = h; g_Wlo[i] = l;
        g_Wh[i] = __float2half_rn(wov[i]);
    }
}

// ---------------------------------------------------------------------------
// Merged Q+V kernel (z=0: Q hilo 3-pass; z=1: V fp16 BK=64)
// ---------------------------------------------------------------------------
__global__ __launch_bounds__(128, 2) void k_qv() {
    extern __shared__ __align__(1024) char smem[];
    const uint32_t sb = smem_u32(smem);
    const int tid = threadIdx.x;
    const int m0 = blockIdx.y * 128, n0 = blockIdx.x * 128;
    const int lane = tid & 31, wid = tid >> 5;
    const int wm = wid >> 1, wn = wid & 1;
    float c[4][8][4] = {};

    if (blockIdx.z == 0) {
        gemm_hilo(g_Xhi + (size_t)m0 * D_, g_Xlo + (size_t)m0 * D_, D_,
                  g_Whi + (size_t)n0 * D_, g_Wlo + (size_t)n0 * D_, D_,
                  D_ / 32, sb, tid, c);
#pragma unroll
        for (int mi = 0; mi < 4; mi++) {
            const int r0 = m0 + wm * 64 + mi * 16 + (lane >> 2);
#pragma unroll
            for (int ni = 0; ni < 8; ni++) {
                const int gc = n0 + wn * 64 + ni * 8 + (lane & 3) * 2;
                const float* cc = c[mi][ni];
#pragma unroll
                for (int h = 0; h < 2; h++) {
                    const size_t idx = (size_t)(r0 + 8 * h) * D_ + gc;
                    bf16 h0, l0, h1, l1;
                    split_bf16(cc[2 * h],     h0, l0);
                    split_bf16(cc[2 * h + 1], h1, l1);
                    __nv_bfloat162 hh; hh.x = h0; hh.y = h1;
                    __nv_bfloat162 ll; ll.x = l0; ll.y = l1;
                    *(__nv_bfloat162*)(g_Qhi + idx) = hh;
                    *(__nv_bfloat162*)(g_Qlo + idx) = ll;
                }
            }
        }
    } else {
        gemm_f16nt(g_Xh + (size_t)m0 * D_, D_, g_Wh + (size_t)n0 * D_, D_,
                   D_ / 64, sb, tid, c);
#pragma unroll
        for (int mi = 0; mi < 4; mi++) {
            const int r0 = m0 + wm * 64 + mi * 16 + (lane >> 2);
#pragma unroll
            for (int ni = 0; ni < 8; ni++) {
                const int gc = n0 + wn * 64 + ni * 8 + (lane & 3) * 2;
                const float* cc = c[mi][ni];
#pragma unroll
                for (int h = 0; h < 2; h++) {
                    const size_t idx = (size_t)(r0 + 8 * h) * D_ + gc;
                    *(__half2*)(g_Vh + idx) = __floats2half2_rn(cc[2 * h], cc[2 * h + 1]);
                }
            }
        }
    }
}

__global__ __launch_bounds__(128, 2) void k_scores(float* __restrict__ Aout) {
    if (blockIdx.x > blockIdx.y) return;   // strictly above diagonal
    extern __shared__ __align__(1024) char smem[];
    const uint32_t sb = smem_u32(smem);
    const int tid = threadIdx.x;
    const int b = blockIdx.z;
    const int m0 = blockIdx.y * 128, n0 = blockIdx.x * 128;
    const size_t xb = (size_t)b * S_ * D_;
    float c[4][8][4] = {};
    gemm_hilo(g_Qhi + xb + (size_t)m0 * D_, g_Qlo + xb + (size_t)m0 * D_, D_,
              g_Xhi + xb + (size_t)n0 * D_, g_Xlo + xb + (size_t)n0 * D_, D_,
              D_ / 32, sb, tid, c);
    const int lane = tid & 31, wid = tid >> 5;
    const int wm = wid >> 1, wn = wid & 1;
    float* Ab = Aout + (size_t)b * S_ * S_;
#pragma unroll
    for (int mi = 0; mi < 4; mi++) {
        const int r0 = m0 + wm * 64 + mi * 16 + (lane >> 2);
#pragma unroll
        for (int ni = 0; ni < 8; ni++) {
            const int gc = n0 + wn * 64 + ni * 8 + (lane & 3) * 2;
            const float* cc = c[mi][ni];
#pragma unroll
            for (int h = 0; h < 2; h++) {
                float2 v = make_float2(cc[2 * h] * 32.0f, cc[2 * h + 1] * 32.0f);
                *(float2*)(Ab + (size_t)(r0 + 8 * h) * S_ + gc) = v;
            }
        }
    }
}

// ---------------------------------------------------------------------------
// Softmax (causal, in place) + fp16 A emission
// ---------------------------------------------------------------------------
__global__ void k_softmax(float* __restrict__ A) {
    const int s = blockIdx.x, b = blockIdx.y;
    const size_t rb = ((size_t)b * S_ + s) * S_;
    float* row = A + rb;
    __half* Ah = g_Ah + rb;
    const int len = s + 1;
    const int tid = threadIdx.x;
    __shared__ float red[256];

    float v[8];
    float m = -1e30f;
#pragma unroll
    for (int it = 0; it < 8; it++) {
        int j = tid + it * 256;
        v[it] = (j < len) ? row[j] : -1e30f;
        m = fmaxf(m, v[it]);
    }
    red[tid] = m; __syncthreads();
    for (int o = 128; o > 0; o >>= 1) {
        if (tid < o) red[tid] = fmaxf(red[tid], red[tid + o]);
        __syncthreads();
    }
    m = red[0]; __syncthreads();

    float sum = 0.0f;
#pragma unroll
    for (int it = 0; it < 8; it++) {
        int j = tid + it * 256;
        v[it] = (j < len) ? __expf(v[it] - m) : 0.0f;
        sum += v[it];
    }
    red[tid] = sum; __syncthreads();
    for (int o = 128; o > 0; o >>= 1) {
        if (tid < o) red[tid] += red[tid + o];
        __syncthreads();
    }
    const float inv = 1.0f / red[0];

#pragma unroll
    for (int it = 0; it < 8; it++) {
        int j = tid + it * 256;
        float a = v[it] * inv;
        row[j] = a;
        Ah[j]  = __float2half_rn(a);
    }
}

// ---------------------------------------------------------------------------
// GEMM3: Y = A@V (fp16, causal K-truncation, BK=64), out = X + Y
// ---------------------------------------------------------------------------
__global__ __launch_bounds__(128, 2) void k_av(const float* __restrict__ X,
                                               float* __restrict__ Yout) {
    extern __shared__ __align__(1024) char smem[];
    const uint32_t sb = smem_u32(smem);
    const int tid = threadIdx.x;
    const int b = blockIdx.z;
    const int m0 = blockIdx.y * 128, n0 = blockIdx.x * 128;
    float c[4][8][4] = {};
    gemm_f16t(g_Ah + (size_t)b * S_ * S_ + (size_t)m0 * S_, S_,
              g_Vh + (size_t)b * S_ * D_ + n0, D_,
              (blockIdx.y + 1) * 2, sb, tid, c);
    const int lane = tid & 31, wid = tid >> 5;
    const int wm = wid >> 1, wn = wid & 1;
#pragma unroll
    for (int mi = 0; mi < 4; mi++) {
        const int r0 = m0 + wm * 64 + mi * 16 + (lane >> 2);
#pragma unroll
        for (int ni = 0; ni < 8; ni++) {
            const int gc = n0 + wn * 64 + ni * 8 + (lane & 3) * 2;
            const float* cc = c[mi][ni];
#pragma unroll
            for (int h = 0; h < 2; h++) {
                const size_t idx = ((size_t)b * S_ + (r0 + 8 * h)) * D_ + gc;
                float2 x2 = *(const float2*)(X + idx);
                float2 o = make_float2(cc[2 * h] + x2.x, cc[2 * h + 1] + x2.y);
                *(float2*)(Yout + idx) = o;
            }
        }
    }
}

// ---------------------------------------------------------------------------
extern "C" void kernel_launch(void* const* d_in, const int* in_sizes, int n_in,
                              void* d_out, int out_size) {
    const float* X   = (const float*)d_in[0];
    const float* WQK = (const float*)d_in[2];
    const float* WOV = (const float*)d_in[3];
    float* out = (float*)d_out;

    const size_t nY = (size_t)M1 * D_;
    const size_t nA = (size_t)B_ * S_ * S_;
    float* Aout;
    if ((size_t)out_size >= nY + nA) {
        Aout = out + nY;
    } else {
        void* p = nullptr;
        cudaGetSymbolAddress(&p, g_Afallback);
        Aout = (float*)p;
    }

    static bool attrs_set = false;
    if (!attrs_set) {
        cudaFuncSetAttribute(k_qv,     cudaFuncAttributeMaxDynamicSharedMemorySize, SMEM_HILO);
        cudaFuncSetAttribute(k_scores, cudaFuncAttributeMaxDynamicSharedMemorySize, SMEM_HILO);
        cudaFuncSetAttribute(k_av,     cudaFuncAttributeMaxDynamicSharedMemorySize, SMEM_AV);
        attrs_set = true;
    }

    // 1) conversions
    k_cvtX<<<512, 256>>>(X, M1 * D_);
    k_cvtW<<<256, 256>>>(WQK, WOV, D_ * D_);
    // 2) Q (hilo bf16 3-pass) + V (fp16, BK=64) merged
    k_qv<<<dim3(D_ / 128, M1 / 128, 2), 128, SMEM_HILO>>>();
    // 3) causal scaled scores -> A region (fp32)
    k_scores<<<dim3(S_ / 128, S_ / 128, B_), 128, SMEM_HILO>>>(Aout);
    // 4) softmax in place + A fp16
    k_softmax<<<dim3(S_, B_), 256>>>(Aout);
    // 5) Y = A@V + X (BK=64)
    k_av<<<dim3(D_ / 128, S_ / 128, B_), 128, SMEM_AV>>>(X, out);
}

// round 10
// speedup vs baseline: 3.6485x; 1.0178x over previous
#include <cuda_runtime.h>
#include <cuda_bf16.h>
#include <cuda_fp16.h>
#include <cstdint>

#define B_  4
#define S_  2048
#define D_  1024
#define M1  (B_ * S_)

typedef __nv_bfloat16 bf16;

// ---------------------------------------------------------------------------
// Scratch (__device__ globals; no allocation allowed)
// ---------------------------------------------------------------------------
__device__ __align__(256) bf16   g_Xhi[(size_t)M1 * D_];
__device__ __align__(256) bf16   g_Xlo[(size_t)M1 * D_];
__device__ __align__(256) __half g_Xh [(size_t)M1 * D_];
__device__ __align__(256) bf16   g_Whi[(size_t)D_ * D_];
__device__ __align__(256) bf16   g_Wlo[(size_t)D_ * D_];
__device__ __align__(256) __half g_Wh [(size_t)D_ * D_];
__device__ __align__(256) bf16   g_Qhi[(size_t)M1 * D_];
__device__ __align__(256) bf16   g_Qlo[(size_t)M1 * D_];
__device__ __align__(256) __half g_Vh [(size_t)M1 * D_];        // V [m][d]
__device__ __align__(256) __half g_Ah [(size_t)B_ * S_ * S_];   // A fp16 [s][t]
__device__ float g_Afallback[(size_t)B_ * S_ * S_];

// ---------------------------------------------------------------------------
// Baseline-PTX primitives
// ---------------------------------------------------------------------------
__device__ __forceinline__ uint32_t smem_u32(const void* p) {
    uint32_t a;
    asm("{ .reg .u64 t; cvta.to.shared.u64 t, %1; cvt.u32.u64 %0, t; }" : "=r"(a) : "l"(p));
    return a;
}
#define CPA(dst, src)  asm volatile("cp.async.cg.shared.global [%0], [%1], 16;\n" :: "r"(dst), "l"(src))
#define CP_COMMIT()    asm volatile("cp.async.commit_group;\n" ::: "memory")
#define CP_WAIT1()     asm volatile("cp.async.wait_group 1;\n" ::: "memory")
#define CP_WAIT0()     asm volatile("cp.async.wait_group 0;\n" ::: "memory")

__device__ __forceinline__ void ldsm4(uint32_t r[4], uint32_t a) {
    asm volatile("ldmatrix.sync.aligned.m8n8.x4.shared.b16 {%0,%1,%2,%3}, [%4];\n"
                 : "=r"(r[0]), "=r"(r[1]), "=r"(r[2]), "=r"(r[3]) : "r"(a));
}
__device__ __forceinline__ void ldsm4t(uint32_t r[4], uint32_t a) {
    asm volatile("ldmatrix.sync.aligned.m8n8.x4.trans.shared.b16 {%0,%1,%2,%3}, [%4];\n"
                 : "=r"(r[0]), "=r"(r[1]), "=r"(r[2]), "=r"(r[3]) : "r"(a));
}
__device__ __forceinline__ void mma_bf16(float* c, const uint32_t a[4], uint32_t b0, uint32_t b1) {
    asm volatile("mma.sync.aligned.m16n8k16.row.col.f32.bf16.bf16.f32 "
                 "{%0,%1,%2,%3}, {%4,%5,%6,%7}, {%8,%9}, {%0,%1,%2,%3};\n"
                 : "+f"(c[0]), "+f"(c[1]), "+f"(c[2]), "+f"(c[3])
                 : "r"(a[0]), "r"(a[1]), "r"(a[2]), "r"(a[3]), "r"(b0), "r"(b1));
}
__device__ __forceinline__ void mma_f16(float* c, const uint32_t a[4], uint32_t b0, uint32_t b1) {
    asm volatile("mma.sync.aligned.m16n8k16.row.col.f32.f16.f16.f32 "
                 "{%0,%1,%2,%3}, {%4,%5,%6,%7}, {%8,%9}, {%0,%1,%2,%3};\n"
                 : "+f"(c[0]), "+f"(c[1]), "+f"(c[2]), "+f"(c[3])
                 : "r"(a[0]), "r"(a[1]), "r"(a[2]), "r"(a[3]), "r"(b0), "r"(b1));
}
__device__ __forceinline__ void split_bf16(float v, bf16& h, bf16& l) {
    h = __float2bfloat16_rn(v);
    l = __float2bfloat16_rn(v - __bfloat162float(h));
}

// ---------------------------------------------------------------------------
// Tile loaders: 128 threads. K-major [128 rows][32 elems], smem rows 80B.
// ---------------------------------------------------------------------------
__device__ __forceinline__ void cpa_k(uint32_t sdst, const void* g, int ldbytes, int tid) {
#pragma unroll
    for (int i = 0; i < 4; i++) {
        int u = tid + i * 128;
        int r = u >> 2, c = u & 3;
        CPA(sdst + r * 80 + c * 16, (const char*)g + (size_t)r * ldbytes + c * 16);
    }
}
// Transposed tile [32 k][128 n], 256B rows, XOR swizzle (128 threads, 4 iters)
__device__ __forceinline__ void cpa_t(uint32_t sdst, const void* g, int ldbytes, int tid) {
#pragma unroll
    for (int i = 0; i < 4; i++) {
        int u = tid + i * 128;
        int k = u >> 4, c = u & 15;
        CPA(sdst + k * 256 + ((c ^ ((k & 7) << 1)) << 4),
            (const char*)g + (size_t)k * ldbytes + c * 16);
    }
}

__device__ __forceinline__ void ld4frag(uint32_t base, uint32_t r[4][4]) {
#pragma unroll
    for (int i = 0; i < 4; i++) ldsm4(r[i], base + i * 1280);
}
// 64-row fragment, K-major smem sub-tile
__device__ __forceinline__ void ldF64(uint32_t r[4][4], uint32_t base, int w, int lane, int ks) {
    const int row = lane & 15;
    const int ch  = (lane >> 4) + ks * 2;
    ld4frag(base + (w * 64 + row) * 80 + ch * 16, r);
}
// B fragment from transposed [k][n] smem sub-tile (ldsm trans), 64 cols
__device__ __forceinline__ void ldBT64(uint32_t r[4][4], uint32_t bbase, int wn, int lane, int ks) {
    const int k = ks * 16 + (lane & 15);
#pragma unroll
    for (int nj = 0; nj < 4; nj++) {
        const int cl = wn * 8 + nj * 2 + (lane >> 4);
        ldsm4t(r[nj], bbase + k * 256 + ((cl ^ ((k & 7) << 1)) << 4));
    }
}

__device__ __forceinline__ void mmas_bf16(float c[4][8][4], uint32_t a[4][4], uint32_t b[4][4]) {
#pragma unroll
    for (int mi = 0; mi < 4; mi++)
#pragma unroll
        for (int nj = 0; nj < 4; nj++) {
            mma_bf16(c[mi][2 * nj],     a[mi], b[nj][0], b[nj][2]);
            mma_bf16(c[mi][2 * nj + 1], a[mi], b[nj][1], b[nj][3]);
        }
}
__device__ __forceinline__ void mmas_f16(float c[4][8][4], uint32_t a[4][4], uint32_t b[4][4]) {
#pragma unroll
    for (int mi = 0; mi < 4; mi++)
#pragma unroll
        for (int nj = 0; nj < 4; nj++) {
            mma_f16(c[mi][2 * nj],     a[mi], b[nj][0], b[nj][2]);
            mma_f16(c[mi][2 * nj + 1], a[mi], b[nj][1], b[nj][3]);
        }
}
__device__ __forceinline__ void mmas_f16t(float c[4][8][4], uint32_t a[4][4], uint32_t b[4][4]) {
#pragma unroll
    for (int mi = 0; mi < 4; mi++)
#pragma unroll
        for (int nj = 0; nj < 4; nj++) {
            mma_f16(c[mi][2 * nj],     a[mi], b[nj][0], b[nj][1]);
            mma_f16(c[mi][2 * nj + 1], a[mi], b[nj][2], b[nj][3]);
        }
}

// 2-stage pipeline bottom (iter it): publish stage(it+1), refill freed buffer.
#define PIPE2_BOTTOM(LOADI, it, nit, STGB)                        \
    do {                                                          \
        if ((it) + 1 < (nit)) {                                   \
            __syncthreads();      /* stage(it) reads done */      \
            const bool more = ((it) + 2 < (nit));                 \
            if (more) { LOADI(sb + ((it) & 1) * (STGB), (it) + 2); } \
            if (more) { CP_WAIT1(); } else { CP_WAIT0(); }        \
            __syncthreads();      /* stage(it+1) published */     \
        }                                                         \
    } while (0)

// ---------------------------------------------------------------------------
// hi/lo 3-pass GEMM: CTA 128x128, 4 warps (2m x 2n), warp 64x64, BK=32
// ---------------------------------------------------------------------------
#define HL_ALO 10240
#define HL_BHI 20480
#define HL_BLO 30720
#define HL_STG 40960
#define SMEM_HILO (2 * HL_STG)

#define HL_LOADI(saddr, itn)                                      \
    do {                                                          \
        const int ko_ = (itn) * 32;                               \
        cpa_k((saddr),           Ah + ko_, la, tid);              \
        cpa_k((saddr) + HL_ALO,  Al + ko_, la, tid);              \
        cpa_k((saddr) + HL_BHI,  Bh + ko_, lb, tid);              \
        cpa_k((saddr) + HL_BLO,  Bl + ko_, lb, tid);              \
        CP_COMMIT();                                              \
    } while (0)

// Fully hoisted k16 step: 16 ldsm, then uninterrupted 24-MMA stream.
__device__ __forceinline__ void kstep_hilo(uint32_t stg, int ks, int lane,
                                           int wm, int wn, float c[4][8][4]) {
    uint32_t ah[4][4], al[4][4], bh[4][4], bl[4][4];
    ldF64(ah, stg, wm, lane, ks);
    ldF64(bh, stg + HL_BHI, wn, lane, ks);
    ldF64(bl, stg + HL_BLO, wn, lane, ks);
    ldF64(al, stg + HL_ALO, wm, lane, ks);
    mmas_bf16(c, ah, bh);
    mmas_bf16(c, ah, bl);
    mmas_bf16(c, al, bh);
}

__device__ __forceinline__ void gemm_hilo(const bf16* Ah, const bf16* Al, int lda,
                                          const bf16* Bh, const bf16* Bl, int ldb,
                                          int nit, uint32_t sb, int tid, float c[4][8][4]) {
    const int lane = tid & 31, wid = tid >> 5;
    const int wm = wid >> 1, wn = wid & 1;
    const int la = lda * 2, lb = ldb * 2;
    HL_LOADI(sb, 0);
    if (nit > 1) { HL_LOADI(sb + HL_STG, 1); CP_WAIT1(); }
    else         { CP_WAIT0(); }
    __syncthreads();
    for (int it = 0; it < nit; it++) {
        const uint32_t stg = sb + (it & 1) * HL_STG;
        kstep_hilo(stg, 0, lane, wm, wn, c);
        kstep_hilo(stg, 1, lane, wm, wn, c);
        PIPE2_BOTTOM(HL_LOADI, it, nit, HL_STG);
    }
}

// ---------------------------------------------------------------------------
// fp16 single-pass GEMM (B K-major): CTA 128x128, BK=64
// ---------------------------------------------------------------------------
#define V_STG  40960
#define SMEM_V (2 * V_STG)

#define V_LOADI(saddr, itn)                                       \
    do {                                                          \
        const int ko_ = (itn) * 64;                               \
        cpa_k((saddr),          Af + ko_,      la, tid);          \
        cpa_k((saddr) + 10240,  Af + ko_ + 32, la, tid);          \
        cpa_k((saddr) + 20480,  Bf + ko_,      lb, tid);          \
        cpa_k((saddr) + 30720,  Bf + ko_ + 32, lb, tid);          \
        CP_COMMIT();                                              \
    } while (0)

__device__ __forceinline__ void gemm_f16nt(const __half* Af, int lda, const __half* Bf, int ldb,
                                           int nit, uint32_t sb, int tid, float c[4][8][4]) {
    const int lane = tid & 31, wid = tid >> 5;
    const int wm = wid >> 1, wn = wid & 1;
    const int la = lda * 2, lb = ldb * 2;
    V_LOADI(sb, 0);
    if (nit > 1) { V_LOADI(sb + V_STG, 1); CP_WAIT1(); }
    else         { CP_WAIT0(); }
    __syncthreads();
    for (int it = 0; it < nit; it++) {
        const uint32_t stg = sb + (it & 1) * V_STG;
#pragma unroll
        for (int k4 = 0; k4 < 4; k4++) {
            const int sub = k4 >> 1, ks = k4 & 1;
            uint32_t ah[4][4], bh[4][4];
            ldF64(ah, stg + sub * 10240, wm, lane, ks);
            ldF64(bh, stg + 20480 + sub * 10240, wn, lane, ks);
            mmas_f16(c, ah, bh);
        }
        PIPE2_BOTTOM(V_LOADI, it, nit, V_STG);
    }
}

// ---------------------------------------------------------------------------
// fp16 single-pass GEMM (B transposed [k][n]): CTA 128x128, BK=64
// ---------------------------------------------------------------------------
#define AV_STG  36864
#define SMEM_AV (2 * AV_STG)

#define AV_LOADI(saddr, itn)                                      \
    do {                                                          \
        const int ko_ = (itn) * 64;                               \
        cpa_k((saddr),          Af + ko_,      la, tid);          \
        cpa_k((saddr) + 10240,  Af + ko_ + 32, la, tid);          \
        cpa_t((saddr) + 20480,  Bf + (size_t)ko_ * ldb,        lb, tid); \
        cpa_t((saddr) + 28672,  Bf + (size_t)(ko_ + 32) * ldb, lb, tid); \
        CP_COMMIT();                                              \
    } while (0)

__device__ __forceinline__ void gemm_f16t(const __half* Af, int lda, const __half* Bf, int ldb,
                                          int nit, uint32_t sb, int tid, float c[4][8][4]) {
    const int lane = tid & 31, wid = tid >> 5;
    const int wm = wid >> 1, wn = wid & 1;
    const int la = lda * 2, lb = ldb * 2;
    AV_LOADI(sb, 0);
    if (nit > 1) { AV_LOADI(sb + AV_STG, 1); CP_WAIT1(); }
    else         { CP_WAIT0(); }
    __syncthreads();
    for (int it = 0; it < nit; it++) {
        const uint32_t stg = sb + (it & 1) * AV_STG;
#pragma unroll
        for (int k4 = 0; k4 < 4; k4++) {
            const int sub = k4 >> 1, ks = k4 & 1;
            uint32_t ah[4][4], bt[4][4];
            ldF64 (ah, stg + sub * 10240, wm, lane, ks);
            ldBT64(bt, stg + 20480 + sub * 8192, wn, lane, ks);
            mmas_f16t(c, ah, bt);
        }
        PIPE2_BOTTOM(AV_LOADI, it, nit, AV_STG);
    }
}

// ---------------------------------------------------------------------------
// Conversions (vectorized float4)
// ---------------------------------------------------------------------------
__global__ void k_cvtX(const float4* __restrict__ x, int n4) {
    int i = blockIdx.x * 256 + threadIdx.x;
    const int stride = gridDim.x * 256;
    for (; i < n4; i += stride) {
        float4 v = x[i];
        bf16 h0, l0, h1, l1, h2, l2, h3, l3;
        split_bf16(v.x, h0, l0); split_bf16(v.y, h1, l1);
        split_bf16(v.z, h2, l2); split_bf16(v.w, h3, l3);
        uint2 hh, ll;
        hh.x = ((uint32_t)*(uint16_t*)&h1 << 16) | *(uint16_t*)&h0;
        hh.y = ((uint32_t)*(uint16_t*)&h3 << 16) | *(uint16_t*)&h2;
        ll.x = ((uint32_t)*(uint16_t*)&l1 << 16) | *(uint16_t*)&l0;
        ll.y = ((uint32_t)*(uint16_t*)&l3 << 16) | *(uint16_t*)&l2;
        *(uint2*)(g_Xhi + (size_t)i * 4) = hh;
        *(uint2*)(g_Xlo + (size_t)i * 4) = ll;
        __half2 f01 = __floats2half2_rn(v.x, v.y);
        __half2 f23 = __floats2half2_rn(v.z, v.w);
        uint2 ff; ff.x = *(uint32_t*)&f01; ff.y = *(uint32_t*)&f23;
        *(uint2*)(g_Xh + (size_t)i * 4) = ff;
    }
}
__global__ void k_cvtW(const float4* __restrict__ wqk, const float4* __restrict__ wov, int n4) {
    int i = blockIdx.x * 256 + threadIdx.x;
    const int stride = gridDim.x * 256;
    for (; i < n4; i += stride) {
        float4 v = wqk[i];
        bf16 h0, l0, h1, l1, h2, l2, h3, l3;
        split_bf16(v.x, h0, l0); split_bf16(v.y, h1, l1);
        split_bf16(v.z, h2, l2); split_bf16(v.w, h3, l3);
        uint2 hh, ll;
        hh.x = ((uint32_t)*(uint16_t*)&h1 << 16) | *(uint16_t*)&h0;
        hh.y = ((uint32_t)*(uint16_t*)&h3 << 16) | *(uint16_t*)&h2;
        ll.x = ((uint32_t)*(uint16_t*)&l1 << 16) | *(uint16_t*)&l0;
        ll.y = ((uint32_t)*(uint16_t*)&l3 << 16) | *(uint16_t*)&l2;
        *(uint2*)(g_Whi + (size_t)i * 4) = hh;
        *(uint2*)(g_Wlo + (size_t)i * 4) = ll;
        float4 w = wov[i];
        __half2 f01 = __floats2half2_rn(w.x, w.y);
        __half2 f23 = __floats2half2_rn(w.z, w.w);
        uint2 ff; ff.x = *(uint32_t*)&f01; ff.y = *(uint32_t*)&f23;
        *(uint2*)(g_Wh + (size_t)i * 4) = ff;
    }
}

// ---------------------------------------------------------------------------
// Merged Q+V kernel (z=0: Q hilo 3-pass; z=1: V fp16 BK=64)
// ---------------------------------------------------------------------------
__global__ __launch_bounds__(128, 2) void k_qv() {
    extern __shared__ __align__(1024) char smem[];
    const uint32_t sb = smem_u32(smem);
    const int tid = threadIdx.x;
    const int m0 = blockIdx.y * 128, n0 = blockIdx.x * 128;
    const int lane = tid & 31, wid = tid >> 5;
    const int wm = wid >> 1, wn = wid & 1;
    float c[4][8][4] = {};

    if (blockIdx.z == 0) {
        gemm_hilo(g_Xhi + (size_t)m0 * D_, g_Xlo + (size_t)m0 * D_, D_,
                  g_Whi + (size_t)n0 * D_, g_Wlo + (size_t)n0 * D_, D_,
                  D_ / 32, sb, tid, c);
#pragma unroll
        for (int mi = 0; mi < 4; mi++) {
            const int r0 = m0 + wm * 64 + mi * 16 + (lane >> 2);
#pragma unroll
            for (int ni = 0; ni < 8; ni++) {
                const int gc = n0 + wn * 64 + ni * 8 + (lane & 3) * 2;
                const float* cc = c[mi][ni];
#pragma unroll
                for (int h = 0; h < 2; h++) {
                    const size_t idx = (size_t)(r0 + 8 * h) * D_ + gc;
                    bf16 h0, l0, h1, l1;
                    split_bf16(cc[2 * h],     h0, l0);
                    split_bf16(cc[2 * h + 1], h1, l1);
                    __nv_bfloat162 hh; hh.x = h0; hh.y = h1;
                    __nv_bfloat162 ll; ll.x = l0; ll.y = l1;
                    *(__nv_bfloat162*)(g_Qhi + idx) = hh;
                    *(__nv_bfloat162*)(g_Qlo + idx) = ll;
                }
            }
        }
    } else {
        gemm_f16nt(g_Xh + (size_t)m0 * D_, D_, g_Wh + (size_t)n0 * D_, D_,
                   D_ / 64, sb, tid, c);
#pragma unroll
        for (int mi = 0; mi < 4; mi++) {
            const int r0 = m0 + wm * 64 + mi * 16 + (lane >> 2);
#pragma unroll
            for (int ni = 0; ni < 8; ni++) {
                const int gc = n0 + wn * 64 + ni * 8 + (lane & 3) * 2;
                const float* cc = c[mi][ni];
#pragma unroll
                for (int h = 0; h < 2; h++) {
                    const size_t idx = (size_t)(r0 + 8 * h) * D_ + gc;
                    *(__half2*)(g_Vh + idx) = __floats2half2_rn(cc[2 * h], cc[2 * h + 1]);
                }
            }
        }
    }
}

__global__ __launch_bounds__(128, 2) void k_scores(float* __restrict__ Aout) {
    if (blockIdx.x > blockIdx.y) return;   // strictly above diagonal
    extern __shared__ __align__(1024) char smem[];
    const uint32_t sb = smem_u32(smem);
    const int tid = threadIdx.x;
    const int b = blockIdx.z;
    const int m0 = blockIdx.y * 128, n0 = blockIdx.x * 128;
    const size_t xb = (size_t)b * S_ * D_;
    float c[4][8][4] = {};
    gemm_hilo(g_Qhi + xb + (size_t)m0 * D_, g_Qlo + xb + (size_t)m0 * D_, D_,
              g_Xhi + xb + (size_t)n0 * D_, g_Xlo + xb + (size_t)n0 * D_, D_,
              D_ / 32, sb, tid, c);
    const int lane = tid & 31, wid = tid >> 5;
    const int wm = wid >> 1, wn = wid & 1;
    float* Ab = Aout + (size_t)b * S_ * S_;
#pragma unroll
    for (int mi = 0; mi < 4; mi++) {
        const int r0 = m0 + wm * 64 + mi * 16 + (lane >> 2);
#pragma unroll
        for (int ni = 0; ni < 8; ni++) {
            const int gc = n0 + wn * 64 + ni * 8 + (lane & 3) * 2;
            const float* cc = c[mi][ni];
#pragma unroll
            for (int h = 0; h < 2; h++) {
                float2 v = make_float2(cc[2 * h] * 32.0f, cc[2 * h + 1] * 32.0f);
                *(float2*)(Ab + (size_t)(r0 + 8 * h) * S_ + gc) = v;
            }
        }
    }
}

// ---------------------------------------------------------------------------
// Softmax (causal, in place) + fp16 A emission. Vectorized float4.
// 256 threads, 2 float4s per thread (2048 cols).
// ---------------------------------------------------------------------------
__global__ void k_softmax(float* __restrict__ A) {
    const int s = blockIdx.x, b = blockIdx.y;
    const size_t rb = ((size_t)b * S_ + s) * S_;
    float4* row = (float4*)(A + rb);
    const int len = s + 1;
    const int tid = threadIdx.x;
    const int lane = tid & 31, warp = tid >> 5;
    __shared__ float red[8];

    float4 v[2];
    float m = -1e30f;
#pragma unroll
    for (int it = 0; it < 2; it++) {
        const int j4 = tid + it * 256;          // float4 index
        const int j = j4 * 4;
        float4 t = row[j4];
        t.x = (j + 0 < len) ? t.x : -1e30f;
        t.y = (j + 1 < len) ? t.y : -1e30f;
        t.z = (j + 2 < len) ? t.z : -1e30f;
        t.w = (j + 3 < len) ? t.w : -1e30f;
        v[it] = t;
        m = fmaxf(m, fmaxf(fmaxf(t.x, t.y), fmaxf(t.z, t.w)));
    }
#pragma unroll
    for (int o = 16; o > 0; o >>= 1)
        m = fmaxf(m, __shfl_xor_sync(0xffffffffu, m, o));
    if (lane == 0) red[warp] = m;
    __syncthreads();
    m = red[lane & 7];
#pragma unroll
    for (int o = 4; o > 0; o >>= 1)
        m = fmaxf(m, __shfl_xor_sync(0xffffffffu, m, o));

    float sum = 0.0f;
#pragma unroll
    for (int it = 0; it < 2; it++) {
        float4 t = v[it];
        t.x = __expf(t.x - m); t.y = __expf(t.y - m);
        t.z = __expf(t.z - m); t.w = __expf(t.w - m);
        v[it] = t;
        sum += (t.x + t.y) + (t.z + t.w);
    }
#pragma unroll
    for (int o = 16; o > 0; o >>= 1)
        sum += __shfl_xor_sync(0xffffffffu, sum, o);
    if (lane == 0) red[warp] = sum;
    __syncthreads();
    sum = red[lane & 7];
#pragma unroll
    for (int o = 4; o > 0; o >>= 1)
        sum += __shfl_xor_sync(0xffffffffu, sum, o);
    const float inv = 1.0f / sum;

    __half* Ah = g_Ah + rb;
#pragma unroll
    for (int it = 0; it < 2; it++) {
        const int j4 = tid + it * 256;
        float4 t = v[it];
        t.x *= inv; t.y *= inv; t.z *= inv; t.w *= inv;
        row[j4] = t;
        __half2 p0 = __floats2half2_rn(t.x, t.y);
        __half2 p1 = __floats2half2_rn(t.z, t.w);
        uint2 pp; pp.x = *(uint32_t*)&p0; pp.y = *(uint32_t*)&p1;
        *(uint2*)(Ah + (size_t)j4 * 4) = pp;
    }
}

// ---------------------------------------------------------------------------
// GEMM3: Y = A@V (fp16, causal K-truncation, BK=64), out = X + Y
// ---------------------------------------------------------------------------
__global__ __launch_bounds__(128, 2) void k_av(const float* __restrict__ X,
                                               float* __restrict__ Yout) {
    extern __shared__ __align__(1024) char smem[];
    const uint32_t sb = smem_u32(smem);
    const int tid = threadIdx.x;
    const int b = blockIdx.z;
    const int m0 = blockIdx.y * 128, n0 = blockIdx.x * 128;
    float c[4][8][4] = {};
    gemm_f16t(g_Ah + (size_t)b * S_ * S_ + (size_t)m0 * S_, S_,
              g_Vh + (size_t)b * S_ * D_ + n0, D_,
              (blockIdx.y + 1) * 2, sb, tid, c);
    const int lane = tid & 31, wid = tid >> 5;
    const int wm = wid >> 1, wn = wid & 1;
#pragma unroll
    for (int mi = 0; mi < 4; mi++) {
        const int r0 = m0 + wm * 64 + mi * 16 + (lane >> 2);
#pragma unroll
        for (int ni = 0; ni < 8; ni++) {
            const int gc = n0 + wn * 64 + ni * 8 + (lane & 3) * 2;
            const float* cc = c[mi][ni];
#pragma unroll
            for (int h = 0; h < 2; h++) {
                const size_t idx = ((size_t)b * S_ + (r0 + 8 * h)) * D_ + gc;
                float2 x2 = *(const float2*)(X + idx);
                float2 o = make_float2(cc[2 * h] + x2.x, cc[2 * h + 1] + x2.y);
                *(float2*)(Yout + idx) = o;
            }
        }
    }
}

// ---------------------------------------------------------------------------
extern "C" void kernel_launch(void* const* d_in, const int* in_sizes, int n_in,
                              void* d_out, int out_size) {
    const float* X   = (const float*)d_in[0];
    const float* WQK = (const float*)d_in[2];
    const float* WOV = (const float*)d_in[3];
    float* out = (float*)d_out;

    const size_t nY = (size_t)M1 * D_;
    const size_t nA = (size_t)B_ * S_ * S_;
    float* Aout;
    if ((size_t)out_size >= nY + nA) {
        Aout = out + nY;
    } else {
        void* p = nullptr;
        cudaGetSymbolAddress(&p, g_Afallback);
        Aout = (float*)p;
    }

    static bool attrs_set = false;
    if (!attrs_set) {
        cudaFuncSetAttribute(k_qv,     cudaFuncAttributeMaxDynamicSharedMemorySize, SMEM_HILO);
        cudaFuncSetAttribute(k_scores, cudaFuncAttributeMaxDynamicSharedMemorySize, SMEM_HILO);
        cudaFuncSetAttribute(k_av,     cudaFuncAttributeMaxDynamicSharedMemorySize, SMEM_AV);
        attrs_set = true;
    }

    // 1) conversions (vectorized)
    k_cvtX<<<512, 256>>>((const float4*)X, M1 * D_ / 4);
    k_cvtW<<<256, 256>>>((const float4*)WQK, (const float4*)WOV, D_ * D_ / 4);
    // 2) Q (hilo bf16 3-pass) + V (fp16, BK=64) merged
    k_qv<<<dim3(D_ / 128, M1 / 128, 2), 128, SMEM_HILO>>>();
    // 3) causal scaled scores -> A region (fp32)
    k_scores<<<dim3(S_ / 128, S_ / 128, B_), 128, SMEM_HILO>>>(Aout);
    // 4) softmax in place + A fp16 (vectorized)
    k_softmax<<<dim3(S_, B_), 256>>>(Aout);
    // 5) Y = A@V + X (BK=64)
    k_av<<<dim3(D_ / 128, S_ / 128, B_), 128, SMEM_AV>>>(X, out);
}

// round 11
// speedup vs baseline: 5.3908x; 1.4775x over previous
#include <cuda_runtime.h>
#include <cuda_bf16.h>
#include <cuda_fp16.h>
#include <cstdint>

#define B_  4
#define S_  2048
#define D_  1024
#define M1  (B_ * S_)
#define NCAND 32
#define CWIN  40.0f

typedef __nv_bfloat16 bf16;

// ---------------------------------------------------------------------------
// Scratch (__device__ globals; no allocation allowed)
// ---------------------------------------------------------------------------
__device__ __align__(256) bf16   g_Xhi[(size_t)M1 * D_];
__device__ __align__(256) bf16   g_Xlo[(size_t)M1 * D_];
__device__ __align__(256) __half g_Xh [(size_t)M1 * D_];
__device__ __align__(256) bf16   g_Whi[(size_t)D_ * D_];
__device__ __align__(256) bf16   g_Wlo[(size_t)D_ * D_];
__device__ __align__(256) __half g_Wh [(size_t)D_ * D_];
__device__ __align__(256) bf16   g_Qb [(size_t)M1 * D_];   // Q rounded to bf16
__device__ __align__(256) float  g_Qf [(size_t)M1 * D_];   // Q fp32 (for exact fix)
__device__ __align__(256) __half g_Vh [(size_t)M1 * D_];   // V fp16 [m][d]
__device__ int  g_cnt [(size_t)B_ * S_];
__device__ int  g_cand[(size_t)B_ * S_ * NCAND];
__device__ float g_Afallback[(size_t)B_ * S_ * S_];

// ---------------------------------------------------------------------------
// Baseline-PTX primitives
// ---------------------------------------------------------------------------
__device__ __forceinline__ uint32_t smem_u32(const void* p) {
    uint32_t a;
    asm("{ .reg .u64 t; cvta.to.shared.u64 t, %1; cvt.u32.u64 %0, t; }" : "=r"(a) : "l"(p));
    return a;
}
#define CPA(dst, src)  asm volatile("cp.async.cg.shared.global [%0], [%1], 16;\n" :: "r"(dst), "l"(src))
#define CP_COMMIT()    asm volatile("cp.async.commit_group;\n" ::: "memory")
#define CP_WAIT1()     asm volatile("cp.async.wait_group 1;\n" ::: "memory")
#define CP_WAIT0()     asm volatile("cp.async.wait_group 0;\n" ::: "memory")

__device__ __forceinline__ void ldsm4(uint32_t r[4], uint32_t a) {
    asm volatile("ldmatrix.sync.aligned.m8n8.x4.shared.b16 {%0,%1,%2,%3}, [%4];\n"
                 : "=r"(r[0]), "=r"(r[1]), "=r"(r[2]), "=r"(r[3]) : "r"(a));
}
__device__ __forceinline__ void mma_bf16(float* c, const uint32_t a[4], uint32_t b0, uint32_t b1) {
    asm volatile("mma.sync.aligned.m16n8k16.row.col.f32.bf16.bf16.f32 "
                 "{%0,%1,%2,%3}, {%4,%5,%6,%7}, {%8,%9}, {%0,%1,%2,%3};\n"
                 : "+f"(c[0]), "+f"(c[1]), "+f"(c[2]), "+f"(c[3])
                 : "r"(a[0]), "r"(a[1]), "r"(a[2]), "r"(a[3]), "r"(b0), "r"(b1));
}
__device__ __forceinline__ void mma_f16(float* c, const uint32_t a[4], uint32_t b0, uint32_t b1) {
    asm volatile("mma.sync.aligned.m16n8k16.row.col.f32.f16.f16.f32 "
                 "{%0,%1,%2,%3}, {%4,%5,%6,%7}, {%8,%9}, {%0,%1,%2,%3};\n"
                 : "+f"(c[0]), "+f"(c[1]), "+f"(c[2]), "+f"(c[3])
                 : "r"(a[0]), "r"(a[1]), "r"(a[2]), "r"(a[3]), "r"(b0), "r"(b1));
}
__device__ __forceinline__ void split_bf16(float v, bf16& h, bf16& l) {
    h = __float2bfloat16_rn(v);
    l = __float2bfloat16_rn(v - __bfloat162float(h));
}

// ---------------------------------------------------------------------------
// Tile loaders: 128 threads. K-major [128 rows][32 elems], smem rows 80B.
// ---------------------------------------------------------------------------
__device__ __forceinline__ void cpa_k(uint32_t sdst, const void* g, int ldbytes, int tid) {
#pragma unroll
    for (int i = 0; i < 4; i++) {
        int u = tid + i * 128;
        int r = u >> 2, c = u & 3;
        CPA(sdst + r * 80 + c * 16, (const char*)g + (size_t)r * ldbytes + c * 16);
    }
}
__device__ __forceinline__ void ld4frag(uint32_t base, uint32_t r[4][4]) {
#pragma unroll
    for (int i = 0; i < 4; i++) ldsm4(r[i], base + i * 1280);
}
__device__ __forceinline__ void ldF64(uint32_t r[4][4], uint32_t base, int w, int lane, int ks) {
    const int row = lane & 15;
    const int ch  = (lane >> 4) + ks * 2;
    ld4frag(base + (w * 64 + row) * 80 + ch * 16, r);
}
__device__ __forceinline__ void mmas_bf16(float c[4][8][4], uint32_t a[4][4], uint32_t b[4][4]) {
#pragma unroll
    for (int mi = 0; mi < 4; mi++)
#pragma unroll
        for (int nj = 0; nj < 4; nj++) {
            mma_bf16(c[mi][2 * nj],     a[mi], b[nj][0], b[nj][2]);
            mma_bf16(c[mi][2 * nj + 1], a[mi], b[nj][1], b[nj][3]);
        }
}
__device__ __forceinline__ void mmas_f16(float c[4][8][4], uint32_t a[4][4], uint32_t b[4][4]) {
#pragma unroll
    for (int mi = 0; mi < 4; mi++)
#pragma unroll
        for (int nj = 0; nj < 4; nj++) {
            mma_f16(c[mi][2 * nj],     a[mi], b[nj][0], b[nj][2]);
            mma_f16(c[mi][2 * nj + 1], a[mi], b[nj][1], b[nj][3]);
        }
}

#define PIPE2_BOTTOM(LOADI, it, nit, STGB)                        \
    do {                                                          \
        if ((it) + 1 < (nit)) {                                   \
            __syncthreads();                                      \
            const bool more = ((it) + 2 < (nit));                 \
            if (more) { LOADI(sb + ((it) & 1) * (STGB), (it) + 2); } \
            if (more) { CP_WAIT1(); } else { CP_WAIT0(); }        \
            __syncthreads();                                      \
        }                                                         \
    } while (0)

// ---------------------------------------------------------------------------
// hi/lo 3-pass GEMM: CTA 128x128, 4 warps (2m x 2n), warp 64x64, BK=32
// ---------------------------------------------------------------------------
#define HL_ALO 10240
#define HL_BHI 20480
#define HL_BLO 30720
#define HL_STG 40960
#define SMEM_HILO (2 * HL_STG)

#define HL_LOADI(saddr, itn)                                      \
    do {                                                          \
        const int ko_ = (itn) * 32;                               \
        cpa_k((saddr),           Ah + ko_, la, tid);              \
        cpa_k((saddr) + HL_ALO,  Al + ko_, la, tid);              \
        cpa_k((saddr) + HL_BHI,  Bh + ko_, lb, tid);              \
        cpa_k((saddr) + HL_BLO,  Bl + ko_, lb, tid);              \
        CP_COMMIT();                                              \
    } while (0)

__device__ __forceinline__ void kstep_hilo(uint32_t stg, int ks, int lane,
                                           int wm, int wn, float c[4][8][4]) {
    uint32_t ah[4][4], bh[4][4], t[4][4];
    ldF64(ah, stg, wm, lane, ks);
    ldF64(bh, stg + HL_BHI, wn, lane, ks);
    mmas_bf16(c, ah, bh);
    ldF64(t, stg + HL_BLO, wn, lane, ks);
    mmas_bf16(c, ah, t);
    ldF64(t, stg + HL_ALO, wm, lane, ks);
    mmas_bf16(c, t, bh);
}

__device__ __forceinline__ void gemm_hilo(const bf16* Ah, const bf16* Al, int lda,
                                          const bf16* Bh, const bf16* Bl, int ldb,
                                          int nit, uint32_t sb, int tid, float c[4][8][4]) {
    const int lane = tid & 31, wid = tid >> 5;
    const int wm = wid >> 1, wn = wid & 1;
    const int la = lda * 2, lb = ldb * 2;
    HL_LOADI(sb, 0);
    if (nit > 1) { HL_LOADI(sb + HL_STG, 1); CP_WAIT1(); }
    else         { CP_WAIT0(); }
    __syncthreads();
    for (int it = 0; it < nit; it++) {
        const uint32_t stg = sb + (it & 1) * HL_STG;
        kstep_hilo(stg, 0, lane, wm, wn, c);
        kstep_hilo(stg, 1, lane, wm, wn, c);
        PIPE2_BOTTOM(HL_LOADI, it, nit, HL_STG);
    }
}

// ---------------------------------------------------------------------------
// single-pass GEMM (B K-major): CTA 128x128, BK=64. fp16 or bf16 via flag.
// ---------------------------------------------------------------------------
#define NT_STG  40960
#define SMEM_NT (2 * NT_STG)

#define NT_LOADI(saddr, itn)                                      \
    do {                                                          \
        const int ko_ = (itn) * 64;                               \
        cpa_k((saddr),          Ap + ko_,      la, tid);          \
        cpa_k((saddr) + 10240,  Ap + ko_ + 32, la, tid);          \
        cpa_k((saddr) + 20480,  Bp + ko_,      lb, tid);          \
        cpa_k((saddr) + 30720,  Bp + ko_ + 32, lb, tid);          \
        CP_COMMIT();                                              \
    } while (0)

template<bool BF>
__device__ __forceinline__ void gemm_1p(const void* A_, int lda, const void* B_v, int ldb,
                                        int nit, uint32_t sb, int tid, float c[4][8][4]) {
    const int lane = tid & 31, wid = tid >> 5;
    const int wm = wid >> 1, wn = wid & 1;
    const int la = lda * 2, lb = ldb * 2;
    const char* Ap = (const char*)A_;   // element = 2B; offsets below in elems*2
    const char* Bp = (const char*)B_v;
#undef NT_LOADI
#define NT_LOADI(saddr, itn)                                      \
    do {                                                          \
        const int ko_ = (itn) * 64 * 2;                           \
        cpa_k((saddr),          Ap + ko_,      la, tid);          \
        cpa_k((saddr) + 10240,  Ap + ko_ + 64, la, tid);          \
        cpa_k((saddr) + 20480,  Bp + ko_,      lb, tid);          \
        cpa_k((saddr) + 30720,  Bp + ko_ + 64, lb, tid);          \
        CP_COMMIT();                                              \
    } while (0)
    NT_LOADI(sb, 0);
    if (nit > 1) { NT_LOADI(sb + NT_STG, 1); CP_WAIT1(); }
    else         { CP_WAIT0(); }
    __syncthreads();
    for (int it = 0; it < nit; it++) {
        const uint32_t stg = sb + (it & 1) * NT_STG;
#pragma unroll
        for (int k4 = 0; k4 < 4; k4++) {
            const int sub = k4 >> 1, ks = k4 & 1;
            uint32_t ah[4][4], bh[4][4];
            ldF64(ah, stg + sub * 10240, wm, lane, ks);
            ldF64(bh, stg + 20480 + sub * 10240, wn, lane, ks);
            if (BF) mmas_bf16(c, ah, bh);
            else    mmas_f16 (c, ah, bh);
        }
        PIPE2_BOTTOM(NT_LOADI, it, nit, NT_STG);
    }
}

// ---------------------------------------------------------------------------
// Conversions (vectorized float4)
// ---------------------------------------------------------------------------
__global__ void k_cvtX(const float4* __restrict__ x, int n4) {
    int i = blockIdx.x * 256 + threadIdx.x;
    const int stride = gridDim.x * 256;
    for (; i < n4; i += stride) {
        float4 v = x[i];
        bf16 h0, l0, h1, l1, h2, l2, h3, l3;
        split_bf16(v.x, h0, l0); split_bf16(v.y, h1, l1);
        split_bf16(v.z, h2, l2); split_bf16(v.w, h3, l3);
        uint2 hh, ll;
        hh.x = ((uint32_t)*(uint16_t*)&h1 << 16) | *(uint16_t*)&h0;
        hh.y = ((uint32_t)*(uint16_t*)&h3 << 16) | *(uint16_t*)&h2;
        ll.x = ((uint32_t)*(uint16_t*)&l1 << 16) | *(uint16_t*)&l0;
        ll.y = ((uint32_t)*(uint16_t*)&l3 << 16) | *(uint16_t*)&l2;
        *(uint2*)(g_Xhi + (size_t)i * 4) = hh;
        *(uint2*)(g_Xlo + (size_t)i * 4) = ll;
        __half2 f01 = __floats2half2_rn(v.x, v.y);
        __half2 f23 = __floats2half2_rn(v.z, v.w);
        uint2 ff; ff.x = *(uint32_t*)&f01; ff.y = *(uint32_t*)&f23;
        *(uint2*)(g_Xh + (size_t)i * 4) = ff;
    }
}
__global__ void k_cvtW(const float4* __restrict__ wqk, const float4* __restrict__ wov, int n4) {
    int i = blockIdx.x * 256 + threadIdx.x;
    const int stride = gridDim.x * 256;
    for (; i < n4; i += stride) {
        float4 v = wqk[i];
        bf16 h0, l0, h1, l1, h2, l2, h3, l3;
        split_bf16(v.x, h0, l0); split_bf16(v.y, h1, l1);
        split_bf16(v.z, h2, l2); split_bf16(v.w, h3, l3);
        uint2 hh, ll;
        hh.x = ((uint32_t)*(uint16_t*)&h1 << 16) | *(uint16_t*)&h0;
        hh.y = ((uint32_t)*(uint16_t*)&h3 << 16) | *(uint16_t*)&h2;
        ll.x = ((uint32_t)*(uint16_t*)&l1 << 16) | *(uint16_t*)&l0;
        ll.y = ((uint32_t)*(uint16_t*)&l3 << 16) | *(uint16_t*)&l2;
        *(uint2*)(g_Whi + (size_t)i * 4) = hh;
        *(uint2*)(g_Wlo + (size_t)i * 4) = ll;
        float4 w = wov[i];
        __half2 f01 = __floats2half2_rn(w.x, w.y);
        __half2 f23 = __floats2half2_rn(w.z, w.w);
        uint2 ff; ff.x = *(uint32_t*)&f01; ff.y = *(uint32_t*)&f23;
        *(uint2*)(g_Wh + (size_t)i * 4) = ff;
    }
}

// ---------------------------------------------------------------------------
// Merged Q+V kernel (z=0: Q hilo 3-pass -> Qb bf16 + Qf fp32; z=1: V fp16)
// ---------------------------------------------------------------------------
__global__ __launch_bounds__(128, 2) void k_qv() {
    extern __shared__ __align__(1024) char smem[];
    const uint32_t sb = smem_u32(smem);
    const int tid = threadIdx.x;
    const int m0 = blockIdx.y * 128, n0 = blockIdx.x * 128;
    const int lane = tid & 31, wid = tid >> 5;
    const int wm = wid >> 1, wn = wid & 1;
    float c[4][8][4] = {};

    if (blockIdx.z == 0) {
        gemm_hilo(g_Xhi + (size_t)m0 * D_, g_Xlo + (size_t)m0 * D_, D_,
                  g_Whi + (size_t)n0 * D_, g_Wlo + (size_t)n0 * D_, D_,
                  D_ / 32, sb, tid, c);
#pragma unroll
        for (int mi = 0; mi < 4; mi++) {
            const int r0 = m0 + wm * 64 + mi * 16 + (lane >> 2);
#pragma unroll
            for (int ni = 0; ni < 8; ni++) {
                const int gc = n0 + wn * 64 + ni * 8 + (lane & 3) * 2;
                const float* cc = c[mi][ni];
#pragma unroll
                for (int h = 0; h < 2; h++) {
                    const size_t idx = (size_t)(r0 + 8 * h) * D_ + gc;
                    __nv_bfloat162 qq;
                    qq.x = __float2bfloat16_rn(cc[2 * h]);
                    qq.y = __float2bfloat16_rn(cc[2 * h + 1]);
                    *(__nv_bfloat162*)(g_Qb + idx) = qq;
                    *(float2*)(g_Qf + idx) = make_float2(cc[2 * h], cc[2 * h + 1]);
                }
            }
        }
    } else {
        gemm_1p<false>(g_Xh + (size_t)m0 * D_, D_, g_Wh + (size_t)n0 * D_, D_,
                       D_ / 64, sb, tid, c);
#pragma unroll
        for (int mi = 0; mi < 4; mi++) {
            const int r0 = m0 + wm * 64 + mi * 16 + (lane >> 2);
#pragma unroll
            for (int ni = 0; ni < 8; ni++) {
                const int gc = n0 + wn * 64 + ni * 8 + (lane & 3) * 2;
                const float* cc = c[mi][ni];
#pragma unroll
                for (int h = 0; h < 2; h++) {
                    const size_t idx = (size_t)(r0 + 8 * h) * D_ + gc;
                    *(__half2*)(g_Vh + idx) = __floats2half2_rn(cc[2 * h], cc[2 * h + 1]);
                }
            }
        }
    }
}

// ---------------------------------------------------------------------------
// Scores: 1-pass bf16 (Qb * Xhi^T), scaled x32, causal block skip.
// ---------------------------------------------------------------------------
__global__ __launch_bounds__(128, 2) void k_scores(float* __restrict__ Aout) {
    if (blockIdx.x > blockIdx.y) return;
    extern __shared__ __align__(1024) char smem[];
    const uint32_t sb = smem_u32(smem);
    const int tid = threadIdx.x;
    const int b = blockIdx.z;
    const int m0 = blockIdx.y * 128, n0 = blockIdx.x * 128;
    const size_t xb = (size_t)b * S_ * D_;
    float c[4][8][4] = {};
    gemm_1p<true>(g_Qb + xb + (size_t)m0 * D_, D_,
                  g_Xhi + xb + (size_t)n0 * D_, D_,
                  D_ / 64, sb, tid, c);
    const int lane = tid & 31, wid = tid >> 5;
    const int wm = wid >> 1, wn = wid & 1;
    float* Ab = Aout + (size_t)b * S_ * S_;
#pragma unroll
    for (int mi = 0; mi < 4; mi++) {
        const int r0 = m0 + wm * 64 + mi * 16 + (lane >> 2);
#pragma unroll
        for (int ni = 0; ni < 8; ni++) {
            const int gc = n0 + wn * 64 + ni * 8 + (lane & 3) * 2;
            const float* cc = c[mi][ni];
#pragma unroll
            for (int h = 0; h < 2; h++) {
                float2 v = make_float2(cc[2 * h] * 32.0f, cc[2 * h + 1] * 32.0f);
                *(float2*)(Ab + (size_t)(r0 + 8 * h) * S_ + gc) = v;
            }
        }
    }
}

// ---------------------------------------------------------------------------
// Pass B: candidate finder. Per row: max, collect {j: l_j > max-CWIN}, zero row.
// ---------------------------------------------------------------------------
__global__ void k_softmax(float* __restrict__ A) {
    const int s = blockIdx.x, b = blockIdx.y;
    const int rowi = b * S_ + s;
    const size_t rb = (size_t)rowi * S_;
    float4* row = (float4*)(A + rb);
    const int len = s + 1;
    const int tid = threadIdx.x;
    const int lane = tid & 31, warp = tid >> 5;
    __shared__ float red[8];
    __shared__ int scnt;
    if (tid == 0) scnt = 0;

    float4 v[2];
    float m = -3.0e38f;
#pragma unroll
    for (int it = 0; it < 2; it++) {
        const int j4 = tid + it * 256;
        const int j = j4 * 4;
        float4 t = row[j4];
        t.x = (j + 0 < len) ? t.x : -3.0e38f;
        t.y = (j + 1 < len) ? t.y : -3.0e38f;
        t.z = (j + 2 < len) ? t.z : -3.0e38f;
        t.w = (j + 3 < len) ? t.w : -3.0e38f;
        v[it] = t;
        m = fmaxf(m, fmaxf(fmaxf(t.x, t.y), fmaxf(t.z, t.w)));
    }
#pragma unroll
    for (int o = 16; o > 0; o >>= 1)
        m = fmaxf(m, __shfl_xor_sync(0xffffffffu, m, o));
    if (lane == 0) red[warp] = m;
    __syncthreads();
    m = red[lane & 7];
#pragma unroll
    for (int o = 4; o > 0; o >>= 1)
        m = fmaxf(m, __shfl_xor_sync(0xffffffffu, m, o));

    const float thr = m - CWIN;
    int* crow = g_cand + (size_t)rowi * NCAND;
#pragma unroll
    for (int it = 0; it < 2; it++) {
        const int j = (tid + it * 256) * 4;
        const float* t = (const float*)&v[it];
#pragma unroll
        for (int e = 0; e < 4; e++) {
            if (t[e] > thr) {
                int slot = atomicAdd(&scnt, 1);
                if (slot < NCAND) crow[slot] = j + e;
            }
        }
    }
    __syncthreads();
    // zero the full row (2048 cols)
    float4 z4 = make_float4(0.f, 0.f, 0.f, 0.f);
    row[tid] = z4;
    row[tid + 256] = z4;
    if (tid == 0) g_cnt[rowi] = (scnt <= NCAND) ? scnt : 255;
}

// ---------------------------------------------------------------------------
// Pass C: exact softmax for flagged rows (fp32 dots of Qf[s] . X[t]).
// ---------------------------------------------------------------------------
__global__ void k_exact(const float* __restrict__ X, float* __restrict__ Aout) {
    const int s = blockIdx.x, b = blockIdx.y;
    const int rowi = b * S_ + s;
    const int cnt = g_cnt[rowi];
    float* Arow = Aout + (size_t)rowi * S_;
    const int tid = threadIdx.x, lane = tid & 31, warp = tid >> 5;
    const int* crow = g_cand + (size_t)rowi * NCAND;

    if (cnt <= 1) {
        if (cnt == 1 && tid == 0) Arow[crow[0]] = 1.0f;
        return;
    }

    __shared__ float qrow[D_];
    __shared__ float lg[NCAND];
    __shared__ float red[8];
    ((float4*)qrow)[tid] = ((const float4*)(g_Qf + (size_t)rowi * D_))[tid];
    __syncthreads();
    const float* Xb = X + (size_t)b * S_ * D_;

    if (cnt != 255) {
        for (int ci = warp; ci < cnt; ci += 8) {
            const float* xr = Xb + (size_t)crow[ci] * D_;
            float d = 0.f;
            for (int k = lane; k < D_; k += 32) d += qrow[k] * xr[k];
#pragma unroll
            for (int o = 16; o > 0; o >>= 1) d += __shfl_xor_sync(0xffffffffu, d, o);
            if (lane == 0) lg[ci] = d * 32.0f;
        }
        __syncthreads();
        if (tid == 0) {
            float mm = -3.0e38f;
            for (int ci = 0; ci < cnt; ci++) mm = fmaxf(mm, lg[ci]);
            float Z = 0.f;
            for (int ci = 0; ci < cnt; ci++) Z += expf(lg[ci] - mm);
            const float inv = 1.0f / Z;
            for (int ci = 0; ci < cnt; ci++) Arow[crow[ci]] = expf(lg[ci] - mm) * inv;
        }
    } else {
        // fallback: exact logits for all t <= s (stored temporarily in Arow)
        const int len = s + 1;
        for (int t = warp; t < len; t += 8) {
            const float* xr = Xb + (size_t)t * D_;
            float d = 0.f;
            for (int k = lane; k < D_; k += 32) d += qrow[k] * xr[k];
#pragma unroll
            for (int o = 16; o > 0; o >>= 1) d += __shfl_xor_sync(0xffffffffu, d, o);
            if (lane == 0) Arow[t] = d * 32.0f;
        }
        __syncthreads();
        float mm = -3.0e38f;
        for (int j = tid; j < len; j += 256) mm = fmaxf(mm, Arow[j]);
#pragma unroll
        for (int o = 16; o > 0; o >>= 1) mm = fmaxf(mm, __shfl_xor_sync(0xffffffffu, mm, o));
        if (lane == 0) red[warp] = mm;
        __syncthreads();
        mm = red[lane & 7];
#pragma unroll
        for (int o = 4; o > 0; o >>= 1) mm = fmaxf(mm, __shfl_xor_sync(0xffffffffu, mm, o));
        float Z = 0.f;
        for (int j = tid; j < len; j += 256) Z += expf(Arow[j] - mm);
#pragma unroll
        for (int o = 16; o > 0; o >>= 1) Z += __shfl_xor_sync(0xffffffffu, Z, o);
        if (lane == 0) red[warp] = Z;
        __syncthreads();
        Z = red[lane & 7];
#pragma unroll
        for (int o = 4; o > 0; o >>= 1) Z += __shfl_xor_sync(0xffffffffu, Z, o);
        const float inv = 1.0f / Z;
        __syncthreads();
        for (int j = tid; j < len; j += 256) Arow[j] = expf(Arow[j] - mm) * inv;
    }
}

// ---------------------------------------------------------------------------
// Pass D: out = X + A.V via sparse gather over candidates.
// ---------------------------------------------------------------------------
__global__ void k_out(const float* __restrict__ X, float* __restrict__ Yout,
                      const float* __restrict__ Aout) {
    const int s = blockIdx.x, b = blockIdx.y;
    const int rowi = b * S_ + s;
    const int cnt = g_cnt[rowi];
    const int tid = threadIdx.x;
    const size_t xoff = (size_t)rowi * D_;
    const float* Arow = Aout + (size_t)rowi * S_;
    const int* crow = g_cand + (size_t)rowi * NCAND;

    float4 x4 = ((const float4*)(X + xoff))[tid];
    float y0 = 0.f, y1 = 0.f, y2 = 0.f, y3 = 0.f;

    if (cnt != 255) {
        for (int ci = 0; ci < cnt; ci++) {
            const int t = crow[ci];
            const float a = Arow[t];
            const __half2* vr = (const __half2*)(g_Vh + ((size_t)b * S_ + t) * D_) + tid * 2;
            float2 p0 = __half22float2(vr[0]);
            float2 p1 = __half22float2(vr[1]);
            y0 += a * p0.x; y1 += a * p0.y; y2 += a * p1.x; y3 += a * p1.y;
        }
    } else {
        const int len = s + 1;
        for (int t = 0; t < len; t++) {
            const float a = Arow[t];
            if (a > 1e-30f) {
                const __half2* vr = (const __half2*)(g_Vh + ((size_t)b * S_ + t) * D_) + tid * 2;
                float2 p0 = __half22float2(vr[0]);
                float2 p1 = __half22float2(vr[1]);
                y0 += a * p0.x; y1 += a * p0.y; y2 += a * p1.x; y3 += a * p1.y;
            }
        }
    }
    float4 o = make_float4(x4.x + y0, x4.y + y1, x4.z + y2, x4.w + y3);
    ((float4*)(Yout + xoff))[tid] = o;
}

// ---------------------------------------------------------------------------
extern "C" void kernel_launch(void* const* d_in, const int* in_sizes, int n_in,
                              void* d_out, int out_size) {
    const float* X   = (const float*)d_in[0];
    const float* WQK = (const float*)d_in[2];
    const float* WOV = (const float*)d_in[3];
    float* out = (float*)d_out;

    const size_t nY = (size_t)M1 * D_;
    const size_t nA = (size_t)B_ * S_ * S_;
    float* Aout;
    if ((size_t)out_size >= nY + nA) {
        Aout = out + nY;
    } else {
        void* p = nullptr;
        cudaGetSymbolAddress(&p, g_Afallback);
        Aout = (float*)p;
    }

    static bool attrs_set = false;
    if (!attrs_set) {
        cudaFuncSetAttribute(k_qv,     cudaFuncAttributeMaxDynamicSharedMemorySize, SMEM_HILO);
        cudaFuncSetAttribute(k_scores, cudaFuncAttributeMaxDynamicSharedMemorySize, SMEM_NT);
        attrs_set = true;
    }

    // 1) conversions
    k_cvtX<<<512, 256>>>((const float4*)X, M1 * D_ / 4);
    k_cvtW<<<256, 256>>>((const float4*)WQK, (const float4*)WOV, D_ * D_ / 4);
    // 2) Q (3-pass hilo -> Qb bf16 + Qf fp32) and V (fp16)
    k_qv<<<dim3(D_ / 128, M1 / 128, 2), 128, SMEM_HILO>>>();
    // 3) approx scores (1-pass bf16), causal
    k_scores<<<dim3(S_ / 128, S_ / 128, B_), 128, SMEM_NT>>>(Aout);
    // 4) candidate finder + zero A
    k_softmax<<<dim3(S_, B_), 256>>>(Aout);
    // 5) exact softmax on flagged rows
    k_exact<<<dim3(S_, B_), 256>>>(X, Aout);
    // 6) out = X + A.V (sparse gather)
    k_out<<<dim3(S_, B_), 256>>>(X, out, Aout);
}

// round 12
// speedup vs baseline: 6.0110x; 1.1151x over previous
#include <cuda_runtime.h>
#include <cuda_bf16.h>
#include <cuda_fp16.h>
#include <cstdint>

#define B_  4
#define S_  2048
#define D_  1024
#define M1  (B_ * S_)
#define NCAND 32
#define CWIN  46.0f

typedef __nv_bfloat16 bf16;

// ---------------------------------------------------------------------------
// Scratch (__device__ globals; no allocation allowed)
// ---------------------------------------------------------------------------
__device__ __align__(256) bf16   g_Xhi[(size_t)M1 * D_];
__device__ __align__(256) bf16   g_Xlo[(size_t)M1 * D_];
__device__ __align__(256) __half g_Xh [(size_t)M1 * D_];
__device__ __align__(256) bf16   g_Whi[(size_t)D_ * D_];
__device__ __align__(256) bf16   g_Wlo[(size_t)D_ * D_];
__device__ __align__(256) __half g_Wh [(size_t)D_ * D_];
__device__ __align__(256) bf16   g_Qb [(size_t)M1 * D_];   // Q 1-pass, bf16
__device__ __align__(256) __half g_Vh [(size_t)M1 * D_];   // V fp16 [m][d]
// compact exact-Q machinery (flagged rows only)
__device__ __align__(256) bf16   g_Xchi[(size_t)M1 * D_];
__device__ __align__(256) bf16   g_Xclo[(size_t)M1 * D_];
__device__ __align__(256) float  g_Qc  [(size_t)M1 * D_];
__device__ int  g_nfix;
__device__ int  g_fixrows[(size_t)B_ * S_];
__device__ int  g_slot   [(size_t)B_ * S_];
__device__ int  g_cnt [(size_t)B_ * S_];
__device__ int  g_cand[(size_t)B_ * S_ * NCAND];
__device__ float g_Afallback[(size_t)B_ * S_ * S_];

// ---------------------------------------------------------------------------
// Baseline-PTX primitives
// ---------------------------------------------------------------------------
__device__ __forceinline__ uint32_t smem_u32(const void* p) {
    uint32_t a;
    asm("{ .reg .u64 t; cvta.to.shared.u64 t, %1; cvt.u32.u64 %0, t; }" : "=r"(a) : "l"(p));
    return a;
}
#define CPA(dst, src)  asm volatile("cp.async.cg.shared.global [%0], [%1], 16;\n" :: "r"(dst), "l"(src))
#define CP_COMMIT()    asm volatile("cp.async.commit_group;\n" ::: "memory")
#define CP_WAIT1()     asm volatile("cp.async.wait_group 1;\n" ::: "memory")
#define CP_WAIT0()     asm volatile("cp.async.wait_group 0;\n" ::: "memory")

__device__ __forceinline__ void ldsm4(uint32_t r[4], uint32_t a) {
    asm volatile("ldmatrix.sync.aligned.m8n8.x4.shared.b16 {%0,%1,%2,%3}, [%4];\n"
                 : "=r"(r[0]), "=r"(r[1]), "=r"(r[2]), "=r"(r[3]) : "r"(a));
}
__device__ __forceinline__ void mma_bf16(float* c, const uint32_t a[4], uint32_t b0, uint32_t b1) {
    asm volatile("mma.sync.aligned.m16n8k16.row.col.f32.bf16.bf16.f32 "
                 "{%0,%1,%2,%3}, {%4,%5,%6,%7}, {%8,%9}, {%0,%1,%2,%3};\n"
                 : "+f"(c[0]), "+f"(c[1]), "+f"(c[2]), "+f"(c[3])
                 : "r"(a[0]), "r"(a[1]), "r"(a[2]), "r"(a[3]), "r"(b0), "r"(b1));
}
__device__ __forceinline__ void mma_f16(float* c, const uint32_t a[4], uint32_t b0, uint32_t b1) {
    asm volatile("mma.sync.aligned.m16n8k16.row.col.f32.f16.f16.f32 "
                 "{%0,%1,%2,%3}, {%4,%5,%6,%7}, {%8,%9}, {%0,%1,%2,%3};\n"
                 : "+f"(c[0]), "+f"(c[1]), "+f"(c[2]), "+f"(c[3])
                 : "r"(a[0]), "r"(a[1]), "r"(a[2]), "r"(a[3]), "r"(b0), "r"(b1));
}
__device__ __forceinline__ void split_bf16(float v, bf16& h, bf16& l) {
    h = __float2bfloat16_rn(v);
    l = __float2bfloat16_rn(v - __bfloat162float(h));
}

// ---------------------------------------------------------------------------
// Tile loaders: 128 threads. K-major [128 rows][32 elems], smem rows 80B.
// ---------------------------------------------------------------------------
__device__ __forceinline__ void cpa_k(uint32_t sdst, const void* g, int ldbytes, int tid) {
#pragma unroll
    for (int i = 0; i < 4; i++) {
        int u = tid + i * 128;
        int r = u >> 2, c = u & 3;
        CPA(sdst + r * 80 + c * 16, (const char*)g + (size_t)r * ldbytes + c * 16);
    }
}
__device__ __forceinline__ void ld4frag(uint32_t base, uint32_t r[4][4]) {
#pragma unroll
    for (int i = 0; i < 4; i++) ldsm4(r[i], base + i * 1280);
}
__device__ __forceinline__ void ldF64(uint32_t r[4][4], uint32_t base, int w, int lane, int ks) {
    const int row = lane & 15;
    const int ch  = (lane >> 4) + ks * 2;
    ld4frag(base + (w * 64 + row) * 80 + ch * 16, r);
}
__device__ __forceinline__ void mmas_bf16(float c[4][8][4], uint32_t a[4][4], uint32_t b[4][4]) {
#pragma unroll
    for (int mi = 0; mi < 4; mi++)
#pragma unroll
        for (int nj = 0; nj < 4; nj++) {
            mma_bf16(c[mi][2 * nj],     a[mi], b[nj][0], b[nj][2]);
            mma_bf16(c[mi][2 * nj + 1], a[mi], b[nj][1], b[nj][3]);
        }
}
__device__ __forceinline__ void mmas_f16(float c[4][8][4], uint32_t a[4][4], uint32_t b[4][4]) {
#pragma unroll
    for (int mi = 0; mi < 4; mi++)
#pragma unroll
        for (int nj = 0; nj < 4; nj++) {
            mma_f16(c[mi][2 * nj],     a[mi], b[nj][0], b[nj][2]);
            mma_f16(c[mi][2 * nj + 1], a[mi], b[nj][1], b[nj][3]);
        }
}

#define PIPE2_BOTTOM(LOADI, it, nit, STGB)                        \
    do {                                                          \
        if ((it) + 1 < (nit)) {                                   \
            __syncthreads();                                      \
            const bool more = ((it) + 2 < (nit));                 \
            if (more) { LOADI(sb + ((it) & 1) * (STGB), (it) + 2); } \
            if (more) { CP_WAIT1(); } else { CP_WAIT0(); }        \
            __syncthreads();                                      \
        }                                                         \
    } while (0)

// ---------------------------------------------------------------------------
// hi/lo 3-pass GEMM: CTA 128x128, 4 warps (2m x 2n), warp 64x64, BK=32
// ---------------------------------------------------------------------------
#define HL_ALO 10240
#define HL_BHI 20480
#define HL_BLO 30720
#define HL_STG 40960
#define SMEM_HILO (2 * HL_STG)

#define HL_LOADI(saddr, itn)                                      \
    do {                                                          \
        const int ko_ = (itn) * 32;                               \
        cpa_k((saddr),           Ah + ko_, la, tid);              \
        cpa_k((saddr) + HL_ALO,  Al + ko_, la, tid);              \
        cpa_k((saddr) + HL_BHI,  Bh + ko_, lb, tid);              \
        cpa_k((saddr) + HL_BLO,  Bl + ko_, lb, tid);              \
        CP_COMMIT();                                              \
    } while (0)

__device__ __forceinline__ void kstep_hilo(uint32_t stg, int ks, int lane,
                                           int wm, int wn, float c[4][8][4]) {
    uint32_t ah[4][4], bh[4][4], t[4][4];
    ldF64(ah, stg, wm, lane, ks);
    ldF64(bh, stg + HL_BHI, wn, lane, ks);
    mmas_bf16(c, ah, bh);
    ldF64(t, stg + HL_BLO, wn, lane, ks);
    mmas_bf16(c, ah, t);
    ldF64(t, stg + HL_ALO, wm, lane, ks);
    mmas_bf16(c, t, bh);
}

__device__ __forceinline__ void gemm_hilo(const bf16* Ah, const bf16* Al, int lda,
                                          const bf16* Bh, const bf16* Bl, int ldb,
                                          int nit, uint32_t sb, int tid, float c[4][8][4]) {
    const int lane = tid & 31, wid = tid >> 5;
    const int wm = wid >> 1, wn = wid & 1;
    const int la = lda * 2, lb = ldb * 2;
    HL_LOADI(sb, 0);
    if (nit > 1) { HL_LOADI(sb + HL_STG, 1); CP_WAIT1(); }
    else         { CP_WAIT0(); }
    __syncthreads();
    for (int it = 0; it < nit; it++) {
        const uint32_t stg = sb + (it & 1) * HL_STG;
        kstep_hilo(stg, 0, lane, wm, wn, c);
        kstep_hilo(stg, 1, lane, wm, wn, c);
        PIPE2_BOTTOM(HL_LOADI, it, nit, HL_STG);
    }
}

// ---------------------------------------------------------------------------
// single-pass GEMM (B K-major): CTA 128x128, BK=64. bf16 or fp16.
// ---------------------------------------------------------------------------
#define NT_STG  40960
#define SMEM_NT (2 * NT_STG)

template<bool BF>
__device__ __forceinline__ void gemm_1p(const void* A_, int lda, const void* B_v, int ldb,
                                        int nit, uint32_t sb, int tid, float c[4][8][4]) {
    const int lane = tid & 31, wid = tid >> 5;
    const int wm = wid >> 1, wn = wid & 1;
    const int la = lda * 2, lb = ldb * 2;
    const char* Ap = (const char*)A_;
    const char* Bp = (const char*)B_v;
#define NT_LOADI(saddr, itn)                                      \
    do {                                                          \
        const int ko_ = (itn) * 64 * 2;                           \
        cpa_k((saddr),          Ap + ko_,      la, tid);          \
        cpa_k((saddr) + 10240,  Ap + ko_ + 64, la, tid);          \
        cpa_k((saddr) + 20480,  Bp + ko_,      lb, tid);          \
        cpa_k((saddr) + 30720,  Bp + ko_ + 64, lb, tid);          \
        CP_COMMIT();                                              \
    } while (0)
    NT_LOADI(sb, 0);
    if (nit > 1) { NT_LOADI(sb + NT_STG, 1); CP_WAIT1(); }
    else         { CP_WAIT0(); }
    __syncthreads();
    for (int it = 0; it < nit; it++) {
        const uint32_t stg = sb + (it & 1) * NT_STG;
#pragma unroll
        for (int k4 = 0; k4 < 4; k4++) {
            const int sub = k4 >> 1, ks = k4 & 1;
            uint32_t ah[4][4], bh[4][4];
            ldF64(ah, stg + sub * 10240, wm, lane, ks);
            ldF64(bh, stg + 20480 + sub * 10240, wn, lane, ks);
            if (BF) mmas_bf16(c, ah, bh);
            else    mmas_f16 (c, ah, bh);
        }
        PIPE2_BOTTOM(NT_LOADI, it, nit, NT_STG);
    }
#undef NT_LOADI
}

// ---------------------------------------------------------------------------
// Conversions (vectorized float4)
// ---------------------------------------------------------------------------
__global__ void k_cvtX(const float4* __restrict__ x, int n4) {
    if (blockIdx.x == 0 && threadIdx.x == 0) g_nfix = 0;
    int i = blockIdx.x * 256 + threadIdx.x;
    const int stride = gridDim.x * 256;
    for (; i < n4; i += stride) {
        float4 v = x[i];
        bf16 h0, l0, h1, l1, h2, l2, h3, l3;
        split_bf16(v.x, h0, l0); split_bf16(v.y, h1, l1);
        split_bf16(v.z, h2, l2); split_bf16(v.w, h3, l3);
        uint2 hh, ll;
        hh.x = ((uint32_t)*(uint16_t*)&h1 << 16) | *(uint16_t*)&h0;
        hh.y = ((uint32_t)*(uint16_t*)&h3 << 16) | *(uint16_t*)&h2;
        ll.x = ((uint32_t)*(uint16_t*)&l1 << 16) | *(uint16_t*)&l0;
        ll.y = ((uint32_t)*(uint16_t*)&l3 << 16) | *(uint16_t*)&l2;
        *(uint2*)(g_Xhi + (size_t)i * 4) = hh;
        *(uint2*)(g_Xlo + (size_t)i * 4) = ll;
        __half2 f01 = __floats2half2_rn(v.x, v.y);
        __half2 f23 = __floats2half2_rn(v.z, v.w);
        uint2 ff; ff.x = *(uint32_t*)&f01; ff.y = *(uint32_t*)&f23;
        *(uint2*)(g_Xh + (size_t)i * 4) = ff;
    }
}
__global__ void k_cvtW(const float4* __restrict__ wqk, const float4* __restrict__ wov, int n4) {
    int i = blockIdx.x * 256 + threadIdx.x;
    const int stride = gridDim.x * 256;
    for (; i < n4; i += stride) {
        float4 v = wqk[i];
        bf16 h0, l0, h1, l1, h2, l2, h3, l3;
        split_bf16(v.x, h0, l0); split_bf16(v.y, h1, l1);
        split_bf16(v.z, h2, l2); split_bf16(v.w, h3, l3);
        uint2 hh, ll;
        hh.x = ((uint32_t)*(uint16_t*)&h1 << 16) | *(uint16_t*)&h0;
        hh.y = ((uint32_t)*(uint16_t*)&h3 << 16) | *(uint16_t*)&h2;
        ll.x = ((uint32_t)*(uint16_t*)&l1 << 16) | *(uint16_t*)&l0;
        ll.y = ((uint32_t)*(uint16_t*)&l3 << 16) | *(uint16_t*)&l2;
        *(uint2*)(g_Whi + (size_t)i * 4) = hh;
        *(uint2*)(g_Wlo + (size_t)i * 4) = ll;
        float4 w = wov[i];
        __half2 f01 = __floats2half2_rn(w.x, w.y);
        __half2 f23 = __floats2half2_rn(w.z, w.w);
        uint2 ff; ff.x = *(uint32_t*)&f01; ff.y = *(uint32_t*)&f23;
        *(uint2*)(g_Wh + (size_t)i * 4) = ff;
    }
}

// ---------------------------------------------------------------------------
// Merged Q+V kernel (z=0: Q 1-pass bf16 -> Qb; z=1: V 1-pass fp16)
// ---------------------------------------------------------------------------
__global__ __launch_bounds__(128, 2) void k_qv() {
    extern __shared__ __align__(1024) char smem[];
    const uint32_t sb = smem_u32(smem);
    const int tid = threadIdx.x;
    const int m0 = blockIdx.y * 128, n0 = blockIdx.x * 128;
    const int lane = tid & 31, wid = tid >> 5;
    const int wm = wid >> 1, wn = wid & 1;
    float c[4][8][4] = {};

    if (blockIdx.z == 0) {
        gemm_1p<true>(g_Xhi + (size_t)m0 * D_, D_, g_Whi + (size_t)n0 * D_, D_,
                      D_ / 64, sb, tid, c);
#pragma unroll
        for (int mi = 0; mi < 4; mi++) {
            const int r0 = m0 + wm * 64 + mi * 16 + (lane >> 2);
#pragma unroll
            for (int ni = 0; ni < 8; ni++) {
                const int gc = n0 + wn * 64 + ni * 8 + (lane & 3) * 2;
                const float* cc = c[mi][ni];
#pragma unroll
                for (int h = 0; h < 2; h++) {
                    const size_t idx = (size_t)(r0 + 8 * h) * D_ + gc;
                    __nv_bfloat162 qq;
                    qq.x = __float2bfloat16_rn(cc[2 * h]);
                    qq.y = __float2bfloat16_rn(cc[2 * h + 1]);
                    *(__nv_bfloat162*)(g_Qb + idx) = qq;
                }
            }
        }
    } else {
        gemm_1p<false>(g_Xh + (size_t)m0 * D_, D_, g_Wh + (size_t)n0 * D_, D_,
                       D_ / 64, sb, tid, c);
#pragma unroll
        for (int mi = 0; mi < 4; mi++) {
            const int r0 = m0 + wm * 64 + mi * 16 + (lane >> 2);
#pragma unroll
            for (int ni = 0; ni < 8; ni++) {
                const int gc = n0 + wn * 64 + ni * 8 + (lane & 3) * 2;
                const float* cc = c[mi][ni];
#pragma unroll
                for (int h = 0; h < 2; h++) {
                    const size_t idx = (size_t)(r0 + 8 * h) * D_ + gc;
                    *(__half2*)(g_Vh + idx) = __floats2half2_rn(cc[2 * h], cc[2 * h + 1]);
                }
            }
        }
    }
}

// ---------------------------------------------------------------------------
// Scores: 1-pass bf16 (Qb * Xhi^T), scaled x32, causal block skip.
// ---------------------------------------------------------------------------
__global__ __launch_bounds__(128, 2) void k_scores(float* __restrict__ Aout) {
    if (blockIdx.x > blockIdx.y) return;
    extern __shared__ __align__(1024) char smem[];
    const uint32_t sb = smem_u32(smem);
    const int tid = threadIdx.x;
    const int b = blockIdx.z;
    const int m0 = blockIdx.y * 128, n0 = blockIdx.x * 128;
    const size_t xb = (size_t)b * S_ * D_;
    float c[4][8][4] = {};
    gemm_1p<true>(g_Qb + xb + (size_t)m0 * D_, D_,
                  g_Xhi + xb + (size_t)n0 * D_, D_,
                  D_ / 64, sb, tid, c);
    const int lane = tid & 31, wid = tid >> 5;
    const int wm = wid >> 1, wn = wid & 1;
    float* Ab = Aout + (size_t)b * S_ * S_;
#pragma unroll
    for (int mi = 0; mi < 4; mi++) {
        const int r0 = m0 + wm * 64 + mi * 16 + (lane >> 2);
#pragma unroll
        for (int ni = 0; ni < 8; ni++) {
            const int gc = n0 + wn * 64 + ni * 8 + (lane & 3) * 2;
            const float* cc = c[mi][ni];
#pragma unroll
            for (int h = 0; h < 2; h++) {
                float2 v = make_float2(cc[2 * h] * 32.0f, cc[2 * h + 1] * 32.0f);
                *(float2*)(Ab + (size_t)(r0 + 8 * h) * S_ + gc) = v;
            }
        }
    }
}

// ---------------------------------------------------------------------------
// Pass B: candidate finder. Per row: max, collect {j: l_j > max-CWIN}, zero row,
// enqueue flagged rows (cnt>1) for exact Q recompute.
// ---------------------------------------------------------------------------
__global__ void k_softmax(float* __restrict__ A) {
    const int s = blockIdx.x, b = blockIdx.y;
    const int rowi = b * S_ + s;
    const size_t rb = (size_t)rowi * S_;
    float4* row = (float4*)(A + rb);
    const int len = s + 1;
    const int tid = threadIdx.x;
    const int lane = tid & 31, warp = tid >> 5;
    __shared__ float red[8];
    __shared__ int scnt;
    if (tid == 0) scnt = 0;

    float4 v[2];
    float m = -3.0e38f;
#pragma unroll
    for (int it = 0; it < 2; it++) {
        const int j4 = tid + it * 256;
        const int j = j4 * 4;
        float4 t = row[j4];
        t.x = (j + 0 < len) ? t.x : -3.0e38f;
        t.y = (j + 1 < len) ? t.y : -3.0e38f;
        t.z = (j + 2 < len) ? t.z : -3.0e38f;
        t.w = (j + 3 < len) ? t.w : -3.0e38f;
        v[it] = t;
        m = fmaxf(m, fmaxf(fmaxf(t.x, t.y), fmaxf(t.z, t.w)));
    }
#pragma unroll
    for (int o = 16; o > 0; o >>= 1)
        m = fmaxf(m, __shfl_xor_sync(0xffffffffu, m, o));
    if (lane == 0) red[warp] = m;
    __syncthreads();
    m = red[lane & 7];
#pragma unroll
    for (int o = 4; o > 0; o >>= 1)
        m = fmaxf(m, __shfl_xor_sync(0xffffffffu, m, o));

    const float thr = m - CWIN;
    int* crow = g_cand + (size_t)rowi * NCAND;
#pragma unroll
    for (int it = 0; it < 2; it++) {
        const int j = (tid + it * 256) * 4;
        const float* t = (const float*)&v[it];
#pragma unroll
        for (int e = 0; e < 4; e++) {
            if (t[e] > thr) {
                int slot = atomicAdd(&scnt, 1);
                if (slot < NCAND) crow[slot] = j + e;
            }
        }
    }
    __syncthreads();
    float4 z4 = make_float4(0.f, 0.f, 0.f, 0.f);
    row[tid] = z4;
    row[tid + 256] = z4;
    if (tid == 0) {
        g_cnt[rowi] = (scnt <= NCAND) ? scnt : 255;
        if (scnt > 1) {
            int slot = atomicAdd(&g_nfix, 1);
            g_fixrows[slot] = rowi;
            g_slot[rowi] = slot;
        }
    }
}

// ---------------------------------------------------------------------------
// Gather flagged Xhi/Xlo rows into compact matrices.
// ---------------------------------------------------------------------------
__global__ void k_gather() {
    const int i = blockIdx.x;
    if (i >= g_nfix) return;
    const int rowi = g_fixrows[i];
    const int tid = threadIdx.x;
    ((uint2*)(g_Xchi + (size_t)i * D_))[tid] =
        ((const uint2*)(g_Xhi + (size_t)rowi * D_))[tid];
    ((uint2*)(g_Xclo + (size_t)i * D_))[tid] =
        ((const uint2*)(g_Xlo + (size_t)rowi * D_))[tid];
}

// ---------------------------------------------------------------------------
// Exact Q for flagged rows: compact 3-pass hilo GEMM -> g_Qc fp32.
// ---------------------------------------------------------------------------
__global__ __launch_bounds__(128, 2) void k_qfix() {
    const int m0 = blockIdx.y * 128;
    if (m0 >= g_nfix) return;
    extern __shared__ __align__(1024) char smem[];
    const uint32_t sb = smem_u32(smem);
    const int tid = threadIdx.x;
    const int n0 = blockIdx.x * 128;
    float c[4][8][4] = {};
    gemm_hilo(g_Xchi + (size_t)m0 * D_, g_Xclo + (size_t)m0 * D_, D_,
              g_Whi + (size_t)n0 * D_, g_Wlo + (size_t)n0 * D_, D_,
              D_ / 32, sb, tid, c);
    const int lane = tid & 31, wid = tid >> 5;
    const int wm = wid >> 1, wn = wid & 1;
#pragma unroll
    for (int mi = 0; mi < 4; mi++) {
        const int r0 = m0 + wm * 64 + mi * 16 + (lane >> 2);
#pragma unroll
        for (int ni = 0; ni < 8; ni++) {
            const int gc = n0 + wn * 64 + ni * 8 + (lane & 3) * 2;
            const float* cc = c[mi][ni];
#pragma unroll
            for (int h = 0; h < 2; h++) {
                const size_t idx = (size_t)(r0 + 8 * h) * D_ + gc;
                *(float2*)(g_Qc + idx) = make_float2(cc[2 * h], cc[2 * h + 1]);
            }
        }
    }
}

// ---------------------------------------------------------------------------
// Pass C: exact softmax for flagged rows (fp32 dots of Qc[slot] . X[t]).
// ---------------------------------------------------------------------------
__global__ void k_exact(const float* __restrict__ X, float* __restrict__ Aout) {
    const int s = blockIdx.x, b = blockIdx.y;
    const int rowi = b * S_ + s;
    const int cnt = g_cnt[rowi];
    float* Arow = Aout + (size_t)rowi * S_;
    const int tid = threadIdx.x, lane = tid & 31, warp = tid >> 5;
    const int* crow = g_cand + (size_t)rowi * NCAND;

    if (cnt <= 1) {
        if (cnt == 1 && tid == 0) Arow[crow[0]] = 1.0f;
        return;
    }

    __shared__ float qrow[D_];
    __shared__ float lg[NCAND];
    __shared__ float red[8];
    const int slot = g_slot[rowi];
    ((float4*)qrow)[tid] = ((const float4*)(g_Qc + (size_t)slot * D_))[tid];
    __syncthreads();
    const float* Xb = X + (size_t)b * S_ * D_;

    if (cnt != 255) {
        for (int ci = warp; ci < cnt; ci += 8) {
            const float* xr = Xb + (size_t)crow[ci] * D_;
            float d = 0.f;
            for (int k = lane; k < D_; k += 32) d += qrow[k] * xr[k];
#pragma unroll
            for (int o = 16; o > 0; o >>= 1) d += __shfl_xor_sync(0xffffffffu, d, o);
            if (lane == 0) lg[ci] = d * 32.0f;
        }
        __syncthreads();
        if (tid == 0) {
            float mm = -3.0e38f;
            for (int ci = 0; ci < cnt; ci++) mm = fmaxf(mm, lg[ci]);
            float Z = 0.f;
            for (int ci = 0; ci < cnt; ci++) Z += expf(lg[ci] - mm);
            const float inv = 1.0f / Z;
            for (int ci = 0; ci < cnt; ci++) Arow[crow[ci]] = expf(lg[ci] - mm) * inv;
        }
    } else {
        const int len = s + 1;
        for (int t = warp; t < len; t += 8) {
            const float* xr = Xb + (size_t)t * D_;
            float d = 0.f;
            for (int k = lane; k < D_; k += 32) d += qrow[k] * xr[k];
#pragma unroll
            for (int o = 16; o > 0; o >>= 1) d += __shfl_xor_sync(0xffffffffu, d, o);
            if (lane == 0) Arow[t] = d * 32.0f;
        }
        __syncthreads();
        float mm = -3.0e38f;
        for (int j = tid; j < len; j += 256) mm = fmaxf(mm, Arow[j]);
#pragma unroll
        for (int o = 16; o > 0; o >>= 1) mm = fmaxf(mm, __shfl_xor_sync(0xffffffffu, mm, o));
        if (lane == 0) red[warp] = mm;
        __syncthreads();
        mm = red[lane & 7];
#pragma unroll
        for (int o = 4; o > 0; o >>= 1) mm = fmaxf(mm, __shfl_xor_sync(0xffffffffu, mm, o));
        float Z = 0.f;
        for (int j = tid; j < len; j += 256) Z += expf(Arow[j] - mm);
#pragma unroll
        for (int o = 16; o > 0; o >>= 1) Z += __shfl_xor_sync(0xffffffffu, Z, o);
        if (lane == 0) red[warp] = Z;
        __syncthreads();
        Z = red[lane & 7];
#pragma unroll
        for (int o = 4; o > 0; o >>= 1) Z += __shfl_xor_sync(0xffffffffu, Z, o);
        const float inv = 1.0f / Z;
        __syncthreads();
        for (int j = tid; j < len; j += 256) Arow[j] = expf(Arow[j] - mm) * inv;
    }
}

// ---------------------------------------------------------------------------
// Pass D: out = X + A.V via sparse gather over candidates.
// ---------------------------------------------------------------------------
__global__ void k_out(const float* __restrict__ X, float* __restrict__ Yout,
                      const float* __restrict__ Aout) {
    const int s = blockIdx.x, b = blockIdx.y;
    const int rowi = b * S_ + s;
    const int cnt = g_cnt[rowi];
    const int tid = threadIdx.x;
    const size_t xoff = (size_t)rowi * D_;
    const float* Arow = Aout + (size_t)rowi * S_;
    const int* crow = g_cand + (size_t)rowi * NCAND;

    float4 x4 = ((const float4*)(X + xoff))[tid];
    float y0 = 0.f, y1 = 0.f, y2 = 0.f, y3 = 0.f;

    if (cnt != 255) {
        for (int ci = 0; ci < cnt; ci++) {
            const int t = crow[ci];
            const float a = Arow[t];
            const __half2* vr = (const __half2*)(g_Vh + ((size_t)b * S_ + t) * D_) + tid * 2;
            float2 p0 = __half22float2(vr[0]);
            float2 p1 = __half22float2(vr[1]);
            y0 += a * p0.x; y1 += a * p0.y; y2 += a * p1.x; y3 += a * p1.y;
        }
    } else {
        const int len = s + 1;
        for (int t = 0; t < len; t++) {
            const float a = Arow[t];
            if (a > 1e-30f) {
                const __half2* vr = (const __half2*)(g_Vh + ((size_t)b * S_ + t) * D_) + tid * 2;
                float2 p0 = __half22float2(vr[0]);
                float2 p1 = __half22float2(vr[1]);
                y0 += a * p0.x; y1 += a * p0.y; y2 += a * p1.x; y3 += a * p1.y;
            }
        }
    }
    float4 o = make_float4(x4.x + y0, x4.y + y1, x4.z + y2, x4.w + y3);
    ((float4*)(Yout + xoff))[tid] = o;
}

// ---------------------------------------------------------------------------
extern "C" void kernel_launch(void* const* d_in, const int* in_sizes, int n_in,
                              void* d_out, int out_size) {
    const float* X   = (const float*)d_in[0];
    const float* WQK = (const float*)d_in[2];
    const float* WOV = (const float*)d_in[3];
    float* out = (float*)d_out;

    const size_t nY = (size_t)M1 * D_;
    const size_t nA = (size_t)B_ * S_ * S_;
    float* Aout;
    if ((size_t)out_size >= nY + nA) {
        Aout = out + nY;
    } else {
        void* p = nullptr;
        cudaGetSymbolAddress(&p, g_Afallback);
        Aout = (float*)p;
    }

    static bool attrs_set = false;
    if (!attrs_set) {
        cudaFuncSetAttribute(k_qv,     cudaFuncAttributeMaxDynamicSharedMemorySize, SMEM_NT);
        cudaFuncSetAttribute(k_scores, cudaFuncAttributeMaxDynamicSharedMemorySize, SMEM_NT);
        cudaFuncSetAttribute(k_qfix,   cudaFuncAttributeMaxDynamicSharedMemorySize, SMEM_HILO);
        attrs_set = true;
    }

    // 1) conversions (+ g_nfix reset)
    k_cvtX<<<512, 256>>>((const float4*)X, M1 * D_ / 4);
    k_cvtW<<<256, 256>>>((const float4*)WQK, (const float4*)WOV, D_ * D_ / 4);
    // 2) Q (1-pass bf16) and V (1-pass fp16)
    k_qv<<<dim3(D_ / 128, M1 / 128, 2), 128, SMEM_NT>>>();
    // 3) approx scores (1-pass bf16), causal
    k_scores<<<dim3(S_ / 128, S_ / 128, B_), 128, SMEM_NT>>>(Aout);
    // 4) candidate finder + zero A + flag rows
    k_softmax<<<dim3(S_, B_), 256>>>(Aout);
    // 5) exact Q for flagged rows (compact 3-pass GEMM)
    k_gather<<<M1, 256>>>();
    k_qfix<<<dim3(D_ / 128, M1 / 128), 128, SMEM_HILO>>>();
    // 6) exact softmax on flagged rows
    k_exact<<<dim3(S_, B_), 256>>>(X, Aout);
    // 7) out = X + A.V (sparse gather)
    k_out<<<dim3(S_, B_), 256>>>(X, out, Aout);
}

// round 13
// speedup vs baseline: 6.2654x; 1.0423x over previous
#include <cuda_runtime.h>
#include <cuda_bf16.h>
#include <cuda_fp16.h>
#include <cstdint>

#define B_  4
#define S_  2048
#define D_  1024
#define M1  (B_ * S_)
#define NCAND 32
#define CWIN  46.0f

typedef __nv_bfloat16 bf16;

// ---------------------------------------------------------------------------
// Scratch (__device__ globals; no allocation allowed)
// ---------------------------------------------------------------------------
__device__ __align__(256) bf16   g_Xhi[(size_t)M1 * D_];
__device__ __align__(256) bf16   g_Xlo[(size_t)M1 * D_];
__device__ __align__(256) __half g_Xh [(size_t)M1 * D_];
__device__ __align__(256) bf16   g_Whi[(size_t)D_ * D_];
__device__ __align__(256) bf16   g_Wlo[(size_t)D_ * D_];
__device__ __align__(256) __half g_Wh [(size_t)D_ * D_];
__device__ __align__(256) bf16   g_Qb [(size_t)M1 * D_];   // Q 1-pass, bf16
__device__ __align__(256) __half g_Vh [(size_t)M1 * D_];   // V fp16 [m][d]
__device__ __align__(256) float  g_Qc [(size_t)M1 * D_];   // exact Q, compact
__device__ int  g_nfix;
__device__ int  g_fixrows[(size_t)B_ * S_];
__device__ int  g_slot   [(size_t)B_ * S_];
__device__ int  g_cnt [(size_t)B_ * S_];
__device__ int  g_cand[(size_t)B_ * S_ * NCAND];
__device__ float g_Afallback[(size_t)B_ * S_ * S_];

// ---------------------------------------------------------------------------
// Baseline-PTX primitives
// ---------------------------------------------------------------------------
__device__ __forceinline__ uint32_t smem_u32(const void* p) {
    uint32_t a;
    asm("{ .reg .u64 t; cvta.to.shared.u64 t, %1; cvt.u32.u64 %0, t; }" : "=r"(a) : "l"(p));
    return a;
}
#define CPA(dst, src)  asm volatile("cp.async.cg.shared.global [%0], [%1], 16;\n" :: "r"(dst), "l"(src))
#define CP_COMMIT()    asm volatile("cp.async.commit_group;\n" ::: "memory")
#define CP_WAIT1()     asm volatile("cp.async.wait_group 1;\n" ::: "memory")
#define CP_WAIT0()     asm volatile("cp.async.wait_group 0;\n" ::: "memory")

__device__ __forceinline__ void ldsm4(uint32_t r[4], uint32_t a) {
    asm volatile("ldmatrix.sync.aligned.m8n8.x4.shared.b16 {%0,%1,%2,%3}, [%4];\n"
                 : "=r"(r[0]), "=r"(r[1]), "=r"(r[2]), "=r"(r[3]) : "r"(a));
}
__device__ __forceinline__ void mma_bf16(float* c, const uint32_t a[4], uint32_t b0, uint32_t b1) {
    asm volatile("mma.sync.aligned.m16n8k16.row.col.f32.bf16.bf16.f32 "
                 "{%0,%1,%2,%3}, {%4,%5,%6,%7}, {%8,%9}, {%0,%1,%2,%3};\n"
                 : "+f"(c[0]), "+f"(c[1]), "+f"(c[2]), "+f"(c[3])
                 : "r"(a[0]), "r"(a[1]), "r"(a[2]), "r"(a[3]), "r"(b0), "r"(b1));
}
__device__ __forceinline__ void mma_f16(float* c, const uint32_t a[4], uint32_t b0, uint32_t b1) {
    asm volatile("mma.sync.aligned.m16n8k16.row.col.f32.f16.f16.f32 "
                 "{%0,%1,%2,%3}, {%4,%5,%6,%7}, {%8,%9}, {%0,%1,%2,%3};\n"
                 : "+f"(c[0]), "+f"(c[1]), "+f"(c[2]), "+f"(c[3])
                 : "r"(a[0]), "r"(a[1]), "r"(a[2]), "r"(a[3]), "r"(b0), "r"(b1));
}
__device__ __forceinline__ void split_bf16(float v, bf16& h, bf16& l) {
    h = __float2bfloat16_rn(v);
    l = __float2bfloat16_rn(v - __bfloat162float(h));
}

// ---------------------------------------------------------------------------
// Tile loaders: 128 threads. K-major [128 rows][32 elems], smem rows 80B.
// ---------------------------------------------------------------------------
__device__ __forceinline__ void cpa_k(uint32_t sdst, const void* g, int ldbytes, int tid) {
#pragma unroll
    for (int i = 0; i < 4; i++) {
        int u = tid + i * 128;
        int r = u >> 2, c = u & 3;
        CPA(sdst + r * 80 + c * 16, (const char*)g + (size_t)r * ldbytes + c * 16);
    }
}
// Indirect-row variant: row r comes from sidx[r] (smem table)
__device__ __forceinline__ void cpa_ki(uint32_t sdst, const bf16* base,
                                       const int* sidx, int ko, int tid) {
#pragma unroll
    for (int i = 0; i < 4; i++) {
        int u = tid + i * 128;
        int r = u >> 2, c = u & 3;
        CPA(sdst + r * 80 + c * 16, base + (size_t)sidx[r] * D_ + ko + c * 8);
    }
}
__device__ __forceinline__ void ld4frag(uint32_t base, uint32_t r[4][4]) {
#pragma unroll
    for (int i = 0; i < 4; i++) ldsm4(r[i], base + i * 1280);
}
__device__ __forceinline__ void ldF64(uint32_t r[4][4], uint32_t base, int w, int lane, int ks) {
    const int row = lane & 15;
    const int ch  = (lane >> 4) + ks * 2;
    ld4frag(base + (w * 64 + row) * 80 + ch * 16, r);
}
__device__ __forceinline__ void mmas_bf16(float c[4][8][4], uint32_t a[4][4], uint32_t b[4][4]) {
#pragma unroll
    for (int mi = 0; mi < 4; mi++)
#pragma unroll
        for (int nj = 0; nj < 4; nj++) {
            mma_bf16(c[mi][2 * nj],     a[mi], b[nj][0], b[nj][2]);
            mma_bf16(c[mi][2 * nj + 1], a[mi], b[nj][1], b[nj][3]);
        }
}
__device__ __forceinline__ void mmas_f16(float c[4][8][4], uint32_t a[4][4], uint32_t b[4][4]) {
#pragma unroll
    for (int mi = 0; mi < 4; mi++)
#pragma unroll
        for (int nj = 0; nj < 4; nj++) {
            mma_f16(c[mi][2 * nj],     a[mi], b[nj][0], b[nj][2]);
            mma_f16(c[mi][2 * nj + 1], a[mi], b[nj][1], b[nj][3]);
        }
}

#define PIPE2_BOTTOM(LOADI, it, nit, STGB)                        \
    do {                                                          \
        if ((it) + 1 < (nit)) {                                   \
            __syncthreads();                                      \
            const bool more = ((it) + 2 < (nit));                 \
            if (more) { LOADI(sb + ((it) & 1) * (STGB), (it) + 2); } \
            if (more) { CP_WAIT1(); } else { CP_WAIT0(); }        \
            __syncthreads();                                      \
        }                                                         \
    } while (0)

// ---------------------------------------------------------------------------
// hi/lo 3-pass GEMM pieces (used by k_qfix)
// ---------------------------------------------------------------------------
#define HL_ALO 10240
#define HL_BHI 20480
#define HL_BLO 30720
#define HL_STG 40960
#define SMEM_HILO (2 * HL_STG)

__device__ __forceinline__ void kstep_hilo(uint32_t stg, int ks, int lane,
                                           int wm, int wn, float c[4][8][4]) {
    uint32_t ah[4][4], bh[4][4], t[4][4];
    ldF64(ah, stg, wm, lane, ks);
    ldF64(bh, stg + HL_BHI, wn, lane, ks);
    mmas_bf16(c, ah, bh);
    ldF64(t, stg + HL_BLO, wn, lane, ks);
    mmas_bf16(c, ah, t);
    ldF64(t, stg + HL_ALO, wm, lane, ks);
    mmas_bf16(c, t, bh);
}

// ---------------------------------------------------------------------------
// single-pass GEMM (B K-major): CTA 128x128, BK=64. bf16 or fp16.
// ---------------------------------------------------------------------------
#define NT_STG  40960
#define SMEM_NT (2 * NT_STG)

template<bool BF>
__device__ __forceinline__ void gemm_1p(const void* A_, int lda, const void* B_v, int ldb,
                                        int nit, uint32_t sb, int tid, float c[4][8][4]) {
    const int lane = tid & 31, wid = tid >> 5;
    const int wm = wid >> 1, wn = wid & 1;
    const int la = lda * 2, lb = ldb * 2;
    const char* Ap = (const char*)A_;
    const char* Bp = (const char*)B_v;
#define NT_LOADI(saddr, itn)                                      \
    do {                                                          \
        const int ko_ = (itn) * 64 * 2;                           \
        cpa_k((saddr),          Ap + ko_,      la, tid);          \
        cpa_k((saddr) + 10240,  Ap + ko_ + 64, la, tid);          \
        cpa_k((saddr) + 20480,  Bp + ko_,      lb, tid);          \
        cpa_k((saddr) + 30720,  Bp + ko_ + 64, lb, tid);          \
        CP_COMMIT();                                              \
    } while (0)
    NT_LOADI(sb, 0);
    if (nit > 1) { NT_LOADI(sb + NT_STG, 1); CP_WAIT1(); }
    else         { CP_WAIT0(); }
    __syncthreads();
    for (int it = 0; it < nit; it++) {
        const uint32_t stg = sb + (it & 1) * NT_STG;
#pragma unroll
        for (int k4 = 0; k4 < 4; k4++) {
            const int sub = k4 >> 1, ks = k4 & 1;
            uint32_t ah[4][4], bh[4][4];
            ldF64(ah, stg + sub * 10240, wm, lane, ks);
            ldF64(bh, stg + 20480 + sub * 10240, wn, lane, ks);
            if (BF) mmas_bf16(c, ah, bh);
            else    mmas_f16 (c, ah, bh);
        }
        PIPE2_BOTTOM(NT_LOADI, it, nit, NT_STG);
    }
#undef NT_LOADI
}

// ---------------------------------------------------------------------------
// Conversions (vectorized float4)
// ---------------------------------------------------------------------------
__global__ void k_cvtX(const float4* __restrict__ x, int n4) {
    if (blockIdx.x == 0 && threadIdx.x == 0) g_nfix = 0;
    int i = blockIdx.x * 256 + threadIdx.x;
    const int stride = gridDim.x * 256;
    for (; i < n4; i += stride) {
        float4 v = x[i];
        bf16 h0, l0, h1, l1, h2, l2, h3, l3;
        split_bf16(v.x, h0, l0); split_bf16(v.y, h1, l1);
        split_bf16(v.z, h2, l2); split_bf16(v.w, h3, l3);
        uint2 hh, ll;
        hh.x = ((uint32_t)*(uint16_t*)&h1 << 16) | *(uint16_t*)&h0;
        hh.y = ((uint32_t)*(uint16_t*)&h3 << 16) | *(uint16_t*)&h2;
        ll.x = ((uint32_t)*(uint16_t*)&l1 << 16) | *(uint16_t*)&l0;
        ll.y = ((uint32_t)*(uint16_t*)&l3 << 16) | *(uint16_t*)&l2;
        *(uint2*)(g_Xhi + (size_t)i * 4) = hh;
        *(uint2*)(g_Xlo + (size_t)i * 4) = ll;
        __half2 f01 = __floats2half2_rn(v.x, v.y);
        __half2 f23 = __floats2half2_rn(v.z, v.w);
        uint2 ff; ff.x = *(uint32_t*)&f01; ff.y = *(uint32_t*)&f23;
        *(uint2*)(g_Xh + (size_t)i * 4) = ff;
    }
}
__global__ void k_cvtW(const float4* __restrict__ wqk, const float4* __restrict__ wov, int n4) {
    int i = blockIdx.x * 256 + threadIdx.x;
    const int stride = gridDim.x * 256;
    for (; i < n4; i += stride) {
        float4 v = wqk[i];
        bf16 h0, l0, h1, l1, h2, l2, h3, l3;
        split_bf16(v.x, h0, l0); split_bf16(v.y, h1, l1);
        split_bf16(v.z, h2, l2); split_bf16(v.w, h3, l3);
        uint2 hh, ll;
        hh.x = ((uint32_t)*(uint16_t*)&h1 << 16) | *(uint16_t*)&h0;
        hh.y = ((uint32_t)*(uint16_t*)&h3 << 16) | *(uint16_t*)&h2;
        ll.x = ((uint32_t)*(uint16_t*)&l1 << 16) | *(uint16_t*)&l0;
        ll.y = ((uint32_t)*(uint16_t*)&l3 << 16) | *(uint16_t*)&l2;
        *(uint2*)(g_Whi + (size_t)i * 4) = hh;
        *(uint2*)(g_Wlo + (size_t)i * 4) = ll;
        float4 w = wov[i];
        __half2 f01 = __floats2half2_rn(w.x, w.y);
        __half2 f23 = __floats2half2_rn(w.z, w.w);
        uint2 ff; ff.x = *(uint32_t*)&f01; ff.y = *(uint32_t*)&f23;
        *(uint2*)(g_Wh + (size_t)i * 4) = ff;
    }
}

// ---------------------------------------------------------------------------
// Merged Q+V kernel (z=0: Q 1-pass bf16 -> Qb; z=1: V 1-pass fp16)
// ---------------------------------------------------------------------------
__global__ __launch_bounds__(128, 2) void k_qv() {
    extern __shared__ __align__(1024) char smem[];
    const uint32_t sb = smem_u32(smem);
    const int tid = threadIdx.x;
    const int m0 = blockIdx.y * 128, n0 = blockIdx.x * 128;
    const int lane = tid & 31, wid = tid >> 5;
    const int wm = wid >> 1, wn = wid & 1;
    float c[4][8][4] = {};

    if (blockIdx.z == 0) {
        gemm_1p<true>(g_Xhi + (size_t)m0 * D_, D_, g_Whi + (size_t)n0 * D_, D_,
                      D_ / 64, sb, tid, c);
#pragma unroll
        for (int mi = 0; mi < 4; mi++) {
            const int r0 = m0 + wm * 64 + mi * 16 + (lane >> 2);
#pragma unroll
            for (int ni = 0; ni < 8; ni++) {
                const int gc = n0 + wn * 64 + ni * 8 + (lane & 3) * 2;
                const float* cc = c[mi][ni];
#pragma unroll
                for (int h = 0; h < 2; h++) {
                    const size_t idx = (size_t)(r0 + 8 * h) * D_ + gc;
                    __nv_bfloat162 qq;
                    qq.x = __float2bfloat16_rn(cc[2 * h]);
                    qq.y = __float2bfloat16_rn(cc[2 * h + 1]);
                    *(__nv_bfloat162*)(g_Qb + idx) = qq;
                }
            }
        }
    } else {
        gemm_1p<false>(g_Xh + (size_t)m0 * D_, D_, g_Wh + (size_t)n0 * D_, D_,
                       D_ / 64, sb, tid, c);
#pragma unroll
        for (int mi = 0; mi < 4; mi++) {
            const int r0 = m0 + wm * 64 + mi * 16 + (lane >> 2);
#pragma unroll
            for (int ni = 0; ni < 8; ni++) {
                const int gc = n0 + wn * 64 + ni * 8 + (lane & 3) * 2;
                const float* cc = c[mi][ni];
#pragma unroll
                for (int h = 0; h < 2; h++) {
                    const size_t idx = (size_t)(r0 + 8 * h) * D_ + gc;
                    *(__half2*)(g_Vh + idx) = __floats2half2_rn(cc[2 * h], cc[2 * h + 1]);
                }
            }
        }
    }
}

// ---------------------------------------------------------------------------
// Scores: 1-pass bf16 (Qb * Xhi^T), scaled x32; skipped upper blocks -> zeros.
// ---------------------------------------------------------------------------
__global__ __launch_bounds__(128, 2) void k_scores(float* __restrict__ Aout) {
    const int b = blockIdx.z;
    const int m0 = blockIdx.y * 128, n0 = blockIdx.x * 128;
    float* Ab = Aout + (size_t)b * S_ * S_;
    const int tid = threadIdx.x;

    if (blockIdx.x > blockIdx.y) {
        // strictly above diagonal: write zeros
        const float4 z = make_float4(0.f, 0.f, 0.f, 0.f);
        for (int i = tid; i < 128 * 32; i += 128) {
            const int r = i >> 5, c4 = i & 31;
            ((float4*)(Ab + (size_t)(m0 + r) * S_ + n0))[c4] = z;
        }
        return;
    }

    extern __shared__ __align__(1024) char smem[];
    const uint32_t sb = smem_u32(smem);
    const size_t xb = (size_t)b * S_ * D_;
    float c[4][8][4] = {};
    gemm_1p<true>(g_Qb + xb + (size_t)m0 * D_, D_,
                  g_Xhi + xb + (size_t)n0 * D_, D_,
                  D_ / 64, sb, tid, c);
    const int lane = tid & 31, wid = tid >> 5;
    const int wm = wid >> 1, wn = wid & 1;
#pragma unroll
    for (int mi = 0; mi < 4; mi++) {
        const int r0 = m0 + wm * 64 + mi * 16 + (lane >> 2);
#pragma unroll
        for (int ni = 0; ni < 8; ni++) {
            const int gc = n0 + wn * 64 + ni * 8 + (lane & 3) * 2;
            const float* cc = c[mi][ni];
#pragma unroll
            for (int h = 0; h < 2; h++) {
                float2 v = make_float2(cc[2 * h] * 32.0f, cc[2 * h + 1] * 32.0f);
                *(float2*)(Ab + (size_t)(r0 + 8 * h) * S_ + gc) = v;
            }
        }
    }
}

// ---------------------------------------------------------------------------
// Pass B: candidate finder over [0, diag-block-end) only; zeroes that range.
// ---------------------------------------------------------------------------
__global__ void k_softmax(float* __restrict__ A) {
    const int s = blockIdx.x, b = blockIdx.y;
    const int rowi = b * S_ + s;
    const size_t rb = (size_t)rowi * S_;
    float4* row = (float4*)(A + rb);
    const int len = s + 1;
    const int blkend4 = (((s >> 7) + 1) << 7) >> 2;  // float4s up to diag block end
    const int tid = threadIdx.x;
    const int lane = tid & 31, warp = tid >> 5;
    __shared__ float red[8];
    __shared__ int scnt;
    if (tid == 0) scnt = 0;

    float4 v[2];
    float m = -3.0e38f;
#pragma unroll
    for (int it = 0; it < 2; it++) {
        const int j4 = tid + it * 256;
        const int j = j4 * 4;
        float4 t = make_float4(-3.0e38f, -3.0e38f, -3.0e38f, -3.0e38f);
        if (j4 < blkend4) {
            t = row[j4];
            t.x = (j + 0 < len) ? t.x : -3.0e38f;
            t.y = (j + 1 < len) ? t.y : -3.0e38f;
            t.z = (j + 2 < len) ? t.z : -3.0e38f;
            t.w = (j + 3 < len) ? t.w : -3.0e38f;
        }
        v[it] = t;
        m = fmaxf(m, fmaxf(fmaxf(t.x, t.y), fmaxf(t.z, t.w)));
    }
#pragma unroll
    for (int o = 16; o > 0; o >>= 1)
        m = fmaxf(m, __shfl_xor_sync(0xffffffffu, m, o));
    if (lane == 0) red[warp] = m;
    __syncthreads();
    m = red[lane & 7];
#pragma unroll
    for (int o = 4; o > 0; o >>= 1)
        m = fmaxf(m, __shfl_xor_sync(0xffffffffu, m, o));

    const float thr = m - CWIN;
    int* crow = g_cand + (size_t)rowi * NCAND;
#pragma unroll
    for (int it = 0; it < 2; it++) {
        const int j = (tid + it * 256) * 4;
        const float* t = (const float*)&v[it];
#pragma unroll
        for (int e = 0; e < 4; e++) {
            if (t[e] > thr) {
                int slot = atomicAdd(&scnt, 1);
                if (slot < NCAND) crow[slot] = j + e;
            }
        }
    }
    __syncthreads();
    const float4 z4 = make_float4(0.f, 0.f, 0.f, 0.f);
#pragma unroll
    for (int it = 0; it < 2; it++) {
        const int j4 = tid + it * 256;
        if (j4 < blkend4) row[j4] = z4;
    }
    if (tid == 0) {
        g_cnt[rowi] = (scnt <= NCAND) ? scnt : 255;
        if (scnt > 1) {
            int slot = atomicAdd(&g_nfix, 1);
            g_fixrows[slot] = rowi;
            g_slot[rowi] = slot;
        }
    }
}

// ---------------------------------------------------------------------------
// Exact Q for flagged rows: 3-pass hilo GEMM with indirect A rows -> g_Qc.
// ---------------------------------------------------------------------------
__global__ __launch_bounds__(128, 2) void k_qfix() {
    const int m0 = blockIdx.y * 128;
    const int nfix = g_nfix;
    if (m0 >= nfix) return;
    extern __shared__ __align__(1024) char smem[];
    __shared__ int sidx[128];
    const uint32_t sb = smem_u32(smem);
    const int tid = threadIdx.x;
    const int n0 = blockIdx.x * 128;
    if (tid < 128) sidx[tid] = (m0 + tid < nfix) ? g_fixrows[m0 + tid] : 0;
    __syncthreads();

    const bf16* Bh = g_Whi + (size_t)n0 * D_;
    const bf16* Bl = g_Wlo + (size_t)n0 * D_;
    const int lb = D_ * 2;
    const int lane = tid & 31, wid = tid >> 5;
    const int wm = wid >> 1, wn = wid & 1;
    float c[4][8][4] = {};

#define HLX_LOADI(saddr, itn)                                     \
    do {                                                          \
        const int ko_ = (itn) * 32;                               \
        cpa_ki((saddr),          g_Xhi, sidx, ko_, tid);          \
        cpa_ki((saddr) + HL_ALO, g_Xlo, sidx, ko_, tid);          \
        cpa_k ((saddr) + HL_BHI, Bh + ko_, lb, tid);              \
        cpa_k ((saddr) + HL_BLO, Bl + ko_, lb, tid);              \
        CP_COMMIT();                                              \
    } while (0)

    const int nit = D_ / 32;
    HLX_LOADI(sb, 0);
    HLX_LOADI(sb + HL_STG, 1);
    CP_WAIT1();
    __syncthreads();
    for (int it = 0; it < nit; it++) {
        const uint32_t stg = sb + (it & 1) * HL_STG;
        kstep_hilo(stg, 0, lane, wm, wn, c);
        kstep_hilo(stg, 1, lane, wm, wn, c);
        PIPE2_BOTTOM(HLX_LOADI, it, nit, HL_STG);
    }
#undef HLX_LOADI

#pragma unroll
    for (int mi = 0; mi < 4; mi++) {
        const int r0 = m0 + wm * 64 + mi * 16 + (lane >> 2);
#pragma unroll
        for (int ni = 0; ni < 8; ni++) {
            const int gc = n0 + wn * 64 + ni * 8 + (lane & 3) * 2;
            const float* cc = c[mi][ni];
#pragma unroll
            for (int h = 0; h < 2; h++) {
                const size_t idx = (size_t)(r0 + 8 * h) * D_ + gc;
                *(float2*)(g_Qc + idx) = make_float2(cc[2 * h], cc[2 * h + 1]);
            }
        }
    }
}

// ---------------------------------------------------------------------------
// k_finish: exact softmax for flagged rows + out = X + A.V, all in one pass.
// ---------------------------------------------------------------------------
__global__ void k_finish(const float* __restrict__ X, float* __restrict__ Yout,
                         float* __restrict__ Aout) {
    const int s = blockIdx.x, b = blockIdx.y;
    const int rowi = b * S_ + s;
    const int cnt = g_cnt[rowi];
    const int tid = threadIdx.x, lane = tid & 31, warp = tid >> 5;
    const size_t xoff = (size_t)rowi * D_;
    float* Arow = Aout + (size_t)rowi * S_;
    const int* crow = g_cand + (size_t)rowi * NCAND;

    float4 x4 = ((const float4*)(X + xoff))[tid];

    if (cnt <= 1) {
        const int t = crow[0];
        if (tid == 0) Arow[t] = 1.0f;
        const __half2* vr = (const __half2*)(g_Vh + ((size_t)b * S_ + t) * D_) + tid * 2;
        float2 p0 = __half22float2(vr[0]);
        float2 p1 = __half22float2(vr[1]);
        float4 o = make_float4(x4.x + p0.x, x4.y + p0.y, x4.z + p1.x, x4.w + p1.y);
        ((float4*)(Yout + xoff))[tid] = o;
        return;
    }

    __shared__ float qrow[D_];
    __shared__ float av[NCAND];
    __shared__ float red[8];
    const int slot = g_slot[rowi];
    ((float4*)qrow)[tid] = ((const float4*)(g_Qc + (size_t)slot * D_))[tid];
    __syncthreads();
    const float* Xb = X + (size_t)b * S_ * D_;

    float y0 = 0.f, y1 = 0.f, y2 = 0.f, y3 = 0.f;

    if (cnt != 255) {
        for (int ci = warp; ci < cnt; ci += 8) {
            const float* xr = Xb + (size_t)crow[ci] * D_;
            float d = 0.f;
            for (int k = lane; k < D_; k += 32) d += qrow[k] * xr[k];
#pragma unroll
            for (int o = 16; o > 0; o >>= 1) d += __shfl_xor_sync(0xffffffffu, d, o);
            if (lane == 0) av[ci] = d * 32.0f;
        }
        __syncthreads();
        if (tid == 0) {
            float mm = -3.0e38f;
            for (int ci = 0; ci < cnt; ci++) mm = fmaxf(mm, av[ci]);
            float Z = 0.f;
            for (int ci = 0; ci < cnt; ci++) { av[ci] = expf(av[ci] - mm); Z += av[ci]; }
            const float inv = 1.0f / Z;
            for (int ci = 0; ci < cnt; ci++) {
                av[ci] *= inv;
                Arow[crow[ci]] = av[ci];
            }
        }
        __syncthreads();
        for (int ci = 0; ci < cnt; ci++) {
            const float a = av[ci];
            const __half2* vr = (const __half2*)(g_Vh + ((size_t)b * S_ + crow[ci]) * D_) + tid * 2;
            float2 p0 = __half22float2(vr[0]);
            float2 p1 = __half22float2(vr[1]);
            y0 += a * p0.x; y1 += a * p0.y; y2 += a * p1.x; y3 += a * p1.y;
        }
    } else {
        // rare fallback: exact logits for all t <= s
        const int len = s + 1;
        for (int t = warp; t < len; t += 8) {
            const float* xr = Xb + (size_t)t * D_;
            float d = 0.f;
            for (int k = lane; k < D_; k += 32) d += qrow[k] * xr[k];
#pragma unroll
            for (int o = 16; o > 0; o >>= 1) d += __shfl_xor_sync(0xffffffffu, d, o);
            if (lane == 0) Arow[t] = d * 32.0f;
        }
        __syncthreads();
        float mm = -3.0e38f;
        for (int j = tid; j < len; j += 256) mm = fmaxf(mm, Arow[j]);
#pragma unroll
        for (int o = 16; o > 0; o >>= 1) mm = fmaxf(mm, __shfl_xor_sync(0xffffffffu, mm, o));
        if (lane == 0) red[warp] = mm;
        __syncthreads();
        mm = red[lane & 7];
#pragma unroll
        for (int o = 4; o > 0; o >>= 1) mm = fmaxf(mm, __shfl_xor_sync(0xffffffffu, mm, o));
        float Z = 0.f;
        for (int j = tid; j < len; j += 256) Z += expf(Arow[j] - mm);
#pragma unroll
        for (int o = 16; o > 0; o >>= 1) Z += __shfl_xor_sync(0xffffffffu, Z, o);
        if (lane == 0) red[warp] = Z;
        __syncthreads();
        Z = red[lane & 7];
#pragma unroll
        for (int o = 4; o > 0; o >>= 1) Z += __shfl_xor_sync(0xffffffffu, Z, o);
        const float inv = 1.0f / Z;
        __syncthreads();
        for (int j = tid; j < len; j += 256) Arow[j] = expf(Arow[j] - mm) * inv;
        __syncthreads();
        for (int t = 0; t < len; t++) {
            const float a = Arow[t];
            if (a > 1e-30f) {
                const __half2* vr = (const __half2*)(g_Vh + ((size_t)b * S_ + t) * D_) + tid * 2;
                float2 p0 = __half22float2(vr[0]);
                float2 p1 = __half22float2(vr[1]);
                y0 += a * p0.x; y1 += a * p0.y; y2 += a * p1.x; y3 += a * p1.y;
            }
        }
    }
    float4 o = make_float4(x4.x + y0, x4.y + y1, x4.z + y2, x4.w + y3);
    ((float4*)(Yout + xoff))[tid] = o;
}

// ---------------------------------------------------------------------------
extern "C" void kernel_launch(void* const* d_in, const int* in_sizes, int n_in,
                              void* d_out, int out_size) {
    const float* X   = (const float*)d_in[0];
    const float* WQK = (const float*)d_in[2];
    const float* WOV = (const float*)d_in[3];
    float* out = (float*)d_out;

    const size_t nY = (size_t)M1 * D_;
    const size_t nA = (size_t)B_ * S_ * S_;
    float* Aout;
    if ((size_t)out_size >= nY + nA) {
        Aout = out + nY;
    } else {
        void* p = nullptr;
        cudaGetSymbolAddress(&p, g_Afallback);
        Aout = (float*)p;
    }

    static bool attrs_set = false;
    if (!attrs_set) {
        cudaFuncSetAttribute(k_qv,     cudaFuncAttributeMaxDynamicSharedMemorySize, SMEM_NT);
        cudaFuncSetAttribute(k_scores, cudaFuncAttributeMaxDynamicSharedMemorySize, SMEM_NT);
        cudaFuncSetAttribute(k_qfix,   cudaFuncAttributeMaxDynamicSharedMemorySize, SMEM_HILO);
        attrs_set = true;
    }

    // 1) conversions (+ g_nfix reset)
    k_cvtX<<<512, 256>>>((const float4*)X, M1 * D_ / 4);
    k_cvtW<<<256, 256>>>((const float4*)WQK, (const float4*)WOV, D_ * D_ / 4);
    // 2) Q (1-pass bf16) and V (1-pass fp16)
    k_qv<<<dim3(D_ / 128, M1 / 128, 2), 128, SMEM_NT>>>();
    // 3) approx scores (1-pass bf16); upper-tri blocks zero-filled
    k_scores<<<dim3(S_ / 128, S_ / 128, B_), 128, SMEM_NT>>>(Aout);
    // 4) candidate finder + zero diag range + flag rows
    k_softmax<<<dim3(S_, B_), 256>>>(Aout);
    // 5) exact Q for flagged rows (indirect 3-pass GEMM)
    k_qfix<<<dim3(D_ / 128, M1 / 128), 128, SMEM_HILO>>>();
    // 6) exact softmax + out = X + A.V in one pass
    k_finish<<<dim3(S_, B_), 256>>>(X, out, Aout);
}